// round 1
// baseline (speedup 1.0000x reference)
#include <cuda_runtime.h>
#include <math.h>

#define B_SZ    4
#define S_LEN   4096
#define D_MODEL 1024
#define HEAD    64
#define R_TOT   (B_SZ * S_LEN)
#define HALF    (HEAD / 2)

// Scratch (allocation-free rule: __device__ globals)
__device__ float g_Q[R_TOT * HEAD];
__device__ float g_K[R_TOT * HEAD];
__device__ float g_V[R_TOT * HEAD];
__device__ float g_sin[S_LEN * HALF];
__device__ float g_cos[S_LEN * HALF];

// ---------------------------------------------------------------------------
// RoPE table: match JAX fp32 semantics: theta_f = fp32(10000^(-i/32)),
// freq_f = fp32(s * theta_f), then (near-)correctly-rounded fp32 sin/cos via
// double-precision evaluation (immune to --use_fast_math degrading sinf).
// ---------------------------------------------------------------------------
__global__ void rope_table_kernel() {
    int idx = blockIdx.x * blockDim.x + threadIdx.x;
    if (idx >= S_LEN * HALF) return;
    int s = idx >> 5;        // / HALF
    int i = idx & (HALF - 1);
    float theta = (float)pow(10000.0, -(double)i / (double)HALF);
    float fr = (float)s * theta;
    double sd, cd;
    sincos((double)fr, &sd, &cd);
    g_sin[idx] = (float)sd;
    g_cos[idx] = (float)cd;
}

// ---------------------------------------------------------------------------
// Projection + fused RoPE epilogue.
// grid = (256, 3): blockIdx.x = 64-row tile, blockIdx.y = {Q,K,V}.
// 256 threads, 64x64 output tile, 4x4 microtile, K-chunks of 16.
// ---------------------------------------------------------------------------
__global__ void __launch_bounds__(256) proj_rope_kernel(
    const float* __restrict__ x,
    const float* __restrict__ Wq,
    const float* __restrict__ Wk,
    const float* __restrict__ Wv)
{
    const int which = blockIdx.y;
    const float* __restrict__ W = (which == 0) ? Wq : (which == 1) ? Wk : Wv;
    float* __restrict__ outp    = (which == 0) ? g_Q : (which == 1) ? g_K : g_V;

    __shared__ float xs_t[16][68];   // transposed x chunk, padded (stride 272B, 16B aligned)
    __shared__ float ws[16][64];

    const int tid  = threadIdx.x;
    const int tr   = tid >> 4;   // 0..15 row group
    const int tc   = tid & 15;   // 0..15 col group
    const int row0 = blockIdx.x * 64;

    float acc[4][4] = {};

    for (int k0 = 0; k0 < D_MODEL; k0 += 16) {
        {   // x chunk -> transposed smem
            int a = tid >> 2;    // 0..63 local row
            int v = tid & 3;     // 0..3 float4
            float4 xv = *(const float4*)(x + (size_t)(row0 + a) * D_MODEL + k0 + v * 4);
            xs_t[v * 4 + 0][a] = xv.x;
            xs_t[v * 4 + 1][a] = xv.y;
            xs_t[v * 4 + 2][a] = xv.z;
            xs_t[v * 4 + 3][a] = xv.w;
        }
        {   // W chunk
            int kk = tid >> 4;
            int c4 = tid & 15;
            *(float4*)&ws[kk][c4 * 4] =
                *(const float4*)(W + (size_t)(k0 + kk) * HEAD + c4 * 4);
        }
        __syncthreads();
        #pragma unroll
        for (int kk = 0; kk < 16; kk++) {
            float4 xa = *(float4*)&xs_t[kk][tr * 4];
            float4 wb = *(float4*)&ws[kk][tc * 4];
            acc[0][0] += xa.x * wb.x; acc[0][1] += xa.x * wb.y; acc[0][2] += xa.x * wb.z; acc[0][3] += xa.x * wb.w;
            acc[1][0] += xa.y * wb.x; acc[1][1] += xa.y * wb.y; acc[1][2] += xa.y * wb.z; acc[1][3] += xa.y * wb.w;
            acc[2][0] += xa.z * wb.x; acc[2][1] += xa.z * wb.y; acc[2][2] += xa.z * wb.z; acc[2][3] += xa.z * wb.w;
            acc[3][0] += xa.w * wb.x; acc[3][1] += xa.w * wb.y; acc[3][2] += xa.w * wb.z; acc[3][3] += xa.w * wb.w;
        }
        __syncthreads();
    }

    const int c0 = tc * 4;   // even; rope pairs (c0,c0+1),(c0+2,c0+3) are intra-thread
    #pragma unroll
    for (int ii = 0; ii < 4; ii++) {
        int gr = row0 + tr * 4 + ii;
        int s  = gr & (S_LEN - 1);
        float v0 = acc[ii][0], v1 = acc[ii][1], v2 = acc[ii][2], v3 = acc[ii][3];
        float4 r;
        if (which < 2) {
            int i0 = c0 >> 1;
            float sn0 = g_sin[s * HALF + i0],     cs0 = g_cos[s * HALF + i0];
            float sn1 = g_sin[s * HALF + i0 + 1], cs1 = g_cos[s * HALF + i0 + 1];
            r.x = v0 * cs0 - v1 * sn0;   // out[2i]   = a*cos - b*sin
            r.y = v1 * cs0 + v0 * sn0;   // out[2i+1] = b*cos + a*sin
            r.z = v2 * cs1 - v3 * sn1;
            r.w = v3 * cs1 + v2 * sn1;
        } else {
            r.x = v0; r.y = v1; r.z = v2; r.w = v3;
        }
        *(float4*)(outp + (size_t)gr * HEAD + c0) = r;
    }
}

// ---------------------------------------------------------------------------
// Causal flash attention: 1 query row per thread (q,o resident in registers),
// 64x64 K/V tiles in smem (warp-broadcast reads), online softmax.
// grid = 256 blocks (4 batches x 64 q-tiles), 64 threads.
// Largest-work tiles scheduled first (qt reversed) for wave balance.
// ---------------------------------------------------------------------------
__global__ void __launch_bounds__(64) attn_kernel(float* __restrict__ out) {
    __shared__ float4 Ks4[1024];          // 64x64 K tile
    __shared__ float4 Vs4[1024];          // 64x64 V tile
    __shared__ float  sc[64][64];         // per-row scores, rotate-swizzled

    const int bid   = blockIdx.x;
    const int batch = bid & 3;
    const int qt    = 63 - (bid >> 2);    // big tiles first
    const int t     = threadIdx.x;
    const int q     = qt * 64 + t;

    const float4* __restrict__ Qg =
        (const float4*)(g_Q + ((size_t)batch * S_LEN + q) * HEAD);

    float4 qv[16], o[16];
    #pragma unroll
    for (int k = 0; k < 16; k++) { qv[k] = Qg[k]; o[k] = make_float4(0.f, 0.f, 0.f, 0.f); }

    float m = -1e30f, l = 0.f;
    const float scale = 0.125f;   // HEAD^-0.5

    for (int jt = 0; jt <= qt; jt++) {
        const float4* __restrict__ Kg =
            (const float4*)(g_K + ((size_t)batch * S_LEN + jt * 64) * HEAD);
        const float4* __restrict__ Vg =
            (const float4*)(g_V + ((size_t)batch * S_LEN + jt * 64) * HEAD);
        for (int i = t; i < 1024; i += 64) { Ks4[i] = Kg[i]; Vs4[i] = Vg[i]; }
        __syncthreads();

        const int jmax = q - jt * 64;     // valid keys: j <= jmax
        float mt = -1e30f;
        for (int j = 0; j < 64; j++) {
            const float4* kr = &Ks4[j * 16];
            float d0 = 0.f, d1 = 0.f, d2 = 0.f, d3 = 0.f;
            #pragma unroll
            for (int kk = 0; kk < 16; kk++) {
                float4 kv = kr[kk];
                d0 += qv[kk].x * kv.x; d1 += qv[kk].y * kv.y;
                d2 += qv[kk].z * kv.z; d3 += qv[kk].w * kv.w;
            }
            float sco = (d0 + d1 + d2 + d3) * scale;
            sco = (j <= jmax) ? sco : -1e30f;
            sc[t][(j + t) & 63] = sco;    // rotation keeps banks conflict-free
            mt = fmaxf(mt, sco);
        }

        float mn   = fmaxf(m, mt);
        float corr = expf(m - mn);
        l *= corr;
        #pragma unroll
        for (int k = 0; k < 16; k++) {
            o[k].x *= corr; o[k].y *= corr; o[k].z *= corr; o[k].w *= corr;
        }
        for (int j = 0; j < 64; j++) {
            float p = expf(sc[t][(j + t) & 63] - mn);
            l += p;
            const float4* vr = &Vs4[j * 16];
            #pragma unroll
            for (int kk = 0; kk < 16; kk++) {
                float4 vv = vr[kk];
                o[kk].x += p * vv.x; o[kk].y += p * vv.y;
                o[kk].z += p * vv.z; o[kk].w += p * vv.w;
            }
        }
        m = mn;
        __syncthreads();
    }

    const float inv = 1.0f / l;
    float4* __restrict__ Og = (float4*)(out + ((size_t)batch * S_LEN + q) * HEAD);
    #pragma unroll
    for (int k = 0; k < 16; k++) {
        float4 r = o[k];
        r.x *= inv; r.y *= inv; r.z *= inv; r.w *= inv;
        Og[k] = r;
    }
}

// ---------------------------------------------------------------------------
extern "C" void kernel_launch(void* const* d_in, const int* in_sizes, int n_in,
                              void* d_out, int out_size) {
    const float* x  = (const float*)d_in[0];
    const float* Wq = (const float*)d_in[1];
    const float* Wk = (const float*)d_in[2];
    const float* Wv = (const float*)d_in[3];
    float* out = (float*)d_out;

    rope_table_kernel<<<(S_LEN * HALF + 255) / 256, 256>>>();
    proj_rope_kernel<<<dim3(R_TOT / 64, 3), 256>>>(x, Wq, Wk, Wv);
    attn_kernel<<<B_SZ * (S_LEN / 64), 64>>>(out);
}

// round 2
// speedup vs baseline: 2.5466x; 2.5466x over previous
#include <cuda_runtime.h>
#include <math.h>

#define B_SZ    4
#define S_LEN   4096
#define D_MODEL 1024
#define HEAD    64
#define R_TOT   (B_SZ * S_LEN)
#define HALF    (HEAD / 2)
#define LOG2E   1.4426950408889634f

// Scratch (allocation-free rule: __device__ globals)
__device__ float g_Q[R_TOT * HEAD];
__device__ float g_K[R_TOT * HEAD];
__device__ float g_V[R_TOT * HEAD];
__device__ float g_sin[S_LEN * HALF];
__device__ float g_cos[S_LEN * HALF];
__device__ float g_theta[HALF];

// ---------------------------------------------------------------------------
// Theta table: 32 correctly-rounded fp32 values of 10000^(-i/32).
// ---------------------------------------------------------------------------
__global__ void theta_kernel() {
    int i = threadIdx.x;
    if (i < HALF) g_theta[i] = (float)pow(10000.0, -(double)i / (double)HALF);
}

// ---------------------------------------------------------------------------
// RoPE table. Reference semantics: theta is fp32, freq = fp32(s * theta),
// then ACCURATE sin/cos of that fp32 value. We do the range reduction in
// double (3 FP64 ops) and the sin/cos with fp32 Taylor polys on |r|<=pi/4.
// ---------------------------------------------------------------------------
__global__ void rope_table_kernel() {
    int idx = blockIdx.x * blockDim.x + threadIdx.x;
    if (idx >= S_LEN * HALF) return;
    int s = idx >> 5;
    int i = idx & (HALF - 1);
    float fr = (float)s * g_theta[i];

    double x  = (double)fr;
    double kd = rint(x * 0.6366197723675814);            // 2/pi
    int    k  = (int)kd;
    double r  = fma(-kd, 1.5707963267948966, x);          // pi/2 hi
    r         = fma(-kd, 6.123233995736766e-17, r);       // pi/2 lo
    float rf = (float)r;
    float r2 = rf * rf;
    float sp = rf * (1.f + r2 * (-1.66666667e-1f + r2 * (8.33333310e-3f +
               r2 * (-1.98412698e-4f + r2 * 2.75573140e-6f))));
    float cp = 1.f + r2 * (-0.5f + r2 * (4.16666679e-2f +
               r2 * (-1.38888892e-3f + r2 * 2.47868524e-5f)));
    float sn, cs;
    switch (k & 3) {
        case 0:  sn = sp;  cs = cp;  break;
        case 1:  sn = cp;  cs = -sp; break;
        case 2:  sn = -sp; cs = -cp; break;
        default: sn = -cp; cs = sp;  break;
    }
    g_sin[idx] = sn;
    g_cos[idx] = cs;
}

// ---------------------------------------------------------------------------
// Projection + fused RoPE epilogue (unchanged, fp32 — precision anchor).
// ---------------------------------------------------------------------------
__global__ void __launch_bounds__(256) proj_rope_kernel(
    const float* __restrict__ x,
    const float* __restrict__ Wq,
    const float* __restrict__ Wk,
    const float* __restrict__ Wv)
{
    const int which = blockIdx.y;
    const float* __restrict__ W = (which == 0) ? Wq : (which == 1) ? Wk : Wv;
    float* __restrict__ outp    = (which == 0) ? g_Q : (which == 1) ? g_K : g_V;

    __shared__ float xs_t[16][68];
    __shared__ float ws[16][64];

    const int tid  = threadIdx.x;
    const int tr   = tid >> 4;
    const int tc   = tid & 15;
    const int row0 = blockIdx.x * 64;

    float acc[4][4] = {};

    for (int k0 = 0; k0 < D_MODEL; k0 += 16) {
        {
            int a = tid >> 2;
            int v = tid & 3;
            float4 xv = *(const float4*)(x + (size_t)(row0 + a) * D_MODEL + k0 + v * 4);
            xs_t[v * 4 + 0][a] = xv.x;
            xs_t[v * 4 + 1][a] = xv.y;
            xs_t[v * 4 + 2][a] = xv.z;
            xs_t[v * 4 + 3][a] = xv.w;
        }
        {
            int kk = tid >> 4;
            int c4 = tid & 15;
            *(float4*)&ws[kk][c4 * 4] =
                *(const float4*)(W + (size_t)(k0 + kk) * HEAD + c4 * 4);
        }
        __syncthreads();
        #pragma unroll
        for (int kk = 0; kk < 16; kk++) {
            float4 xa = *(float4*)&xs_t[kk][tr * 4];
            float4 wb = *(float4*)&ws[kk][tc * 4];
            acc[0][0] += xa.x * wb.x; acc[0][1] += xa.x * wb.y; acc[0][2] += xa.x * wb.z; acc[0][3] += xa.x * wb.w;
            acc[1][0] += xa.y * wb.x; acc[1][1] += xa.y * wb.y; acc[1][2] += xa.y * wb.z; acc[1][3] += xa.y * wb.w;
            acc[2][0] += xa.z * wb.x; acc[2][1] += xa.z * wb.y; acc[2][2] += xa.z * wb.z; acc[2][3] += xa.z * wb.w;
            acc[3][0] += xa.w * wb.x; acc[3][1] += xa.w * wb.y; acc[3][2] += xa.w * wb.z; acc[3][3] += xa.w * wb.w;
        }
        __syncthreads();
    }

    const int c0 = tc * 4;
    #pragma unroll
    for (int ii = 0; ii < 4; ii++) {
        int gr = row0 + tr * 4 + ii;
        int s  = gr & (S_LEN - 1);
        float v0 = acc[ii][0], v1 = acc[ii][1], v2 = acc[ii][2], v3 = acc[ii][3];
        float4 r;
        if (which < 2) {
            int i0 = c0 >> 1;
            float sn0 = g_sin[s * HALF + i0],     cs0 = g_cos[s * HALF + i0];
            float sn1 = g_sin[s * HALF + i0 + 1], cs1 = g_cos[s * HALF + i0 + 1];
            r.x = v0 * cs0 - v1 * sn0;
            r.y = v1 * cs0 + v0 * sn0;
            r.z = v2 * cs1 - v3 * sn1;
            r.w = v3 * cs1 + v2 * sn1;
        } else {
            r.x = v0; r.y = v1; r.z = v2; r.w = v3;
        }
        *(float4*)(outp + (size_t)gr * HEAD + c0) = r;
    }
}

// ---------------------------------------------------------------------------
// Tensor-core flash attention: mma.sync.m16n8k8 tf32.
// Block = 128 threads (4 warps), 64 query rows (m16 per warp), KV tiles of 64.
// Q pre-scaled by 0.125 (exact). Online softmax in C-fragment layout;
// P repacked C->A via intra-quad shuffles (no smem round trip).
// ---------------------------------------------------------------------------
__device__ __forceinline__ unsigned f2tf(float f) {
    unsigned u;
    asm("cvt.rna.tf32.f32 %0, %1;" : "=r"(u) : "f"(f));
    return u;
}

__device__ __forceinline__ void mma_tf32(float c[4], const unsigned a[4],
                                         unsigned b0, unsigned b1) {
    asm volatile(
        "mma.sync.aligned.m16n8k8.row.col.f32.tf32.tf32.f32 "
        "{%0,%1,%2,%3}, {%4,%5,%6,%7}, {%8,%9}, {%0,%1,%2,%3};\n"
        : "+f"(c[0]), "+f"(c[1]), "+f"(c[2]), "+f"(c[3])
        : "r"(a[0]), "r"(a[1]), "r"(a[2]), "r"(a[3]), "r"(b0), "r"(b1));
}

__global__ void __launch_bounds__(128) attn_mma_kernel(float* __restrict__ out) {
    __shared__ unsigned Ks[64][68];   // K tile [kv][d], tf32 bits; 68-pad = conflict-free frags
    __shared__ unsigned Vs[64][68];   // V tile [kv][d]

    const int tid   = threadIdx.x;
    const int warp  = tid >> 5;
    const int lane  = tid & 31;
    const int g     = lane >> 2;      // row group within fragment
    const int t     = lane & 3;       // col group within fragment
    const int batch = blockIdx.x & 3;
    const int qt    = 63 - (blockIdx.x >> 2);   // big tiles first
    const int q0    = qt * 64;

    // Phase 0: Q tile -> smem (scaled + tf32) -> register A-fragments
    {
        const float4* Qg = (const float4*)(g_Q + ((size_t)batch * S_LEN + q0) * HEAD);
        for (int i = tid; i < 1024; i += 128) {
            int row = i >> 4, c4 = i & 15;
            float4 v = Qg[i];
            uint4 u;
            u.x = f2tf(v.x * 0.125f); u.y = f2tf(v.y * 0.125f);
            u.z = f2tf(v.z * 0.125f); u.w = f2tf(v.w * 0.125f);
            *(uint4*)&Ks[row][c4 * 4] = u;
        }
    }
    __syncthreads();
    unsigned qa[8][4];
    {
        const int r0 = warp * 16 + g;
        #pragma unroll
        for (int kc = 0; kc < 8; kc++) {
            qa[kc][0] = Ks[r0][kc * 8 + t];
            qa[kc][1] = Ks[r0 + 8][kc * 8 + t];
            qa[kc][2] = Ks[r0][kc * 8 + t + 4];
            qa[kc][3] = Ks[r0 + 8][kc * 8 + t + 4];
        }
    }
    __syncthreads();

    float o[8][4];
    #pragma unroll
    for (int nc = 0; nc < 8; nc++) { o[nc][0] = o[nc][1] = o[nc][2] = o[nc][3] = 0.f; }
    float m0 = -1e30f, m1 = -1e30f, l0 = 0.f, l1 = 0.f;
    const int rl0 = warp * 16 + g, rl1 = rl0 + 8;

    for (int jt = 0; jt <= qt; jt++) {
        const float4* Kg = (const float4*)(g_K + ((size_t)batch * S_LEN + jt * 64) * HEAD);
        const float4* Vg = (const float4*)(g_V + ((size_t)batch * S_LEN + jt * 64) * HEAD);
        for (int i = tid; i < 1024; i += 128) {
            int row = i >> 4, c4 = i & 15;
            float4 kv = Kg[i];
            uint4 ku;
            ku.x = f2tf(kv.x); ku.y = f2tf(kv.y); ku.z = f2tf(kv.z); ku.w = f2tf(kv.w);
            *(uint4*)&Ks[row][c4 * 4] = ku;
            float4 vv = Vg[i];
            uint4 vu;
            vu.x = f2tf(vv.x); vu.y = f2tf(vv.y); vu.z = f2tf(vv.z); vu.w = f2tf(vv.w);
            *(uint4*)&Vs[row][c4 * 4] = vu;
        }
        __syncthreads();

        // S = Q K^T  (B-frag: b0 = K[n][k], n = nc*8+g, k = kc*8+t)
        float s[8][4];
        #pragma unroll
        for (int nc = 0; nc < 8; nc++) {
            s[nc][0] = s[nc][1] = s[nc][2] = s[nc][3] = 0.f;
            #pragma unroll
            for (int kc = 0; kc < 8; kc++) {
                unsigned b0 = Ks[nc * 8 + g][kc * 8 + t];
                unsigned b1 = Ks[nc * 8 + g][kc * 8 + t + 4];
                mma_tf32(s[nc], qa[kc], b0, b1);
            }
        }

        // Causal mask (diagonal tile only)
        if (jt == qt) {
            #pragma unroll
            for (int nc = 0; nc < 8; nc++) {
                int cl = nc * 8 + 2 * t;
                if (cl     > rl0) s[nc][0] = -1e30f;
                if (cl + 1 > rl0) s[nc][1] = -1e30f;
                if (cl     > rl1) s[nc][2] = -1e30f;
                if (cl + 1 > rl1) s[nc][3] = -1e30f;
            }
        }

        // Row max across the quad
        float mt0 = -1e30f, mt1 = -1e30f;
        #pragma unroll
        for (int nc = 0; nc < 8; nc++) {
            mt0 = fmaxf(mt0, fmaxf(s[nc][0], s[nc][1]));
            mt1 = fmaxf(mt1, fmaxf(s[nc][2], s[nc][3]));
        }
        mt0 = fmaxf(mt0, __shfl_xor_sync(0xffffffffu, mt0, 1));
        mt0 = fmaxf(mt0, __shfl_xor_sync(0xffffffffu, mt0, 2));
        mt1 = fmaxf(mt1, __shfl_xor_sync(0xffffffffu, mt1, 1));
        mt1 = fmaxf(mt1, __shfl_xor_sync(0xffffffffu, mt1, 2));

        float mn0 = fmaxf(m0, mt0), mn1 = fmaxf(m1, mt1);
        float corr0 = exp2f((m0 - mn0) * LOG2E);
        float corr1 = exp2f((m1 - mn1) * LOG2E);

        float rs0 = 0.f, rs1 = 0.f;
        #pragma unroll
        for (int nc = 0; nc < 8; nc++) {
            s[nc][0] = exp2f((s[nc][0] - mn0) * LOG2E);
            s[nc][1] = exp2f((s[nc][1] - mn0) * LOG2E);
            s[nc][2] = exp2f((s[nc][2] - mn1) * LOG2E);
            s[nc][3] = exp2f((s[nc][3] - mn1) * LOG2E);
            rs0 += s[nc][0] + s[nc][1];
            rs1 += s[nc][2] + s[nc][3];
        }
        rs0 += __shfl_xor_sync(0xffffffffu, rs0, 1);
        rs0 += __shfl_xor_sync(0xffffffffu, rs0, 2);
        rs1 += __shfl_xor_sync(0xffffffffu, rs1, 1);
        rs1 += __shfl_xor_sync(0xffffffffu, rs1, 2);
        l0 = l0 * corr0 + rs0;
        l1 = l1 * corr1 + rs1;

        #pragma unroll
        for (int nc = 0; nc < 8; nc++) {
            o[nc][0] *= corr0; o[nc][1] *= corr0;
            o[nc][2] *= corr1; o[nc][3] *= corr1;
        }

        // Repack P: C-fragment layout -> A-fragment layout via quad shuffles
        unsigned pa[8][4];
        const int  src1 = (lane & ~3) | (t >> 1);
        const int  src2 = src1 + 2;
        const bool odd  = (t & 1);
        #pragma unroll
        for (int kc = 0; kc < 8; kc++) {
            float v00 = __shfl_sync(0xffffffffu, s[kc][0], src1);
            float v01 = __shfl_sync(0xffffffffu, s[kc][1], src1);
            float v10 = __shfl_sync(0xffffffffu, s[kc][2], src1);
            float v11 = __shfl_sync(0xffffffffu, s[kc][3], src1);
            float w00 = __shfl_sync(0xffffffffu, s[kc][0], src2);
            float w01 = __shfl_sync(0xffffffffu, s[kc][1], src2);
            float w10 = __shfl_sync(0xffffffffu, s[kc][2], src2);
            float w11 = __shfl_sync(0xffffffffu, s[kc][3], src2);
            pa[kc][0] = f2tf(odd ? v01 : v00);
            pa[kc][1] = f2tf(odd ? v11 : v10);
            pa[kc][2] = f2tf(odd ? w01 : w00);
            pa[kc][3] = f2tf(odd ? w11 : w10);
        }

        // O += P V   (B-frag: b0 = V[k][n], k = kc*8+t, n = nc*8+g)
        #pragma unroll
        for (int nc = 0; nc < 8; nc++) {
            #pragma unroll
            for (int kc = 0; kc < 8; kc++) {
                unsigned b0 = Vs[kc * 8 + t][nc * 8 + g];
                unsigned b1 = Vs[kc * 8 + t + 4][nc * 8 + g];
                mma_tf32(o[nc], pa[kc], b0, b1);
            }
        }

        m0 = mn0; m1 = mn1;
        __syncthreads();
    }

    const float inv0 = 1.f / l0, inv1 = 1.f / l1;
    float* O0 = out + ((size_t)batch * S_LEN + q0 + rl0) * HEAD;
    float* O1 = out + ((size_t)batch * S_LEN + q0 + rl1) * HEAD;
    #pragma unroll
    for (int nc = 0; nc < 8; nc++) {
        int col = nc * 8 + 2 * t;
        *(float2*)(O0 + col) = make_float2(o[nc][0] * inv0, o[nc][1] * inv0);
        *(float2*)(O1 + col) = make_float2(o[nc][2] * inv1, o[nc][3] * inv1);
    }
}

// ---------------------------------------------------------------------------
extern "C" void kernel_launch(void* const* d_in, const int* in_sizes, int n_in,
                              void* d_out, int out_size) {
    const float* x  = (const float*)d_in[0];
    const float* Wq = (const float*)d_in[1];
    const float* Wk = (const float*)d_in[2];
    const float* Wv = (const float*)d_in[3];
    float* out = (float*)d_out;

    theta_kernel<<<1, 32>>>();
    rope_table_kernel<<<(S_LEN * HALF + 255) / 256, 256>>>();
    proj_rope_kernel<<<dim3(R_TOT / 64, 3), 256>>>(x, Wq, Wk, Wv);
    attn_mma_kernel<<<B_SZ * (S_LEN / 64), 128>>>(out);
}

// round 3
// speedup vs baseline: 3.4616x; 1.3593x over previous
#include <cuda_runtime.h>
#include <math.h>

#define B_SZ    4
#define S_LEN   4096
#define D_MODEL 1024
#define HEAD    64
#define R_TOT   (B_SZ * S_LEN)
#define HALF    (HEAD / 2)
#define LOG2E   1.4426950408889634f
#define SPLIT   4

// Scratch (allocation-free rule: __device__ globals)
__device__ float g_Q[R_TOT * HEAD];
__device__ float g_K[R_TOT * HEAD];
__device__ float g_V[R_TOT * HEAD];
__device__ float g_sin[S_LEN * HALF];
__device__ float g_cos[S_LEN * HALF];
__device__ float g_theta[HALF];
__device__ float g_Os[(size_t)SPLIT * R_TOT * HEAD];   // unnormalized partial O
__device__ float g_m[SPLIT * R_TOT];
__device__ float g_l[SPLIT * R_TOT];

// ---------------------------------------------------------------------------
__global__ void theta_kernel() {
    int i = threadIdx.x;
    if (i < HALF) g_theta[i] = (float)pow(10000.0, -(double)i / (double)HALF);
}

// RoPE table: freq = fp32(s * theta_fp32); accurate sin/cos via double range
// reduction + fp32 Taylor on |r|<=pi/4.
__global__ void rope_table_kernel() {
    int idx = blockIdx.x * blockDim.x + threadIdx.x;
    if (idx >= S_LEN * HALF) return;
    int s = idx >> 5;
    int i = idx & (HALF - 1);
    float fr = (float)s * g_theta[i];

    double x  = (double)fr;
    double kd = rint(x * 0.6366197723675814);
    int    k  = (int)kd;
    double r  = fma(-kd, 1.5707963267948966, x);
    r         = fma(-kd, 6.123233995736766e-17, r);
    float rf = (float)r;
    float r2 = rf * rf;
    float sp = rf * (1.f + r2 * (-1.66666667e-1f + r2 * (8.33333310e-3f +
               r2 * (-1.98412698e-4f + r2 * 2.75573140e-6f))));
    float cp = 1.f + r2 * (-0.5f + r2 * (4.16666679e-2f +
               r2 * (-1.38888892e-3f + r2 * 2.47868524e-5f)));
    float sn, cs;
    switch (k & 3) {
        case 0:  sn = sp;  cs = cp;  break;
        case 1:  sn = cp;  cs = -sp; break;
        case 2:  sn = -sp; cs = -cp; break;
        default: sn = -cp; cs = sp;  break;
    }
    g_sin[idx] = sn;
    g_cos[idx] = cs;
}

// ---------------------------------------------------------------------------
// Projection + fused RoPE epilogue (fp32 — precision anchor).
// ---------------------------------------------------------------------------
__global__ void __launch_bounds__(256) proj_rope_kernel(
    const float* __restrict__ x,
    const float* __restrict__ Wq,
    const float* __restrict__ Wk,
    const float* __restrict__ Wv)
{
    const int which = blockIdx.y;
    const float* __restrict__ W = (which == 0) ? Wq : (which == 1) ? Wk : Wv;
    float* __restrict__ outp    = (which == 0) ? g_Q : (which == 1) ? g_K : g_V;

    __shared__ float xs_t[16][68];
    __shared__ float ws[16][64];

    const int tid  = threadIdx.x;
    const int tr   = tid >> 4;
    const int tc   = tid & 15;
    const int row0 = blockIdx.x * 64;

    float acc[4][4] = {};

    for (int k0 = 0; k0 < D_MODEL; k0 += 16) {
        {
            int a = tid >> 2;
            int v = tid & 3;
            float4 xv = *(const float4*)(x + (size_t)(row0 + a) * D_MODEL + k0 + v * 4);
            xs_t[v * 4 + 0][a] = xv.x;
            xs_t[v * 4 + 1][a] = xv.y;
            xs_t[v * 4 + 2][a] = xv.z;
            xs_t[v * 4 + 3][a] = xv.w;
        }
        {
            int kk = tid >> 4;
            int c4 = tid & 15;
            *(float4*)&ws[kk][c4 * 4] =
                *(const float4*)(W + (size_t)(k0 + kk) * HEAD + c4 * 4);
        }
        __syncthreads();
        #pragma unroll
        for (int kk = 0; kk < 16; kk++) {
            float4 xa = *(float4*)&xs_t[kk][tr * 4];
            float4 wb = *(float4*)&ws[kk][tc * 4];
            acc[0][0] += xa.x * wb.x; acc[0][1] += xa.x * wb.y; acc[0][2] += xa.x * wb.z; acc[0][3] += xa.x * wb.w;
            acc[1][0] += xa.y * wb.x; acc[1][1] += xa.y * wb.y; acc[1][2] += xa.y * wb.z; acc[1][3] += xa.y * wb.w;
            acc[2][0] += xa.z * wb.x; acc[2][1] += xa.z * wb.y; acc[2][2] += xa.z * wb.z; acc[2][3] += xa.z * wb.w;
            acc[3][0] += xa.w * wb.x; acc[3][1] += xa.w * wb.y; acc[3][2] += xa.w * wb.z; acc[3][3] += xa.w * wb.w;
        }
        __syncthreads();
    }

    const int c0 = tc * 4;
    #pragma unroll
    for (int ii = 0; ii < 4; ii++) {
        int gr = row0 + tr * 4 + ii;
        int s  = gr & (S_LEN - 1);
        float v0 = acc[ii][0], v1 = acc[ii][1], v2 = acc[ii][2], v3 = acc[ii][3];
        float4 r;
        if (which < 2) {
            int i0 = c0 >> 1;
            float sn0 = g_sin[s * HALF + i0],     cs0 = g_cos[s * HALF + i0];
            float sn1 = g_sin[s * HALF + i0 + 1], cs1 = g_cos[s * HALF + i0 + 1];
            r.x = v0 * cs0 - v1 * sn0;
            r.y = v1 * cs0 + v0 * sn0;
            r.z = v2 * cs1 - v3 * sn1;
            r.w = v3 * cs1 + v2 * sn1;
        } else {
            r.x = v0; r.y = v1; r.z = v2; r.w = v3;
        }
        *(float4*)(outp + (size_t)gr * HEAD + c0) = r;
    }
}

// ---------------------------------------------------------------------------
// Tensor-core flash attention, 4-way split-KV.
// Block = 128 threads (4 warps) handles (batch, qtile, split): KV tiles
// [split*n/4, (split+1)*n/4) of the n = qt+1 causal tiles. Partials
// (unnormalized O, m, l) go to scratch; combine_kernel merges.
// ---------------------------------------------------------------------------
__device__ __forceinline__ unsigned f2tf(float f) {
    unsigned u;
    asm("cvt.rna.tf32.f32 %0, %1;" : "=r"(u) : "f"(f));
    return u;
}

__device__ __forceinline__ void mma_tf32(float c[4], const unsigned a[4],
                                         unsigned b0, unsigned b1) {
    asm volatile(
        "mma.sync.aligned.m16n8k8.row.col.f32.tf32.tf32.f32 "
        "{%0,%1,%2,%3}, {%4,%5,%6,%7}, {%8,%9}, {%0,%1,%2,%3};\n"
        : "+f"(c[0]), "+f"(c[1]), "+f"(c[2]), "+f"(c[3])
        : "r"(a[0]), "r"(a[1]), "r"(a[2]), "r"(a[3]), "r"(b0), "r"(b1));
}

__global__ void __launch_bounds__(128) attn_mma_kernel() {
    __shared__ unsigned Ks[64][68];
    __shared__ unsigned Vs[64][68];

    const int tid   = threadIdx.x;
    const int warp  = tid >> 5;
    const int lane  = tid & 31;
    const int g     = lane >> 2;
    const int t     = lane & 3;
    const int idx   = blockIdx.x;
    const int qt    = 63 - (idx >> 4);        // big q-tiles first
    const int rem   = idx & 15;
    const int batch = rem >> 2;
    const int split = rem & 3;
    const int q0    = qt * 64;
    const int n     = qt + 1;
    const int lo    = (split * n) >> 2;
    const int hi    = ((split + 1) * n) >> 2;

    const int    rl0     = warp * 16 + g, rl1 = rl0 + 8;
    const size_t rowbase = (size_t)batch * S_LEN + q0;

    if (lo == hi) {                            // empty split: mark and leave
        if (t == 0) {
            int pb = split * R_TOT;
            g_m[pb + rowbase + rl0] = -1e30f;  g_l[pb + rowbase + rl0] = 0.f;
            g_m[pb + rowbase + rl1] = -1e30f;  g_l[pb + rowbase + rl1] = 0.f;
        }
        return;
    }

    // Q tile -> smem (scaled + tf32) -> register A-fragments
    {
        const float4* Qg = (const float4*)(g_Q + rowbase * HEAD);
        for (int i = tid; i < 1024; i += 128) {
            int row = i >> 4, c4 = i & 15;
            float4 v = Qg[i];
            uint4 u;
            u.x = f2tf(v.x * 0.125f); u.y = f2tf(v.y * 0.125f);
            u.z = f2tf(v.z * 0.125f); u.w = f2tf(v.w * 0.125f);
            *(uint4*)&Ks[row][c4 * 4] = u;
        }
    }
    __syncthreads();
    unsigned qa[8][4];
    {
        const int r0 = warp * 16 + g;
        #pragma unroll
        for (int kc = 0; kc < 8; kc++) {
            qa[kc][0] = Ks[r0][kc * 8 + t];
            qa[kc][1] = Ks[r0 + 8][kc * 8 + t];
            qa[kc][2] = Ks[r0][kc * 8 + t + 4];
            qa[kc][3] = Ks[r0 + 8][kc * 8 + t + 4];
        }
    }
    __syncthreads();

    float o[8][4];
    #pragma unroll
    for (int nc = 0; nc < 8; nc++) { o[nc][0] = o[nc][1] = o[nc][2] = o[nc][3] = 0.f; }
    float m0 = -1e30f, m1 = -1e30f, l0 = 0.f, l1 = 0.f;

    for (int jt = lo; jt < hi; jt++) {
        const float4* Kg = (const float4*)(g_K + ((size_t)batch * S_LEN + jt * 64) * HEAD);
        const float4* Vg = (const float4*)(g_V + ((size_t)batch * S_LEN + jt * 64) * HEAD);
        for (int i = tid; i < 1024; i += 128) {
            int row = i >> 4, c4 = i & 15;
            float4 kv = Kg[i];
            uint4 ku;
            ku.x = f2tf(kv.x); ku.y = f2tf(kv.y); ku.z = f2tf(kv.z); ku.w = f2tf(kv.w);
            *(uint4*)&Ks[row][c4 * 4] = ku;
            float4 vv = Vg[i];
            uint4 vu;
            vu.x = f2tf(vv.x); vu.y = f2tf(vv.y); vu.z = f2tf(vv.z); vu.w = f2tf(vv.w);
            *(uint4*)&Vs[row][c4 * 4] = vu;
        }
        __syncthreads();

        // S = Q K^T
        float s[8][4];
        #pragma unroll
        for (int nc = 0; nc < 8; nc++) {
            s[nc][0] = s[nc][1] = s[nc][2] = s[nc][3] = 0.f;
            #pragma unroll
            for (int kc = 0; kc < 8; kc++) {
                unsigned b0 = Ks[nc * 8 + g][kc * 8 + t];
                unsigned b1 = Ks[nc * 8 + g][kc * 8 + t + 4];
                mma_tf32(s[nc], qa[kc], b0, b1);
            }
        }

        // Causal mask (diagonal tile only)
        if (jt == qt) {
            #pragma unroll
            for (int nc = 0; nc < 8; nc++) {
                int cl = nc * 8 + 2 * t;
                if (cl     > rl0) s[nc][0] = -1e30f;
                if (cl + 1 > rl0) s[nc][1] = -1e30f;
                if (cl     > rl1) s[nc][2] = -1e30f;
                if (cl + 1 > rl1) s[nc][3] = -1e30f;
            }
        }

        // Row max across the quad
        float mt0 = -1e30f, mt1 = -1e30f;
        #pragma unroll
        for (int nc = 0; nc < 8; nc++) {
            mt0 = fmaxf(mt0, fmaxf(s[nc][0], s[nc][1]));
            mt1 = fmaxf(mt1, fmaxf(s[nc][2], s[nc][3]));
        }
        mt0 = fmaxf(mt0, __shfl_xor_sync(0xffffffffu, mt0, 1));
        mt0 = fmaxf(mt0, __shfl_xor_sync(0xffffffffu, mt0, 2));
        mt1 = fmaxf(mt1, __shfl_xor_sync(0xffffffffu, mt1, 1));
        mt1 = fmaxf(mt1, __shfl_xor_sync(0xffffffffu, mt1, 2));

        float mn0 = fmaxf(m0, mt0), mn1 = fmaxf(m1, mt1);
        float corr0 = exp2f((m0 - mn0) * LOG2E);
        float corr1 = exp2f((m1 - mn1) * LOG2E);

        float rs0 = 0.f, rs1 = 0.f;
        #pragma unroll
        for (int nc = 0; nc < 8; nc++) {
            s[nc][0] = exp2f((s[nc][0] - mn0) * LOG2E);
            s[nc][1] = exp2f((s[nc][1] - mn0) * LOG2E);
            s[nc][2] = exp2f((s[nc][2] - mn1) * LOG2E);
            s[nc][3] = exp2f((s[nc][3] - mn1) * LOG2E);
            rs0 += s[nc][0] + s[nc][1];
            rs1 += s[nc][2] + s[nc][3];
        }
        rs0 += __shfl_xor_sync(0xffffffffu, rs0, 1);
        rs0 += __shfl_xor_sync(0xffffffffu, rs0, 2);
        rs1 += __shfl_xor_sync(0xffffffffu, rs1, 1);
        rs1 += __shfl_xor_sync(0xffffffffu, rs1, 2);
        l0 = l0 * corr0 + rs0;
        l1 = l1 * corr1 + rs1;

        #pragma unroll
        for (int nc = 0; nc < 8; nc++) {
            o[nc][0] *= corr0; o[nc][1] *= corr0;
            o[nc][2] *= corr1; o[nc][3] *= corr1;
        }

        // Repack P: C-fragment -> A-fragment via quad shuffles
        unsigned pa[8][4];
        const int  src1 = (lane & ~3) | (t >> 1);
        const int  src2 = src1 + 2;
        const bool odd  = (t & 1);
        #pragma unroll
        for (int kc = 0; kc < 8; kc++) {
            float v00 = __shfl_sync(0xffffffffu, s[kc][0], src1);
            float v01 = __shfl_sync(0xffffffffu, s[kc][1], src1);
            float v10 = __shfl_sync(0xffffffffu, s[kc][2], src1);
            float v11 = __shfl_sync(0xffffffffu, s[kc][3], src1);
            float w00 = __shfl_sync(0xffffffffu, s[kc][0], src2);
            float w01 = __shfl_sync(0xffffffffu, s[kc][1], src2);
            float w10 = __shfl_sync(0xffffffffu, s[kc][2], src2);
            float w11 = __shfl_sync(0xffffffffu, s[kc][3], src2);
            pa[kc][0] = f2tf(odd ? v01 : v00);
            pa[kc][1] = f2tf(odd ? v11 : v10);
            pa[kc][2] = f2tf(odd ? w01 : w00);
            pa[kc][3] = f2tf(odd ? w11 : w10);
        }

        // O += P V
        #pragma unroll
        for (int nc = 0; nc < 8; nc++) {
            #pragma unroll
            for (int kc = 0; kc < 8; kc++) {
                unsigned b0 = Vs[kc * 8 + t][nc * 8 + g];
                unsigned b1 = Vs[kc * 8 + t + 4][nc * 8 + g];
                mma_tf32(o[nc], pa[kc], b0, b1);
            }
        }

        m0 = mn0; m1 = mn1;
        __syncthreads();
    }

    // Store unnormalized partials + (m, l)
    float* O0 = g_Os + (size_t)split * R_TOT * HEAD + (rowbase + rl0) * HEAD;
    float* O1 = g_Os + (size_t)split * R_TOT * HEAD + (rowbase + rl1) * HEAD;
    #pragma unroll
    for (int nc = 0; nc < 8; nc++) {
        int col = nc * 8 + 2 * t;
        *(float2*)(O0 + col) = make_float2(o[nc][0], o[nc][1]);
        *(float2*)(O1 + col) = make_float2(o[nc][2], o[nc][3]);
    }
    if (t == 0) {
        int pb = split * R_TOT;
        g_m[pb + rowbase + rl0] = m0;  g_l[pb + rowbase + rl0] = l0;
        g_m[pb + rowbase + rl1] = m1;  g_l[pb + rowbase + rl1] = l1;
    }
}

// ---------------------------------------------------------------------------
// Split-KV combine: one thread per (row, 16-col quarter).
// ---------------------------------------------------------------------------
__global__ void __launch_bounds__(128) combine_kernel(float* __restrict__ out) {
    int gt  = blockIdx.x * 128 + threadIdx.x;
    int row = gt >> 2;
    int qp  = gt & 3;

    float m[SPLIT], l[SPLIT];
    float M = -1e30f;
    #pragma unroll
    for (int s = 0; s < SPLIT; s++) {
        m[s] = g_m[s * R_TOT + row];
        l[s] = g_l[s * R_TOT + row];
        M = fmaxf(M, m[s]);
    }
    float L = 0.f, w[SPLIT];
    #pragma unroll
    for (int s = 0; s < SPLIT; s++) {
        w[s] = exp2f((m[s] - M) * LOG2E);
        L += l[s] * w[s];
    }
    const float inv = 1.f / L;

    float4 acc[4];
    #pragma unroll
    for (int j = 0; j < 4; j++) acc[j] = make_float4(0.f, 0.f, 0.f, 0.f);
    #pragma unroll
    for (int s = 0; s < SPLIT; s++) {
        if (l[s] > 0.f) {
            const float4* p = (const float4*)(g_Os + (size_t)s * R_TOT * HEAD +
                                              (size_t)row * HEAD + qp * 16);
            #pragma unroll
            for (int j = 0; j < 4; j++) {
                float4 v = p[j];
                acc[j].x += w[s] * v.x; acc[j].y += w[s] * v.y;
                acc[j].z += w[s] * v.z; acc[j].w += w[s] * v.w;
            }
        }
    }
    float4* po = (float4*)(out + (size_t)row * HEAD + qp * 16);
    #pragma unroll
    for (int j = 0; j < 4; j++) {
        float4 r = acc[j];
        r.x *= inv; r.y *= inv; r.z *= inv; r.w *= inv;
        po[j] = r;
    }
}

// ---------------------------------------------------------------------------
extern "C" void kernel_launch(void* const* d_in, const int* in_sizes, int n_in,
                              void* d_out, int out_size) {
    const float* x  = (const float*)d_in[0];
    const float* Wq = (const float*)d_in[1];
    const float* Wk = (const float*)d_in[2];
    const float* Wv = (const float*)d_in[3];
    float* out = (float*)d_out;

    theta_kernel<<<1, 32>>>();
    rope_table_kernel<<<(S_LEN * HALF + 255) / 256, 256>>>();
    proj_rope_kernel<<<dim3(R_TOT / 64, 3), 256>>>(x, Wq, Wk, Wv);
    attn_mma_kernel<<<64 * B_SZ * SPLIT, 128>>>();
    combine_kernel<<<(R_TOT * 4) / 128, 128>>>(out);
}

// round 4
// speedup vs baseline: 3.7386x; 1.0800x over previous
#include <cuda_runtime.h>
#include <math.h>

#define B_SZ    4
#define S_LEN   4096
#define D_MODEL 1024
#define HEAD    64
#define R_TOT   (B_SZ * S_LEN)
#define HALF    (HEAD / 2)
#define LOG2E   1.4426950408889634f
#define SPLIT   4
#define NKS     (D_MODEL / 8)   // 128 k-slices

// Scratch (allocation-free rule: __device__ globals)
__device__ float g_Q[R_TOT * HEAD];
__device__ float g_K[R_TOT * HEAD];
__device__ float g_V[R_TOT * HEAD];
__device__ float g_sin[S_LEN * HALF];
__device__ float g_cos[S_LEN * HALF];
__device__ float g_theta[HALF];
__device__ float g_Os[(size_t)SPLIT * R_TOT * HEAD];
__device__ float g_m[SPLIT * R_TOT];
__device__ float g_l[SPLIT * R_TOT];
// Precomputed W B-fragments: [which][ks][nc][lane] = {b0hi, b1hi, b0lo, b1lo}
__device__ unsigned g_Wf[3][NKS][8][32][4];

// ---------------------------------------------------------------------------
__device__ __forceinline__ unsigned f2tf(float f) {
    unsigned u;
    asm("cvt.rna.tf32.f32 %0, %1;" : "=r"(u) : "f"(f));
    return u;
}

__device__ __forceinline__ void mma_tf32(float c[4], const unsigned a[4],
                                         unsigned b0, unsigned b1) {
    asm volatile(
        "mma.sync.aligned.m16n8k8.row.col.f32.tf32.tf32.f32 "
        "{%0,%1,%2,%3}, {%4,%5,%6,%7}, {%8,%9}, {%0,%1,%2,%3};\n"
        : "+f"(c[0]), "+f"(c[1]), "+f"(c[2]), "+f"(c[3])
        : "r"(a[0]), "r"(a[1]), "r"(a[2]), "r"(a[3]), "r"(b0), "r"(b1));
}

// ---------------------------------------------------------------------------
__global__ void theta_kernel() {
    int i = threadIdx.x;
    if (i < HALF) g_theta[i] = (float)pow(10000.0, -(double)i / (double)HALF);
}

// RoPE table: freq = fp32(s * theta_fp32); accurate sin/cos via double range
// reduction + fp32 Taylor on |r|<=pi/4.
__global__ void rope_table_kernel() {
    int idx = blockIdx.x * blockDim.x + threadIdx.x;
    if (idx >= S_LEN * HALF) return;
    int s = idx >> 5;
    int i = idx & (HALF - 1);
    float fr = (float)s * g_theta[i];

    double x  = (double)fr;
    double kd = rint(x * 0.6366197723675814);
    int    k  = (int)kd;
    double r  = fma(-kd, 1.5707963267948966, x);
    r         = fma(-kd, 6.123233995736766e-17, r);
    float rf = (float)r;
    float r2 = rf * rf;
    float sp = rf * (1.f + r2 * (-1.66666667e-1f + r2 * (8.33333310e-3f +
               r2 * (-1.98412698e-4f + r2 * 2.75573140e-6f))));
    float cp = 1.f + r2 * (-0.5f + r2 * (4.16666679e-2f +
               r2 * (-1.38888892e-3f + r2 * 2.47868524e-5f)));
    float sn, cs;
    switch (k & 3) {
        case 0:  sn = sp;  cs = cp;  break;
        case 1:  sn = cp;  cs = -sp; break;
        case 2:  sn = -sp; cs = -cp; break;
        default: sn = -cp; cs = sp;  break;
    }
    g_sin[idx] = sn;
    g_cos[idx] = cs;
}

// ---------------------------------------------------------------------------
// Precompute W B-fragments (hi/lo tf32 split) for the projection MMAs.
// ---------------------------------------------------------------------------
__global__ void wfrag_kernel(const float* __restrict__ Wq,
                             const float* __restrict__ Wk,
                             const float* __restrict__ Wv) {
    int tid = blockIdx.x * 256 + threadIdx.x;
    if (tid >= 3 * NKS * 8 * 32) return;
    int lane  = tid & 31;
    int nc    = (tid >> 5) & 7;
    int ks    = (tid >> 8) & (NKS - 1);
    int which = tid >> 15;
    const float* W = (which == 0) ? Wq : (which == 1) ? Wk : Wv;
    int g = lane >> 2, t = lane & 3;
    int n = nc * 8 + g;
    float w0 = W[(ks * 8 + t) * HEAD + n];
    float w1 = W[(ks * 8 + t + 4) * HEAD + n];
    unsigned h0 = f2tf(w0), h1 = f2tf(w1);
    unsigned l0 = f2tf(w0 - __uint_as_float(h0));
    unsigned l1 = f2tf(w1 - __uint_as_float(h1));
    uint4 v = make_uint4(h0, h1, l0, l1);
    *(uint4*)&g_Wf[which][ks][nc][lane][0] = v;
}

// ---------------------------------------------------------------------------
// Tensor-core projection (3xtf32 = fp32-accurate) + fused RoPE epilogue.
// grid = (128, 3): 128-row tile x {Q,K,V}. 256 threads = 8 warps, each warp
// owns 16 rows x 64 cols. W fragments come straight from gmem (L1-resident).
// ---------------------------------------------------------------------------
__global__ void __launch_bounds__(256) proj_mma_kernel(const float* __restrict__ x) {
    __shared__ float xs[128][68];   // fp32 x chunk, pad 68 -> conflict-free frag LDS

    const int which = blockIdx.y;
    float* __restrict__ outp = (which == 0) ? g_Q : (which == 1) ? g_K : g_V;

    const int tid  = threadIdx.x;
    const int warp = tid >> 5;
    const int lane = tid & 31;
    const int g    = lane >> 2;
    const int t    = lane & 3;
    const int row0 = blockIdx.x * 128;
    const int r0   = warp * 16 + g;     // local fragment row

    float c[8][4] = {};

    for (int kc = 0; kc < D_MODEL; kc += 64) {
        {   // stage x chunk: 128 rows x 64 cols
            int r = tid >> 1, h = tid & 1;
            const float4* xg = (const float4*)(x + (size_t)(row0 + r) * D_MODEL + kc + h * 32);
            #pragma unroll
            for (int j = 0; j < 8; j++)
                *(float4*)&xs[r][h * 32 + j * 4] = xg[j];
        }
        __syncthreads();

        #pragma unroll
        for (int ks = 0; ks < 8; ks++) {
            float a0 = xs[r0][ks * 8 + t];
            float a1 = xs[r0 + 8][ks * 8 + t];
            float a2 = xs[r0][ks * 8 + t + 4];
            float a3 = xs[r0 + 8][ks * 8 + t + 4];
            unsigned ah[4], al[4];
            ah[0] = f2tf(a0); al[0] = f2tf(a0 - __uint_as_float(ah[0]));
            ah[1] = f2tf(a1); al[1] = f2tf(a1 - __uint_as_float(ah[1]));
            ah[2] = f2tf(a2); al[2] = f2tf(a2 - __uint_as_float(ah[2]));
            ah[3] = f2tf(a3); al[3] = f2tf(a3 - __uint_as_float(ah[3]));

            const uint4* wf = (const uint4*)&g_Wf[which][(kc >> 3) + ks][0][lane][0];
            #pragma unroll
            for (int nc = 0; nc < 8; nc++) {
                uint4 b = wf[nc * 32];
                mma_tf32(c[nc], ah, b.x, b.y);   // hi * hi
                mma_tf32(c[nc], ah, b.z, b.w);   // hi * lo
                mma_tf32(c[nc], al, b.x, b.y);   // lo * hi
            }
        }
        __syncthreads();
    }

    // Epilogue: RoPE on C fragments (cols 2t, 2t+1 are exactly a rope pair)
    const int gr0 = row0 + r0;
    const int s0  = gr0 & (S_LEN - 1);
    const int s1  = (gr0 + 8) & (S_LEN - 1);
    #pragma unroll
    for (int nc = 0; nc < 8; nc++) {
        int col = nc * 8 + 2 * t;
        float v0 = c[nc][0], v1 = c[nc][1], v2 = c[nc][2], v3 = c[nc][3];
        float2 o0, o1;
        if (which < 2) {
            int i0 = col >> 1;
            float sn0 = g_sin[s0 * HALF + i0], cs0 = g_cos[s0 * HALF + i0];
            float sn1 = g_sin[s1 * HALF + i0], cs1 = g_cos[s1 * HALF + i0];
            o0 = make_float2(v0 * cs0 - v1 * sn0, v1 * cs0 + v0 * sn0);
            o1 = make_float2(v2 * cs1 - v3 * sn1, v3 * cs1 + v2 * sn1);
        } else {
            o0 = make_float2(v0, v1);
            o1 = make_float2(v2, v3);
        }
        *(float2*)(outp + (size_t)gr0 * HEAD + col)       = o0;
        *(float2*)(outp + (size_t)(gr0 + 8) * HEAD + col) = o1;
    }
}

// ---------------------------------------------------------------------------
// Tensor-core flash attention, 4-way split-KV (tf32 MMA).
// ---------------------------------------------------------------------------
__global__ void __launch_bounds__(128, 4) attn_mma_kernel() {
    __shared__ unsigned Ks[64][68];
    __shared__ unsigned Vs[64][68];

    const int tid   = threadIdx.x;
    const int warp  = tid >> 5;
    const int lane  = tid & 31;
    const int g     = lane >> 2;
    const int t     = lane & 3;
    const int idx   = blockIdx.x;
    const int qt    = 63 - (idx >> 4);
    const int rem   = idx & 15;
    const int batch = rem >> 2;
    const int split = rem & 3;
    const int q0    = qt * 64;
    const int n     = qt + 1;
    const int lo    = (split * n) >> 2;
    const int hi    = ((split + 1) * n) >> 2;

    const int    rl0     = warp * 16 + g, rl1 = rl0 + 8;
    const size_t rowbase = (size_t)batch * S_LEN + q0;

    if (lo == hi) {
        if (t == 0) {
            int pb = split * R_TOT;
            g_m[pb + rowbase + rl0] = -1e30f;  g_l[pb + rowbase + rl0] = 0.f;
            g_m[pb + rowbase + rl1] = -1e30f;  g_l[pb + rowbase + rl1] = 0.f;
        }
        return;
    }

    // Q tile -> smem (scaled + tf32) -> register A-fragments
    {
        const float4* Qg = (const float4*)(g_Q + rowbase * HEAD);
        for (int i = tid; i < 1024; i += 128) {
            int row = i >> 4, c4 = i & 15;
            float4 v = Qg[i];
            uint4 u;
            u.x = f2tf(v.x * 0.125f); u.y = f2tf(v.y * 0.125f);
            u.z = f2tf(v.z * 0.125f); u.w = f2tf(v.w * 0.125f);
            *(uint4*)&Ks[row][c4 * 4] = u;
        }
    }
    __syncthreads();
    unsigned qa[8][4];
    {
        const int r0 = warp * 16 + g;
        #pragma unroll
        for (int kc = 0; kc < 8; kc++) {
            qa[kc][0] = Ks[r0][kc * 8 + t];
            qa[kc][1] = Ks[r0 + 8][kc * 8 + t];
            qa[kc][2] = Ks[r0][kc * 8 + t + 4];
            qa[kc][3] = Ks[r0 + 8][kc * 8 + t + 4];
        }
    }
    __syncthreads();

    float o[8][4];
    #pragma unroll
    for (int nc = 0; nc < 8; nc++) { o[nc][0] = o[nc][1] = o[nc][2] = o[nc][3] = 0.f; }
    float m0 = -1e30f, m1 = -1e30f, l0 = 0.f, l1 = 0.f;

    for (int jt = lo; jt < hi; jt++) {
        const float4* Kg = (const float4*)(g_K + ((size_t)batch * S_LEN + jt * 64) * HEAD);
        const float4* Vg = (const float4*)(g_V + ((size_t)batch * S_LEN + jt * 64) * HEAD);
        for (int i = tid; i < 1024; i += 128) {
            int row = i >> 4, c4 = i & 15;
            float4 kv = Kg[i];
            uint4 ku;
            ku.x = f2tf(kv.x); ku.y = f2tf(kv.y); ku.z = f2tf(kv.z); ku.w = f2tf(kv.w);
            *(uint4*)&Ks[row][c4 * 4] = ku;
            float4 vv = Vg[i];
            uint4 vu;
            vu.x = f2tf(vv.x); vu.y = f2tf(vv.y); vu.z = f2tf(vv.z); vu.w = f2tf(vv.w);
            *(uint4*)&Vs[row][c4 * 4] = vu;
        }
        __syncthreads();

        // S = Q K^T
        float s[8][4];
        #pragma unroll
        for (int nc = 0; nc < 8; nc++) {
            s[nc][0] = s[nc][1] = s[nc][2] = s[nc][3] = 0.f;
            #pragma unroll
            for (int kc = 0; kc < 8; kc++) {
                unsigned b0 = Ks[nc * 8 + g][kc * 8 + t];
                unsigned b1 = Ks[nc * 8 + g][kc * 8 + t + 4];
                mma_tf32(s[nc], qa[kc], b0, b1);
            }
        }

        // Causal mask (diagonal tile only)
        if (jt == qt) {
            #pragma unroll
            for (int nc = 0; nc < 8; nc++) {
                int cl = nc * 8 + 2 * t;
                if (cl     > rl0) s[nc][0] = -1e30f;
                if (cl + 1 > rl0) s[nc][1] = -1e30f;
                if (cl     > rl1) s[nc][2] = -1e30f;
                if (cl + 1 > rl1) s[nc][3] = -1e30f;
            }
        }

        // Row max across the quad
        float mt0 = -1e30f, mt1 = -1e30f;
        #pragma unroll
        for (int nc = 0; nc < 8; nc++) {
            mt0 = fmaxf(mt0, fmaxf(s[nc][0], s[nc][1]));
            mt1 = fmaxf(mt1, fmaxf(s[nc][2], s[nc][3]));
        }
        mt0 = fmaxf(mt0, __shfl_xor_sync(0xffffffffu, mt0, 1));
        mt0 = fmaxf(mt0, __shfl_xor_sync(0xffffffffu, mt0, 2));
        mt1 = fmaxf(mt1, __shfl_xor_sync(0xffffffffu, mt1, 1));
        mt1 = fmaxf(mt1, __shfl_xor_sync(0xffffffffu, mt1, 2));

        float mn0 = fmaxf(m0, mt0), mn1 = fmaxf(m1, mt1);
        float corr0 = exp2f((m0 - mn0) * LOG2E);
        float corr1 = exp2f((m1 - mn1) * LOG2E);

        float rs0 = 0.f, rs1 = 0.f;
        #pragma unroll
        for (int nc = 0; nc < 8; nc++) {
            s[nc][0] = exp2f((s[nc][0] - mn0) * LOG2E);
            s[nc][1] = exp2f((s[nc][1] - mn0) * LOG2E);
            s[nc][2] = exp2f((s[nc][2] - mn1) * LOG2E);
            s[nc][3] = exp2f((s[nc][3] - mn1) * LOG2E);
            rs0 += s[nc][0] + s[nc][1];
            rs1 += s[nc][2] + s[nc][3];
        }
        rs0 += __shfl_xor_sync(0xffffffffu, rs0, 1);
        rs0 += __shfl_xor_sync(0xffffffffu, rs0, 2);
        rs1 += __shfl_xor_sync(0xffffffffu, rs1, 1);
        rs1 += __shfl_xor_sync(0xffffffffu, rs1, 2);
        l0 = l0 * corr0 + rs0;
        l1 = l1 * corr1 + rs1;

        #pragma unroll
        for (int nc = 0; nc < 8; nc++) {
            o[nc][0] *= corr0; o[nc][1] *= corr0;
            o[nc][2] *= corr1; o[nc][3] *= corr1;
        }

        // Repack P (C-frag -> A-frag) interleaved with PV MMAs: pa lives 4 regs
        const int  src1 = (lane & ~3) | (t >> 1);
        const int  src2 = src1 + 2;
        const bool odd  = (t & 1);
        #pragma unroll
        for (int kc = 0; kc < 8; kc++) {
            float v00 = __shfl_sync(0xffffffffu, s[kc][0], src1);
            float v01 = __shfl_sync(0xffffffffu, s[kc][1], src1);
            float v10 = __shfl_sync(0xffffffffu, s[kc][2], src1);
            float v11 = __shfl_sync(0xffffffffu, s[kc][3], src1);
            float w00 = __shfl_sync(0xffffffffu, s[kc][0], src2);
            float w01 = __shfl_sync(0xffffffffu, s[kc][1], src2);
            float w10 = __shfl_sync(0xffffffffu, s[kc][2], src2);
            float w11 = __shfl_sync(0xffffffffu, s[kc][3], src2);
            unsigned pa[4];
            pa[0] = f2tf(odd ? v01 : v00);
            pa[1] = f2tf(odd ? v11 : v10);
            pa[2] = f2tf(odd ? w01 : w00);
            pa[3] = f2tf(odd ? w11 : w10);
            #pragma unroll
            for (int nc = 0; nc < 8; nc++) {
                unsigned b0 = Vs[kc * 8 + t][nc * 8 + g];
                unsigned b1 = Vs[kc * 8 + t + 4][nc * 8 + g];
                mma_tf32(o[nc], pa, b0, b1);
            }
        }

        m0 = mn0; m1 = mn1;
        __syncthreads();
    }

    // Store unnormalized partials + (m, l)
    float* O0 = g_Os + (size_t)split * R_TOT * HEAD + (rowbase + rl0) * HEAD;
    float* O1 = g_Os + (size_t)split * R_TOT * HEAD + (rowbase + rl1) * HEAD;
    #pragma unroll
    for (int nc = 0; nc < 8; nc++) {
        int col = nc * 8 + 2 * t;
        *(float2*)(O0 + col) = make_float2(o[nc][0], o[nc][1]);
        *(float2*)(O1 + col) = make_float2(o[nc][2], o[nc][3]);
    }
    if (t == 0) {
        int pb = split * R_TOT;
        g_m[pb + rowbase + rl0] = m0;  g_l[pb + rowbase + rl0] = l0;
        g_m[pb + rowbase + rl1] = m1;  g_l[pb + rowbase + rl1] = l1;
    }
}

// ---------------------------------------------------------------------------
// Split-KV combine: one thread per (row, 16-col quarter).
// ---------------------------------------------------------------------------
__global__ void __launch_bounds__(128) combine_kernel(float* __restrict__ out) {
    int gt  = blockIdx.x * 128 + threadIdx.x;
    int row = gt >> 2;
    int qp  = gt & 3;

    float m[SPLIT], l[SPLIT];
    float M = -1e30f;
    #pragma unroll
    for (int s = 0; s < SPLIT; s++) {
        m[s] = g_m[s * R_TOT + row];
        l[s] = g_l[s * R_TOT + row];
        M = fmaxf(M, m[s]);
    }
    float L = 0.f, w[SPLIT];
    #pragma unroll
    for (int s = 0; s < SPLIT; s++) {
        w[s] = exp2f((m[s] - M) * LOG2E);
        L += l[s] * w[s];
    }
    const float inv = 1.f / L;

    float4 acc[4];
    #pragma unroll
    for (int j = 0; j < 4; j++) acc[j] = make_float4(0.f, 0.f, 0.f, 0.f);
    #pragma unroll
    for (int s = 0; s < SPLIT; s++) {
        if (l[s] > 0.f) {
            const float4* p = (const float4*)(g_Os + (size_t)s * R_TOT * HEAD +
                                              (size_t)row * HEAD + qp * 16);
            #pragma unroll
            for (int j = 0; j < 4; j++) {
                float4 v = p[j];
                acc[j].x += w[s] * v.x; acc[j].y += w[s] * v.y;
                acc[j].z += w[s] * v.z; acc[j].w += w[s] * v.w;
            }
        }
    }
    float4* po = (float4*)(out + (size_t)row * HEAD + qp * 16);
    #pragma unroll
    for (int j = 0; j < 4; j++) {
        float4 r = acc[j];
        r.x *= inv; r.y *= inv; r.z *= inv; r.w *= inv;
        po[j] = r;
    }
}

// ---------------------------------------------------------------------------
extern "C" void kernel_launch(void* const* d_in, const int* in_sizes, int n_in,
                              void* d_out, int out_size) {
    const float* x  = (const float*)d_in[0];
    const float* Wq = (const float*)d_in[1];
    const float* Wk = (const float*)d_in[2];
    const float* Wv = (const float*)d_in[3];
    float* out = (float*)d_out;

    theta_kernel<<<1, 32>>>();
    rope_table_kernel<<<(S_LEN * HALF + 255) / 256, 256>>>();
    wfrag_kernel<<<(3 * NKS * 8 * 32 + 255) / 256, 256>>>(Wq, Wk, Wv);
    proj_mma_kernel<<<dim3(R_TOT / 128, 3), 256>>>(x);
    attn_mma_kernel<<<64 * B_SZ * SPLIT, 128>>>();
    combine_kernel<<<(R_TOT * 4) / 128, 128>>>(out);
}

// round 5
// speedup vs baseline: 4.9011x; 1.3109x over previous
#include <cuda_runtime.h>
#include <math.h>

#define B_SZ    4
#define S_LEN   4096
#define D_MODEL 1024
#define HEAD    64
#define R_TOT   (B_SZ * S_LEN)
#define HALF    (HEAD / 2)
#define LOG2E   1.4426950408889634f
#define SPLIT   4
#define NKS     (D_MODEL / 8)   // 128 k-slices

// Scratch (allocation-free rule: __device__ globals)
__device__ float g_Q[R_TOT * HEAD];
__device__ float g_K[R_TOT * HEAD];
__device__ float g_V[R_TOT * HEAD];
__device__ float g_sin[S_LEN * HALF];
__device__ float g_cos[S_LEN * HALF];
__device__ float g_theta[HALF];
__device__ float g_Os[(size_t)SPLIT * R_TOT * HEAD];
__device__ float g_m[SPLIT * R_TOT];
__device__ float g_l[SPLIT * R_TOT];
// Precomputed W B-fragments: [which][ks][nc][lane] = {b0hi, b1hi, b0lo, b1lo}
__device__ unsigned g_Wf[3][NKS][8][32][4];

// ---------------------------------------------------------------------------
__device__ __forceinline__ unsigned f2tf(float f) {
    unsigned u;
    asm("cvt.rna.tf32.f32 %0, %1;" : "=r"(u) : "f"(f));
    return u;
}

__device__ __forceinline__ void mma_tf32(float c[4], const unsigned a[4],
                                         unsigned b0, unsigned b1) {
    asm volatile(
        "mma.sync.aligned.m16n8k8.row.col.f32.tf32.tf32.f32 "
        "{%0,%1,%2,%3}, {%4,%5,%6,%7}, {%8,%9}, {%0,%1,%2,%3};\n"
        : "+f"(c[0]), "+f"(c[1]), "+f"(c[2]), "+f"(c[3])
        : "r"(a[0]), "r"(a[1]), "r"(a[2]), "r"(a[3]), "r"(b0), "r"(b1));
}

// ---------------------------------------------------------------------------
__global__ void theta_kernel() {
    int i = threadIdx.x;
    if (i < HALF) g_theta[i] = (float)pow(10000.0, -(double)i / (double)HALF);
}

// RoPE table: freq = fp32(s * theta_fp32); accurate sin/cos via double range
// reduction + fp32 Taylor on |r|<=pi/4.
__global__ void rope_table_kernel() {
    int idx = blockIdx.x * blockDim.x + threadIdx.x;
    if (idx >= S_LEN * HALF) return;
    int s = idx >> 5;
    int i = idx & (HALF - 1);
    float fr = (float)s * g_theta[i];

    double x  = (double)fr;
    double kd = rint(x * 0.6366197723675814);
    int    k  = (int)kd;
    double r  = fma(-kd, 1.5707963267948966, x);
    r         = fma(-kd, 6.123233995736766e-17, r);
    float rf = (float)r;
    float r2 = rf * rf;
    float sp = rf * (1.f + r2 * (-1.66666667e-1f + r2 * (8.33333310e-3f +
               r2 * (-1.98412698e-4f + r2 * 2.75573140e-6f))));
    float cp = 1.f + r2 * (-0.5f + r2 * (4.16666679e-2f +
               r2 * (-1.38888892e-3f + r2 * 2.47868524e-5f)));
    float sn, cs;
    switch (k & 3) {
        case 0:  sn = sp;  cs = cp;  break;
        case 1:  sn = cp;  cs = -sp; break;
        case 2:  sn = -sp; cs = -cp; break;
        default: sn = -cp; cs = sp;  break;
    }
    g_sin[idx] = sn;
    g_cos[idx] = cs;
}

// ---------------------------------------------------------------------------
// Precompute W B-fragments (hi/lo tf32 split) for the projection MMAs.
// ---------------------------------------------------------------------------
__global__ void wfrag_kernel(const float* __restrict__ Wq,
                             const float* __restrict__ Wk,
                             const float* __restrict__ Wv) {
    int tid = blockIdx.x * 256 + threadIdx.x;
    if (tid >= 3 * NKS * 8 * 32) return;
    int lane  = tid & 31;
    int nc    = (tid >> 5) & 7;
    int ks    = (tid >> 8) & (NKS - 1);
    int which = tid >> 15;
    const float* W = (which == 0) ? Wq : (which == 1) ? Wk : Wv;
    int g = lane >> 2, t = lane & 3;
    int n = nc * 8 + g;
    float w0 = W[(ks * 8 + t) * HEAD + n];
    float w1 = W[(ks * 8 + t + 4) * HEAD + n];
    unsigned h0 = f2tf(w0), h1 = f2tf(w1);
    unsigned l0 = f2tf(w0 - __uint_as_float(h0));
    unsigned l1 = f2tf(w1 - __uint_as_float(h1));
    uint4 v = make_uint4(h0, h1, l0, l1);
    *(uint4*)&g_Wf[which][ks][nc][lane][0] = v;
}

// ---------------------------------------------------------------------------
// Tensor-core projection v2 (3xtf32) + fused RoPE epilogue.
// Block = 128 threads (4 warps); block tile 128 rows x 64 cols; each warp
// owns 32 rows (two m16 fragments). Per 64-wide K chunk: x chunk AND the
// matching W-fragment slice (32 KB, contiguous) are staged in smem, so the
// inner loop is LDS-only + MMA (6 MMAs per B-fragment load).
// Dynamic smem: xs[128][68] floats (34816 B) + wfs 2048 uint4 (32768 B).
// ---------------------------------------------------------------------------
#define XS_STRIDE 68
#define XS_BYTES  (128 * XS_STRIDE * 4)

__global__ void __launch_bounds__(128, 3) proj_mma_kernel(const float* __restrict__ x) {
    extern __shared__ char psm[];
    float* xs  = (float*)psm;                    // [128][68]
    uint4* wfs = (uint4*)(psm + XS_BYTES);       // [8 ks][8 nc][32 lane]

    const int which = blockIdx.y;
    float* __restrict__ outp = (which == 0) ? g_Q : (which == 1) ? g_K : g_V;
    const uint4* __restrict__ wsrc = (const uint4*)&g_Wf[which][0][0][0][0];

    const int tid  = threadIdx.x;
    const int warp = tid >> 5;
    const int lane = tid & 31;
    const int g    = lane >> 2;
    const int t    = lane & 3;
    const int row0 = blockIdx.x * 128;
    const int r0   = warp * 32 + g;     // tile0 rows r0, r0+8; tile1 +16

    float c0[8][4] = {}, c1[8][4] = {};

    for (int kc = 0; kc < D_MODEL; kc += 64) {
        // Stage x chunk: 128 rows x 64 cols (coalesced 2 rows/warp rounds)
        #pragma unroll
        for (int j = 0; j < 16; j++) {
            int idx = j * 128 + tid;
            int r = idx >> 4, c4 = idx & 15;
            *(float4*)&xs[r * XS_STRIDE + c4 * 4] =
                *(const float4*)(x + (size_t)(row0 + r) * D_MODEL + kc + c4 * 4);
        }
        // Stage W-fragment slice: 8 ks x 8 nc x 32 lanes, contiguous 32 KB
        {
            const uint4* src = wsrc + (size_t)(kc >> 3) * 256;   // ks stride = 8*32 uint4
            #pragma unroll
            for (int j = 0; j < 16; j++)
                wfs[j * 128 + tid] = src[j * 128 + tid];
        }
        __syncthreads();

        #pragma unroll
        for (int ks = 0; ks < 8; ks++) {
            const int cb = ks * 8 + t;
            float a0 = xs[r0 * XS_STRIDE + cb];
            float a1 = xs[(r0 + 8) * XS_STRIDE + cb];
            float a2 = xs[r0 * XS_STRIDE + cb + 4];
            float a3 = xs[(r0 + 8) * XS_STRIDE + cb + 4];
            float a4 = xs[(r0 + 16) * XS_STRIDE + cb];
            float a5 = xs[(r0 + 24) * XS_STRIDE + cb];
            float a6 = xs[(r0 + 16) * XS_STRIDE + cb + 4];
            float a7 = xs[(r0 + 24) * XS_STRIDE + cb + 4];
            unsigned ah0[4], al0[4], ah1[4], al1[4];
            ah0[0] = f2tf(a0); al0[0] = f2tf(a0 - __uint_as_float(ah0[0]));
            ah0[1] = f2tf(a1); al0[1] = f2tf(a1 - __uint_as_float(ah0[1]));
            ah0[2] = f2tf(a2); al0[2] = f2tf(a2 - __uint_as_float(ah0[2]));
            ah0[3] = f2tf(a3); al0[3] = f2tf(a3 - __uint_as_float(ah0[3]));
            ah1[0] = f2tf(a4); al1[0] = f2tf(a4 - __uint_as_float(ah1[0]));
            ah1[1] = f2tf(a5); al1[1] = f2tf(a5 - __uint_as_float(ah1[1]));
            ah1[2] = f2tf(a6); al1[2] = f2tf(a6 - __uint_as_float(ah1[2]));
            ah1[3] = f2tf(a7); al1[3] = f2tf(a7 - __uint_as_float(ah1[3]));

            const uint4* wrow = wfs + ks * 256 + lane;
            #pragma unroll
            for (int nc = 0; nc < 8; nc++) {
                uint4 b = wrow[nc * 32];
                mma_tf32(c0[nc], ah0, b.x, b.y);
                mma_tf32(c0[nc], ah0, b.z, b.w);
                mma_tf32(c0[nc], al0, b.x, b.y);
                mma_tf32(c1[nc], ah1, b.x, b.y);
                mma_tf32(c1[nc], ah1, b.z, b.w);
                mma_tf32(c1[nc], al1, b.x, b.y);
            }
        }
        __syncthreads();
    }

    // Epilogue: RoPE on C fragments (cols 2t, 2t+1 are exactly a rope pair)
    #pragma unroll
    for (int tt = 0; tt < 2; tt++) {
        float (*cc)[4] = (tt == 0) ? c0 : c1;
        const int gr0 = row0 + r0 + tt * 16;
        const int s0  = gr0 & (S_LEN - 1);
        const int s1  = (gr0 + 8) & (S_LEN - 1);
        #pragma unroll
        for (int nc = 0; nc < 8; nc++) {
            int col = nc * 8 + 2 * t;
            float v0 = cc[nc][0], v1 = cc[nc][1], v2 = cc[nc][2], v3 = cc[nc][3];
            float2 o0, o1;
            if (which < 2) {
                int i0 = col >> 1;
                float sn0 = g_sin[s0 * HALF + i0], cs0 = g_cos[s0 * HALF + i0];
                float sn1 = g_sin[s1 * HALF + i0], cs1 = g_cos[s1 * HALF + i0];
                o0 = make_float2(v0 * cs0 - v1 * sn0, v1 * cs0 + v0 * sn0);
                o1 = make_float2(v2 * cs1 - v3 * sn1, v3 * cs1 + v2 * sn1);
            } else {
                o0 = make_float2(v0, v1);
                o1 = make_float2(v2, v3);
            }
            *(float2*)(outp + (size_t)gr0 * HEAD + col)       = o0;
            *(float2*)(outp + (size_t)(gr0 + 8) * HEAD + col) = o1;
        }
    }
}

// ---------------------------------------------------------------------------
// Tensor-core flash attention, 4-way split-KV (tf32 MMA).
// ---------------------------------------------------------------------------
__global__ void __launch_bounds__(128, 4) attn_mma_kernel() {
    __shared__ unsigned Ks[64][68];
    __shared__ unsigned Vs[64][68];

    const int tid   = threadIdx.x;
    const int warp  = tid >> 5;
    const int lane  = tid & 31;
    const int g     = lane >> 2;
    const int t     = lane & 3;
    const int idx   = blockIdx.x;
    const int qt    = 63 - (idx >> 4);
    const int rem   = idx & 15;
    const int batch = rem >> 2;
    const int split = rem & 3;
    const int q0    = qt * 64;
    const int n     = qt + 1;
    const int lo    = (split * n) >> 2;
    const int hi    = ((split + 1) * n) >> 2;

    const int    rl0     = warp * 16 + g, rl1 = rl0 + 8;
    const size_t rowbase = (size_t)batch * S_LEN + q0;

    if (lo == hi) {
        if (t == 0) {
            int pb = split * R_TOT;
            g_m[pb + rowbase + rl0] = -1e30f;  g_l[pb + rowbase + rl0] = 0.f;
            g_m[pb + rowbase + rl1] = -1e30f;  g_l[pb + rowbase + rl1] = 0.f;
        }
        return;
    }

    // Q tile -> smem (scaled + tf32) -> register A-fragments
    {
        const float4* Qg = (const float4*)(g_Q + rowbase * HEAD);
        for (int i = tid; i < 1024; i += 128) {
            int row = i >> 4, c4 = i & 15;
            float4 v = Qg[i];
            uint4 u;
            u.x = f2tf(v.x * 0.125f); u.y = f2tf(v.y * 0.125f);
            u.z = f2tf(v.z * 0.125f); u.w = f2tf(v.w * 0.125f);
            *(uint4*)&Ks[row][c4 * 4] = u;
        }
    }
    __syncthreads();
    unsigned qa[8][4];
    {
        const int r0 = warp * 16 + g;
        #pragma unroll
        for (int kc = 0; kc < 8; kc++) {
            qa[kc][0] = Ks[r0][kc * 8 + t];
            qa[kc][1] = Ks[r0 + 8][kc * 8 + t];
            qa[kc][2] = Ks[r0][kc * 8 + t + 4];
            qa[kc][3] = Ks[r0 + 8][kc * 8 + t + 4];
        }
    }
    __syncthreads();

    float o[8][4];
    #pragma unroll
    for (int nc = 0; nc < 8; nc++) { o[nc][0] = o[nc][1] = o[nc][2] = o[nc][3] = 0.f; }
    float m0 = -1e30f, m1 = -1e30f, l0 = 0.f, l1 = 0.f;

    for (int jt = lo; jt < hi; jt++) {
        const float4* Kg = (const float4*)(g_K + ((size_t)batch * S_LEN + jt * 64) * HEAD);
        const float4* Vg = (const float4*)(g_V + ((size_t)batch * S_LEN + jt * 64) * HEAD);
        for (int i = tid; i < 1024; i += 128) {
            int row = i >> 4, c4 = i & 15;
            float4 kv = Kg[i];
            uint4 ku;
            ku.x = f2tf(kv.x); ku.y = f2tf(kv.y); ku.z = f2tf(kv.z); ku.w = f2tf(kv.w);
            *(uint4*)&Ks[row][c4 * 4] = ku;
            float4 vv = Vg[i];
            uint4 vu;
            vu.x = f2tf(vv.x); vu.y = f2tf(vv.y); vu.z = f2tf(vv.z); vu.w = f2tf(vv.w);
            *(uint4*)&Vs[row][c4 * 4] = vu;
        }
        __syncthreads();

        // S = Q K^T
        float s[8][4];
        #pragma unroll
        for (int nc = 0; nc < 8; nc++) {
            s[nc][0] = s[nc][1] = s[nc][2] = s[nc][3] = 0.f;
            #pragma unroll
            for (int kc = 0; kc < 8; kc++) {
                unsigned b0 = Ks[nc * 8 + g][kc * 8 + t];
                unsigned b1 = Ks[nc * 8 + g][kc * 8 + t + 4];
                mma_tf32(s[nc], qa[kc], b0, b1);
            }
        }

        // Causal mask (diagonal tile only)
        if (jt == qt) {
            #pragma unroll
            for (int nc = 0; nc < 8; nc++) {
                int cl = nc * 8 + 2 * t;
                if (cl     > rl0) s[nc][0] = -1e30f;
                if (cl + 1 > rl0) s[nc][1] = -1e30f;
                if (cl     > rl1) s[nc][2] = -1e30f;
                if (cl + 1 > rl1) s[nc][3] = -1e30f;
            }
        }

        // Row max across the quad
        float mt0 = -1e30f, mt1 = -1e30f;
        #pragma unroll
        for (int nc = 0; nc < 8; nc++) {
            mt0 = fmaxf(mt0, fmaxf(s[nc][0], s[nc][1]));
            mt1 = fmaxf(mt1, fmaxf(s[nc][2], s[nc][3]));
        }
        mt0 = fmaxf(mt0, __shfl_xor_sync(0xffffffffu, mt0, 1));
        mt0 = fmaxf(mt0, __shfl_xor_sync(0xffffffffu, mt0, 2));
        mt1 = fmaxf(mt1, __shfl_xor_sync(0xffffffffu, mt1, 1));
        mt1 = fmaxf(mt1, __shfl_xor_sync(0xffffffffu, mt1, 2));

        float mn0 = fmaxf(m0, mt0), mn1 = fmaxf(m1, mt1);
        float corr0 = exp2f((m0 - mn0) * LOG2E);
        float corr1 = exp2f((m1 - mn1) * LOG2E);

        float rs0 = 0.f, rs1 = 0.f;
        #pragma unroll
        for (int nc = 0; nc < 8; nc++) {
            s[nc][0] = exp2f((s[nc][0] - mn0) * LOG2E);
            s[nc][1] = exp2f((s[nc][1] - mn0) * LOG2E);
            s[nc][2] = exp2f((s[nc][2] - mn1) * LOG2E);
            s[nc][3] = exp2f((s[nc][3] - mn1) * LOG2E);
            rs0 += s[nc][0] + s[nc][1];
            rs1 += s[nc][2] + s[nc][3];
        }
        rs0 += __shfl_xor_sync(0xffffffffu, rs0, 1);
        rs0 += __shfl_xor_sync(0xffffffffu, rs0, 2);
        rs1 += __shfl_xor_sync(0xffffffffu, rs1, 1);
        rs1 += __shfl_xor_sync(0xffffffffu, rs1, 2);
        l0 = l0 * corr0 + rs0;
        l1 = l1 * corr1 + rs1;

        #pragma unroll
        for (int nc = 0; nc < 8; nc++) {
            o[nc][0] *= corr0; o[nc][1] *= corr0;
            o[nc][2] *= corr1; o[nc][3] *= corr1;
        }

        // Repack P (C-frag -> A-frag) interleaved with PV MMAs
        const int  src1 = (lane & ~3) | (t >> 1);
        const int  src2 = src1 + 2;
        const bool odd  = (t & 1);
        #pragma unroll
        for (int kc = 0; kc < 8; kc++) {
            float v00 = __shfl_sync(0xffffffffu, s[kc][0], src1);
            float v01 = __shfl_sync(0xffffffffu, s[kc][1], src1);
            float v10 = __shfl_sync(0xffffffffu, s[kc][2], src1);
            float v11 = __shfl_sync(0xffffffffu, s[kc][3], src1);
            float w00 = __shfl_sync(0xffffffffu, s[kc][0], src2);
            float w01 = __shfl_sync(0xffffffffu, s[kc][1], src2);
            float w10 = __shfl_sync(0xffffffffu, s[kc][2], src2);
            float w11 = __shfl_sync(0xffffffffu, s[kc][3], src2);
            unsigned pa[4];
            pa[0] = f2tf(odd ? v01 : v00);
            pa[1] = f2tf(odd ? v11 : v10);
            pa[2] = f2tf(odd ? w01 : w00);
            pa[3] = f2tf(odd ? w11 : w10);
            #pragma unroll
            for (int nc = 0; nc < 8; nc++) {
                unsigned b0 = Vs[kc * 8 + t][nc * 8 + g];
                unsigned b1 = Vs[kc * 8 + t + 4][nc * 8 + g];
                mma_tf32(o[nc], pa, b0, b1);
            }
        }

        m0 = mn0; m1 = mn1;
        __syncthreads();
    }

    // Store unnormalized partials + (m, l)
    float* O0 = g_Os + (size_t)split * R_TOT * HEAD + (rowbase + rl0) * HEAD;
    float* O1 = g_Os + (size_t)split * R_TOT * HEAD + (rowbase + rl1) * HEAD;
    #pragma unroll
    for (int nc = 0; nc < 8; nc++) {
        int col = nc * 8 + 2 * t;
        *(float2*)(O0 + col) = make_float2(o[nc][0], o[nc][1]);
        *(float2*)(O1 + col) = make_float2(o[nc][2], o[nc][3]);
    }
    if (t == 0) {
        int pb = split * R_TOT;
        g_m[pb + rowbase + rl0] = m0;  g_l[pb + rowbase + rl0] = l0;
        g_m[pb + rowbase + rl1] = m1;  g_l[pb + rowbase + rl1] = l1;
    }
}

// ---------------------------------------------------------------------------
// Split-KV combine: one thread per (row, 16-col quarter).
// ---------------------------------------------------------------------------
__global__ void __launch_bounds__(128) combine_kernel(float* __restrict__ out) {
    int gt  = blockIdx.x * 128 + threadIdx.x;
    int row = gt >> 2;
    int qp  = gt & 3;

    float m[SPLIT], l[SPLIT];
    float M = -1e30f;
    #pragma unroll
    for (int s = 0; s < SPLIT; s++) {
        m[s] = g_m[s * R_TOT + row];
        l[s] = g_l[s * R_TOT + row];
        M = fmaxf(M, m[s]);
    }
    float L = 0.f, w[SPLIT];
    #pragma unroll
    for (int s = 0; s < SPLIT; s++) {
        w[s] = exp2f((m[s] - M) * LOG2E);
        L += l[s] * w[s];
    }
    const float inv = 1.f / L;

    float4 acc[4];
    #pragma unroll
    for (int j = 0; j < 4; j++) acc[j] = make_float4(0.f, 0.f, 0.f, 0.f);
    #pragma unroll
    for (int s = 0; s < SPLIT; s++) {
        if (l[s] > 0.f) {
            const float4* p = (const float4*)(g_Os + (size_t)s * R_TOT * HEAD +
                                              (size_t)row * HEAD + qp * 16);
            #pragma unroll
            for (int j = 0; j < 4; j++) {
                float4 v = p[j];
                acc[j].x += w[s] * v.x; acc[j].y += w[s] * v.y;
                acc[j].z += w[s] * v.z; acc[j].w += w[s] * v.w;
            }
        }
    }
    float4* po = (float4*)(out + (size_t)row * HEAD + qp * 16);
    #pragma unroll
    for (int j = 0; j < 4; j++) {
        float4 r = acc[j];
        r.x *= inv; r.y *= inv; r.z *= inv; r.w *= inv;
        po[j] = r;
    }
}

// ---------------------------------------------------------------------------
extern "C" void kernel_launch(void* const* d_in, const int* in_sizes, int n_in,
                              void* d_out, int out_size) {
    const float* x  = (const float*)d_in[0];
    const float* Wq = (const float*)d_in[1];
    const float* Wk = (const float*)d_in[2];
    const float* Wv = (const float*)d_in[3];
    float* out = (float*)d_out;

    const int proj_smem = XS_BYTES + 8 * 8 * 32 * 16;   // 34816 + 32768 = 67584
    cudaFuncSetAttribute(proj_mma_kernel,
                         cudaFuncAttributeMaxDynamicSharedMemorySize, proj_smem);

    theta_kernel<<<1, 32>>>();
    rope_table_kernel<<<(S_LEN * HALF + 255) / 256, 256>>>();
    wfrag_kernel<<<(3 * NKS * 8 * 32 + 255) / 256, 256>>>(Wq, Wk, Wv);
    proj_mma_kernel<<<dim3(R_TOT / 128, 3), 128, proj_smem>>>(x);
    attn_mma_kernel<<<64 * B_SZ * SPLIT, 128>>>();
    combine_kernel<<<(R_TOT * 4) / 128, 128>>>(out);
}

// round 6
// speedup vs baseline: 6.0306x; 1.2305x over previous
#include <cuda_runtime.h>
#include <cuda_bf16.h>
#include <math.h>

#define B_SZ    4
#define S_LEN   4096
#define D_MODEL 1024
#define HEAD    64
#define R_TOT   (B_SZ * S_LEN)
#define HALF    (HEAD / 2)
#define LOG2E   1.4426950408889634f
#define SPLIT   4
#define NK16    (D_MODEL / 16)   // 64 k16-slices

// Scratch (allocation-free rule: __device__ globals)
__device__ float g_Q[R_TOT * HEAD];
__device__ float g_K[R_TOT * HEAD];
__device__ float g_V[R_TOT * HEAD];
__device__ float g_sin[S_LEN * HALF];
__device__ float g_cos[S_LEN * HALF];
__device__ float g_theta[HALF];
__device__ float g_Os[(size_t)SPLIT * R_TOT * HEAD];
__device__ float g_m[SPLIT * R_TOT];
__device__ float g_l[SPLIT * R_TOT];
// Precomputed W B-fragments (bf16 hi/lo): [which][k16][nc][lane] = {b0h,b1h,b0l,b1l}
__device__ unsigned g_Wf[3][NK16][8][32][4];

// ---------------------------------------------------------------------------
__device__ __forceinline__ unsigned f2tf(float f) {
    unsigned u;
    asm("cvt.rna.tf32.f32 %0, %1;" : "=r"(u) : "f"(f));
    return u;
}

__device__ __forceinline__ void mma_tf32(float c[4], const unsigned a[4],
                                         unsigned b0, unsigned b1) {
    asm volatile(
        "mma.sync.aligned.m16n8k8.row.col.f32.tf32.tf32.f32 "
        "{%0,%1,%2,%3}, {%4,%5,%6,%7}, {%8,%9}, {%0,%1,%2,%3};\n"
        : "+f"(c[0]), "+f"(c[1]), "+f"(c[2]), "+f"(c[3])
        : "r"(a[0]), "r"(a[1]), "r"(a[2]), "r"(a[3]), "r"(b0), "r"(b1));
}

__device__ __forceinline__ void mma_bf16(float c[4], const unsigned a[4],
                                         unsigned b0, unsigned b1) {
    asm volatile(
        "mma.sync.aligned.m16n8k16.row.col.f32.bf16.bf16.f32 "
        "{%0,%1,%2,%3}, {%4,%5,%6,%7}, {%8,%9}, {%0,%1,%2,%3};\n"
        : "+f"(c[0]), "+f"(c[1]), "+f"(c[2]), "+f"(c[3])
        : "r"(a[0]), "r"(a[1]), "r"(a[2]), "r"(a[3]), "r"(b0), "r"(b1));
}

// Split a float pair into packed bf16x2 hi + lo (x -> low half = first k elem)
__device__ __forceinline__ void bfsplit(float fx, float fy,
                                        unsigned& hi, unsigned& lo) {
    __nv_bfloat162 hp = __floats2bfloat162_rn(fx, fy);
    float2 hf = __bfloat1622float2(hp);
    __nv_bfloat162 lp = __floats2bfloat162_rn(fx - hf.x, fy - hf.y);
    hi = *(unsigned*)&hp;
    lo = *(unsigned*)&lp;
}

// ---------------------------------------------------------------------------
__global__ void theta_kernel() {
    int i = threadIdx.x;
    if (i < HALF) g_theta[i] = (float)pow(10000.0, -(double)i / (double)HALF);
}

// RoPE table: freq = fp32(s * theta_fp32); accurate sin/cos via double range
// reduction + fp32 Taylor on |r|<=pi/4.
__global__ void rope_table_kernel() {
    int idx = blockIdx.x * blockDim.x + threadIdx.x;
    if (idx >= S_LEN * HALF) return;
    int s = idx >> 5;
    int i = idx & (HALF - 1);
    float fr = (float)s * g_theta[i];

    double x  = (double)fr;
    double kd = rint(x * 0.6366197723675814);
    int    k  = (int)kd;
    double r  = fma(-kd, 1.5707963267948966, x);
    r         = fma(-kd, 6.123233995736766e-17, r);
    float rf = (float)r;
    float r2 = rf * rf;
    float sp = rf * (1.f + r2 * (-1.66666667e-1f + r2 * (8.33333310e-3f +
               r2 * (-1.98412698e-4f + r2 * 2.75573140e-6f))));
    float cp = 1.f + r2 * (-0.5f + r2 * (4.16666679e-2f +
               r2 * (-1.38888892e-3f + r2 * 2.47868524e-5f)));
    float sn, cs;
    switch (k & 3) {
        case 0:  sn = sp;  cs = cp;  break;
        case 1:  sn = cp;  cs = -sp; break;
        case 2:  sn = -sp; cs = -cp; break;
        default: sn = -cp; cs = sp;  break;
    }
    g_sin[idx] = sn;
    g_cos[idx] = cs;
}

// ---------------------------------------------------------------------------
// Precompute W B-fragments (bf16 hi/lo split) for m16n8k16 projection MMAs.
// B-frag layout: b0 = {W[16ks+2t][n], W[16ks+2t+1][n]}, b1 = rows +8.
// ---------------------------------------------------------------------------
__global__ void wfrag_kernel(const float* __restrict__ Wq,
                             const float* __restrict__ Wk,
                             const float* __restrict__ Wv) {
    int tid = blockIdx.x * 256 + threadIdx.x;
    if (tid >= 3 * NK16 * 8 * 32) return;
    int lane  = tid & 31;
    int nc    = (tid >> 5) & 7;
    int ks    = (tid >> 8) & (NK16 - 1);
    int which = tid >> 14;
    const float* W = (which == 0) ? Wq : (which == 1) ? Wk : Wv;
    int g = lane >> 2, t = lane & 3;
    int n = nc * 8 + g;
    int k0 = ks * 16 + 2 * t;
    float w00 = W[(k0    ) * HEAD + n];
    float w01 = W[(k0 + 1) * HEAD + n];
    float w10 = W[(k0 + 8) * HEAD + n];
    float w11 = W[(k0 + 9) * HEAD + n];
    unsigned b0h, b0l, b1h, b1l;
    bfsplit(w00, w01, b0h, b0l);
    bfsplit(w10, w11, b1h, b1l);
    *(uint4*)&g_Wf[which][ks][nc][lane][0] = make_uint4(b0h, b1h, b0l, b1l);
}

// ---------------------------------------------------------------------------
// Tensor-core projection v3 (bf16 hi/lo 3-split, m16n8k16) + fused RoPE.
// Block = 128 threads (4 warps); tile 128 rows x 64 cols; warp owns 32 rows.
// Per 64-col chunk: x chunk (34.8KB) + W-frag slice (16KB) staged in smem.
// ---------------------------------------------------------------------------
#define XS_STRIDE 68
#define XS_BYTES  (128 * XS_STRIDE * 4)
#define WF_UINT4  (4 * 8 * 32)              // 4 k16-steps x 8 nc x 32 lanes
#define PROJ_SMEM (XS_BYTES + WF_UINT4 * 16)

__global__ void __launch_bounds__(128, 3) proj_mma_kernel(const float* __restrict__ x) {
    extern __shared__ char psm[];
    float* xs  = (float*)psm;                    // [128][68]
    uint4* wfs = (uint4*)(psm + XS_BYTES);       // [4 ks][8 nc][32 lane]

    const int which = blockIdx.y;
    float* __restrict__ outp = (which == 0) ? g_Q : (which == 1) ? g_K : g_V;
    const uint4* __restrict__ wsrc = (const uint4*)&g_Wf[which][0][0][0][0];

    const int tid  = threadIdx.x;
    const int warp = tid >> 5;
    const int lane = tid & 31;
    const int g    = lane >> 2;
    const int t    = lane & 3;
    const int row0 = blockIdx.x * 128;
    const int r0   = warp * 32 + g;

    float c0[8][4] = {}, c1[8][4] = {};

    for (int kc = 0; kc < D_MODEL; kc += 64) {
        // Stage x chunk: 128 rows x 64 cols
        #pragma unroll
        for (int j = 0; j < 16; j++) {
            int idx = j * 128 + tid;
            int r = idx >> 4, c4 = idx & 15;
            *(float4*)&xs[r * XS_STRIDE + c4 * 4] =
                *(const float4*)(x + (size_t)(row0 + r) * D_MODEL + kc + c4 * 4);
        }
        // Stage W-fragment slice: 4 k16 x 8 nc x 32 lanes = 16 KB contiguous
        {
            const uint4* src = wsrc + (size_t)(kc >> 4) * 256;
            #pragma unroll
            for (int j = 0; j < 8; j++)
                wfs[j * 128 + tid] = src[j * 128 + tid];
        }
        __syncthreads();

        #pragma unroll
        for (int ks = 0; ks < 4; ks++) {
            const int cb = ks * 16 + 2 * t;
            float2 f00 = *(float2*)&xs[ r0       * XS_STRIDE + cb];
            float2 f01 = *(float2*)&xs[(r0 +  8) * XS_STRIDE + cb];
            float2 f02 = *(float2*)&xs[ r0       * XS_STRIDE + cb + 8];
            float2 f03 = *(float2*)&xs[(r0 +  8) * XS_STRIDE + cb + 8];
            float2 f10 = *(float2*)&xs[(r0 + 16) * XS_STRIDE + cb];
            float2 f11 = *(float2*)&xs[(r0 + 24) * XS_STRIDE + cb];
            float2 f12 = *(float2*)&xs[(r0 + 16) * XS_STRIDE + cb + 8];
            float2 f13 = *(float2*)&xs[(r0 + 24) * XS_STRIDE + cb + 8];

            unsigned ah0[4], al0[4], ah1[4], al1[4];
            bfsplit(f00.x, f00.y, ah0[0], al0[0]);
            bfsplit(f01.x, f01.y, ah0[1], al0[1]);
            bfsplit(f02.x, f02.y, ah0[2], al0[2]);
            bfsplit(f03.x, f03.y, ah0[3], al0[3]);
            bfsplit(f10.x, f10.y, ah1[0], al1[0]);
            bfsplit(f11.x, f11.y, ah1[1], al1[1]);
            bfsplit(f12.x, f12.y, ah1[2], al1[2]);
            bfsplit(f13.x, f13.y, ah1[3], al1[3]);

            const uint4* wrow = wfs + ks * 256 + lane;
            #pragma unroll
            for (int nc = 0; nc < 8; nc++) {
                uint4 b = wrow[nc * 32];
                mma_bf16(c0[nc], ah0, b.x, b.y);   // hi*hi
                mma_bf16(c0[nc], ah0, b.z, b.w);   // hi*lo
                mma_bf16(c0[nc], al0, b.x, b.y);   // lo*hi
                mma_bf16(c1[nc], ah1, b.x, b.y);
                mma_bf16(c1[nc], ah1, b.z, b.w);
                mma_bf16(c1[nc], al1, b.x, b.y);
            }
        }
        __syncthreads();
    }

    // Epilogue: RoPE on C fragments (cols 2t, 2t+1 are exactly a rope pair)
    #pragma unroll
    for (int tt = 0; tt < 2; tt++) {
        float (*cc)[4] = (tt == 0) ? c0 : c1;
        const int gr0 = row0 + r0 + tt * 16;
        const int s0  = gr0 & (S_LEN - 1);
        const int s1  = (gr0 + 8) & (S_LEN - 1);
        #pragma unroll
        for (int nc = 0; nc < 8; nc++) {
            int col = nc * 8 + 2 * t;
            float v0 = cc[nc][0], v1 = cc[nc][1], v2 = cc[nc][2], v3 = cc[nc][3];
            float2 o0, o1;
            if (which < 2) {
                int i0 = col >> 1;
                float sn0 = g_sin[s0 * HALF + i0], cs0 = g_cos[s0 * HALF + i0];
                float sn1 = g_sin[s1 * HALF + i0], cs1 = g_cos[s1 * HALF + i0];
                o0 = make_float2(v0 * cs0 - v1 * sn0, v1 * cs0 + v0 * sn0);
                o1 = make_float2(v2 * cs1 - v3 * sn1, v3 * cs1 + v2 * sn1);
            } else {
                o0 = make_float2(v0, v1);
                o1 = make_float2(v2, v3);
            }
            *(float2*)(outp + (size_t)gr0 * HEAD + col)       = o0;
            *(float2*)(outp + (size_t)(gr0 + 8) * HEAD + col) = o1;
        }
    }
}

// ---------------------------------------------------------------------------
// Tensor-core flash attention, 4-way split-KV (tf32 MMA).
// ---------------------------------------------------------------------------
__global__ void __launch_bounds__(128, 4) attn_mma_kernel() {
    __shared__ unsigned Ks[64][68];
    __shared__ unsigned Vs[64][68];

    const int tid   = threadIdx.x;
    const int warp  = tid >> 5;
    const int lane  = tid & 31;
    const int g     = lane >> 2;
    const int t     = lane & 3;
    const int idx   = blockIdx.x;
    const int qt    = 63 - (idx >> 4);
    const int rem   = idx & 15;
    const int batch = rem >> 2;
    const int split = rem & 3;
    const int q0    = qt * 64;
    const int n     = qt + 1;
    const int lo    = (split * n) >> 2;
    const int hi    = ((split + 1) * n) >> 2;

    const int    rl0     = warp * 16 + g, rl1 = rl0 + 8;
    const size_t rowbase = (size_t)batch * S_LEN + q0;

    if (lo == hi) {
        if (t == 0) {
            int pb = split * R_TOT;
            g_m[pb + rowbase + rl0] = -1e30f;  g_l[pb + rowbase + rl0] = 0.f;
            g_m[pb + rowbase + rl1] = -1e30f;  g_l[pb + rowbase + rl1] = 0.f;
        }
        return;
    }

    // Q tile -> smem (scaled + tf32) -> register A-fragments
    {
        const float4* Qg = (const float4*)(g_Q + rowbase * HEAD);
        for (int i = tid; i < 1024; i += 128) {
            int row = i >> 4, c4 = i & 15;
            float4 v = Qg[i];
            uint4 u;
            u.x = f2tf(v.x * 0.125f); u.y = f2tf(v.y * 0.125f);
            u.z = f2tf(v.z * 0.125f); u.w = f2tf(v.w * 0.125f);
            *(uint4*)&Ks[row][c4 * 4] = u;
        }
    }
    __syncthreads();
    unsigned qa[8][4];
    {
        const int r0 = warp * 16 + g;
        #pragma unroll
        for (int kc = 0; kc < 8; kc++) {
            qa[kc][0] = Ks[r0][kc * 8 + t];
            qa[kc][1] = Ks[r0 + 8][kc * 8 + t];
            qa[kc][2] = Ks[r0][kc * 8 + t + 4];
            qa[kc][3] = Ks[r0 + 8][kc * 8 + t + 4];
        }
    }
    __syncthreads();

    float o[8][4];
    #pragma unroll
    for (int nc = 0; nc < 8; nc++) { o[nc][0] = o[nc][1] = o[nc][2] = o[nc][3] = 0.f; }
    float m0 = -1e30f, m1 = -1e30f, l0 = 0.f, l1 = 0.f;

    for (int jt = lo; jt < hi; jt++) {
        const float4* Kg = (const float4*)(g_K + ((size_t)batch * S_LEN + jt * 64) * HEAD);
        const float4* Vg = (const float4*)(g_V + ((size_t)batch * S_LEN + jt * 64) * HEAD);
        for (int i = tid; i < 1024; i += 128) {
            int row = i >> 4, c4 = i & 15;
            float4 kv = Kg[i];
            uint4 ku;
            ku.x = f2tf(kv.x); ku.y = f2tf(kv.y); ku.z = f2tf(kv.z); ku.w = f2tf(kv.w);
            *(uint4*)&Ks[row][c4 * 4] = ku;
            float4 vv = Vg[i];
            uint4 vu;
            vu.x = f2tf(vv.x); vu.y = f2tf(vv.y); vu.z = f2tf(vv.z); vu.w = f2tf(vv.w);
            *(uint4*)&Vs[row][c4 * 4] = vu;
        }
        __syncthreads();

        // S = Q K^T
        float s[8][4];
        #pragma unroll
        for (int nc = 0; nc < 8; nc++) {
            s[nc][0] = s[nc][1] = s[nc][2] = s[nc][3] = 0.f;
            #pragma unroll
            for (int kc = 0; kc < 8; kc++) {
                unsigned b0 = Ks[nc * 8 + g][kc * 8 + t];
                unsigned b1 = Ks[nc * 8 + g][kc * 8 + t + 4];
                mma_tf32(s[nc], qa[kc], b0, b1);
            }
        }

        // Causal mask (diagonal tile only)
        if (jt == qt) {
            #pragma unroll
            for (int nc = 0; nc < 8; nc++) {
                int cl = nc * 8 + 2 * t;
                if (cl     > rl0) s[nc][0] = -1e30f;
                if (cl + 1 > rl0) s[nc][1] = -1e30f;
                if (cl     > rl1) s[nc][2] = -1e30f;
                if (cl + 1 > rl1) s[nc][3] = -1e30f;
            }
        }

        // Row max across the quad
        float mt0 = -1e30f, mt1 = -1e30f;
        #pragma unroll
        for (int nc = 0; nc < 8; nc++) {
            mt0 = fmaxf(mt0, fmaxf(s[nc][0], s[nc][1]));
            mt1 = fmaxf(mt1, fmaxf(s[nc][2], s[nc][3]));
        }
        mt0 = fmaxf(mt0, __shfl_xor_sync(0xffffffffu, mt0, 1));
        mt0 = fmaxf(mt0, __shfl_xor_sync(0xffffffffu, mt0, 2));
        mt1 = fmaxf(mt1, __shfl_xor_sync(0xffffffffu, mt1, 1));
        mt1 = fmaxf(mt1, __shfl_xor_sync(0xffffffffu, mt1, 2));

        float mn0 = fmaxf(m0, mt0), mn1 = fmaxf(m1, mt1);
        float corr0 = exp2f((m0 - mn0) * LOG2E);
        float corr1 = exp2f((m1 - mn1) * LOG2E);

        float rs0 = 0.f, rs1 = 0.f;
        #pragma unroll
        for (int nc = 0; nc < 8; nc++) {
            s[nc][0] = exp2f((s[nc][0] - mn0) * LOG2E);
            s[nc][1] = exp2f((s[nc][1] - mn0) * LOG2E);
            s[nc][2] = exp2f((s[nc][2] - mn1) * LOG2E);
            s[nc][3] = exp2f((s[nc][3] - mn1) * LOG2E);
            rs0 += s[nc][0] + s[nc][1];
            rs1 += s[nc][2] + s[nc][3];
        }
        rs0 += __shfl_xor_sync(0xffffffffu, rs0, 1);
        rs0 += __shfl_xor_sync(0xffffffffu, rs0, 2);
        rs1 += __shfl_xor_sync(0xffffffffu, rs1, 1);
        rs1 += __shfl_xor_sync(0xffffffffu, rs1, 2);
        l0 = l0 * corr0 + rs0;
        l1 = l1 * corr1 + rs1;

        #pragma unroll
        for (int nc = 0; nc < 8; nc++) {
            o[nc][0] *= corr0; o[nc][1] *= corr0;
            o[nc][2] *= corr1; o[nc][3] *= corr1;
        }

        // Repack P (C-frag -> A-frag) interleaved with PV MMAs
        const int  src1 = (lane & ~3) | (t >> 1);
        const int  src2 = src1 + 2;
        const bool odd  = (t & 1);
        #pragma unroll
        for (int kc = 0; kc < 8; kc++) {
            float v00 = __shfl_sync(0xffffffffu, s[kc][0], src1);
            float v01 = __shfl_sync(0xffffffffu, s[kc][1], src1);
            float v10 = __shfl_sync(0xffffffffu, s[kc][2], src1);
            float v11 = __shfl_sync(0xffffffffu, s[kc][3], src1);
            float w00 = __shfl_sync(0xffffffffu, s[kc][0], src2);
            float w01 = __shfl_sync(0xffffffffu, s[kc][1], src2);
            float w10 = __shfl_sync(0xffffffffu, s[kc][2], src2);
            float w11 = __shfl_sync(0xffffffffu, s[kc][3], src2);
            unsigned pa[4];
            pa[0] = f2tf(odd ? v01 : v00);
            pa[1] = f2tf(odd ? v11 : v10);
            pa[2] = f2tf(odd ? w01 : w00);
            pa[3] = f2tf(odd ? w11 : w10);
            #pragma unroll
            for (int nc = 0; nc < 8; nc++) {
                unsigned b0 = Vs[kc * 8 + t][nc * 8 + g];
                unsigned b1 = Vs[kc * 8 + t + 4][nc * 8 + g];
                mma_tf32(o[nc], pa, b0, b1);
            }
        }

        m0 = mn0; m1 = mn1;
        __syncthreads();
    }

    // Store unnormalized partials + (m, l)
    float* O0 = g_Os + (size_t)split * R_TOT * HEAD + (rowbase + rl0) * HEAD;
    float* O1 = g_Os + (size_t)split * R_TOT * HEAD + (rowbase + rl1) * HEAD;
    #pragma unroll
    for (int nc = 0; nc < 8; nc++) {
        int col = nc * 8 + 2 * t;
        *(float2*)(O0 + col) = make_float2(o[nc][0], o[nc][1]);
        *(float2*)(O1 + col) = make_float2(o[nc][2], o[nc][3]);
    }
    if (t == 0) {
        int pb = split * R_TOT;
        g_m[pb + rowbase + rl0] = m0;  g_l[pb + rowbase + rl0] = l0;
        g_m[pb + rowbase + rl1] = m1;  g_l[pb + rowbase + rl1] = l1;
    }
}

// ---------------------------------------------------------------------------
// Split-KV combine: one thread per (row, 16-col quarter).
// ---------------------------------------------------------------------------
__global__ void __launch_bounds__(128) combine_kernel(float* __restrict__ out) {
    int gt  = blockIdx.x * 128 + threadIdx.x;
    int row = gt >> 2;
    int qp  = gt & 3;

    float m[SPLIT], l[SPLIT];
    float M = -1e30f;
    #pragma unroll
    for (int s = 0; s < SPLIT; s++) {
        m[s] = g_m[s * R_TOT + row];
        l[s] = g_l[s * R_TOT + row];
        M = fmaxf(M, m[s]);
    }
    float L = 0.f, w[SPLIT];
    #pragma unroll
    for (int s = 0; s < SPLIT; s++) {
        w[s] = exp2f((m[s] - M) * LOG2E);
        L += l[s] * w[s];
    }
    const float inv = 1.f / L;

    float4 acc[4];
    #pragma unroll
    for (int j = 0; j < 4; j++) acc[j] = make_float4(0.f, 0.f, 0.f, 0.f);
    #pragma unroll
    for (int s = 0; s < SPLIT; s++) {
        if (l[s] > 0.f) {
            const float4* p = (const float4*)(g_Os + (size_t)s * R_TOT * HEAD +
                                              (size_t)row * HEAD + qp * 16);
            #pragma unroll
            for (int j = 0; j < 4; j++) {
                float4 v = p[j];
                acc[j].x += w[s] * v.x; acc[j].y += w[s] * v.y;
                acc[j].z += w[s] * v.z; acc[j].w += w[s] * v.w;
            }
        }
    }
    float4* po = (float4*)(out + (size_t)row * HEAD + qp * 16);
    #pragma unroll
    for (int j = 0; j < 4; j++) {
        float4 r = acc[j];
        r.x *= inv; r.y *= inv; r.z *= inv; r.w *= inv;
        po[j] = r;
    }
}

// ---------------------------------------------------------------------------
extern "C" void kernel_launch(void* const* d_in, const int* in_sizes, int n_in,
                              void* d_out, int out_size) {
    const float* x  = (const float*)d_in[0];
    const float* Wq = (const float*)d_in[1];
    const float* Wk = (const float*)d_in[2];
    const float* Wv = (const float*)d_in[3];
    float* out = (float*)d_out;

    cudaFuncSetAttribute(proj_mma_kernel,
                         cudaFuncAttributeMaxDynamicSharedMemorySize, PROJ_SMEM);

    theta_kernel<<<1, 32>>>();
    rope_table_kernel<<<(S_LEN * HALF + 255) / 256, 256>>>();
    wfrag_kernel<<<(3 * NK16 * 8 * 32 + 255) / 256, 256>>>(Wq, Wk, Wv);
    proj_mma_kernel<<<dim3(R_TOT / 128, 3), 128, PROJ_SMEM>>>(x);
    attn_mma_kernel<<<64 * B_SZ * SPLIT, 128>>>();
    combine_kernel<<<(R_TOT * 4) / 128, 128>>>(out);
}

// round 8
// speedup vs baseline: 6.6306x; 1.0995x over previous
#include <cuda_runtime.h>
#include <cuda_bf16.h>
#include <math.h>
#include <stdint.h>

#define B_SZ    4
#define S_LEN   4096
#define D_MODEL 1024
#define HEAD    64
#define R_TOT   (B_SZ * S_LEN)
#define HALF    (HEAD / 2)
#define LOG2E   1.4426950408889634f
#define SPLIT   4
#define NK16    (D_MODEL / 16)   // 64 k16-slices

// Scratch (allocation-free rule: __device__ globals)
// g_Q holds tf32-rounded, 0.125-prescaled Q; g_K/g_V hold tf32-rounded values.
__device__ float g_Q[R_TOT * HEAD];
__device__ float g_K[R_TOT * HEAD];
__device__ float g_V[R_TOT * HEAD];
__device__ float g_sin[S_LEN * HALF];
__device__ float g_cos[S_LEN * HALF];
__device__ float g_theta[HALF];
__device__ float g_Os[(size_t)SPLIT * R_TOT * HEAD];
__device__ float g_m[SPLIT * R_TOT];
__device__ float g_l[SPLIT * R_TOT];
// Precomputed W B-fragments (bf16 hi/lo): [which][k16][nc][lane] = {b0h,b1h,b0l,b1l}
__device__ unsigned g_Wf[3][NK16][8][32][4];

// ---------------------------------------------------------------------------
__device__ __forceinline__ unsigned f2tf(float f) {
    unsigned u;
    asm("cvt.rna.tf32.f32 %0, %1;" : "=r"(u) : "f"(f));
    return u;
}
__device__ __forceinline__ float tf32f(float f) { return __uint_as_float(f2tf(f)); }

__device__ __forceinline__ void mma_tf32(float c[4], const unsigned a[4],
                                         unsigned b0, unsigned b1) {
    asm volatile(
        "mma.sync.aligned.m16n8k8.row.col.f32.tf32.tf32.f32 "
        "{%0,%1,%2,%3}, {%4,%5,%6,%7}, {%8,%9}, {%0,%1,%2,%3};\n"
        : "+f"(c[0]), "+f"(c[1]), "+f"(c[2]), "+f"(c[3])
        : "r"(a[0]), "r"(a[1]), "r"(a[2]), "r"(a[3]), "r"(b0), "r"(b1));
}

__device__ __forceinline__ void mma_bf16(float c[4], const unsigned a[4],
                                         unsigned b0, unsigned b1) {
    asm volatile(
        "mma.sync.aligned.m16n8k16.row.col.f32.bf16.bf16.f32 "
        "{%0,%1,%2,%3}, {%4,%5,%6,%7}, {%8,%9}, {%0,%1,%2,%3};\n"
        : "+f"(c[0]), "+f"(c[1]), "+f"(c[2]), "+f"(c[3])
        : "r"(a[0]), "r"(a[1]), "r"(a[2]), "r"(a[3]), "r"(b0), "r"(b1));
}

// Split a float pair into packed bf16x2 hi + lo (low half = first element)
__device__ __forceinline__ void bfsplit(float fx, float fy,
                                        unsigned& hi, unsigned& lo) {
    __nv_bfloat162 hp = __floats2bfloat162_rn(fx, fy);
    float2 hf = __bfloat1622float2(hp);
    __nv_bfloat162 lp = __floats2bfloat162_rn(fx - hf.x, fy - hf.y);
    hi = *(unsigned*)&hp;
    lo = *(unsigned*)&lp;
}

__device__ __forceinline__ uint32_t smem_u32(const void* p) {
    uint32_t a;
    asm("{ .reg .u64 t; cvta.to.shared.u64 t, %1; cvt.u32.u64 %0, t; }"
        : "=r"(a) : "l"(p));
    return a;
}

__device__ __forceinline__ void cp16(uint32_t dst, const void* src) {
    asm volatile("cp.async.cg.shared.global [%0], [%1], 16;"
                 :: "r"(dst), "l"(src) : "memory");
}
#define CP_COMMIT()  asm volatile("cp.async.commit_group;" ::: "memory")
#define CP_WAIT(n)   asm volatile("cp.async.wait_group %0;" :: "n"(n) : "memory")

// ---------------------------------------------------------------------------
__global__ void theta_kernel() {
    int i = threadIdx.x;
    if (i < HALF) g_theta[i] = (float)pow(10000.0, -(double)i / (double)HALF);
}

// RoPE table: freq = fp32(s * theta_fp32); accurate sin/cos via double range
// reduction + fp32 Taylor on |r|<=pi/4.
__global__ void rope_table_kernel() {
    int idx = blockIdx.x * blockDim.x + threadIdx.x;
    if (idx >= S_LEN * HALF) return;
    int s = idx >> 5;
    int i = idx & (HALF - 1);
    float fr = (float)s * g_theta[i];

    double x  = (double)fr;
    double kd = rint(x * 0.6366197723675814);
    int    k  = (int)kd;
    double r  = fma(-kd, 1.5707963267948966, x);
    r         = fma(-kd, 6.123233995736766e-17, r);
    float rf = (float)r;
    float r2 = rf * rf;
    float sp = rf * (1.f + r2 * (-1.66666667e-1f + r2 * (8.33333310e-3f +
               r2 * (-1.98412698e-4f + r2 * 2.75573140e-6f))));
    float cp = 1.f + r2 * (-0.5f + r2 * (4.16666679e-2f +
               r2 * (-1.38888892e-3f + r2 * 2.47868524e-5f)));
    float sn, cs;
    switch (k & 3) {
        case 0:  sn = sp;  cs = cp;  break;
        case 1:  sn = cp;  cs = -sp; break;
        case 2:  sn = -sp; cs = -cp; break;
        default: sn = -cp; cs = sp;  break;
    }
    g_sin[idx] = sn;
    g_cos[idx] = cs;
}

// ---------------------------------------------------------------------------
// Precompute W B-fragments (bf16 hi/lo split) for m16n8k16 projection MMAs.
// ---------------------------------------------------------------------------
__global__ void wfrag_kernel(const float* __restrict__ Wq,
                             const float* __restrict__ Wk,
                             const float* __restrict__ Wv) {
    int tid = blockIdx.x * 256 + threadIdx.x;
    if (tid >= 3 * NK16 * 8 * 32) return;
    int lane  = tid & 31;
    int nc    = (tid >> 5) & 7;
    int ks    = (tid >> 8) & (NK16 - 1);
    int which = tid >> 14;
    const float* W = (which == 0) ? Wq : (which == 1) ? Wk : Wv;
    int g = lane >> 2, t = lane & 3;
    int n = nc * 8 + g;
    int k0 = ks * 16 + 2 * t;
    float w00 = W[(k0    ) * HEAD + n];
    float w01 = W[(k0 + 1) * HEAD + n];
    float w10 = W[(k0 + 8) * HEAD + n];
    float w11 = W[(k0 + 9) * HEAD + n];
    unsigned b0h, b0l, b1h, b1l;
    bfsplit(w00, w01, b0h, b0l);
    bfsplit(w10, w11, b1h, b1l);
    *(uint4*)&g_Wf[which][ks][nc][lane][0] = make_uint4(b0h, b1h, b0l, b1l);
}

// ---------------------------------------------------------------------------
// Tensor-core projection (bf16 hi/lo 3-split, m16n8k16) + fused RoPE,
// double-buffered cp.async staging of x chunk + W-fragment slice.
// Epilogue stores attention-ready values: Q = tf32(rope*0.125), K = tf32(rope),
// V = tf32(v).
// ---------------------------------------------------------------------------
#define XS_STRIDE 68
#define XS_BYTES  (128 * XS_STRIDE * 4)              // 34816
#define WF_BYTES  (4 * 8 * 32 * 16)                  // 16384
#define PROJ_BUF  (XS_BYTES + WF_BYTES)              // 51200
#define PROJ_SMEM (2 * PROJ_BUF)                     // 102400

__global__ void __launch_bounds__(128, 2) proj_mma_kernel(const float* __restrict__ x) {
    extern __shared__ char psm[];

    const int which = blockIdx.y;
    float* __restrict__ outp = (which == 0) ? g_Q : (which == 1) ? g_K : g_V;
    const char* __restrict__ wsrc = (const char*)&g_Wf[which][0][0][0][0];

    const int tid  = threadIdx.x;
    const int warp = tid >> 5;
    const int lane = tid & 31;
    const int g    = lane >> 2;
    const int t    = lane & 3;
    const int row0 = blockIdx.x * 128;
    const int r0   = warp * 32 + g;

    const uint32_t smb = smem_u32(psm);

    // --- stage chunk c into buffer b (16 x-lines + 8 W-lines per thread) ---
    auto stage = [&](int c, int b) {
        const uint32_t base = smb + b * PROJ_BUF;
        const float* xsrc = x + (size_t)row0 * D_MODEL + c * 64;
        #pragma unroll
        for (int j = 0; j < 16; j++) {
            int idx = j * 128 + tid;
            int r = idx >> 4, c4 = idx & 15;
            cp16(base + (r * XS_STRIDE + c4 * 4) * 4,
                 xsrc + (size_t)r * D_MODEL + c4 * 4);
        }
        const char* ws = wsrc + (size_t)c * WF_BYTES;
        #pragma unroll
        for (int j = 0; j < 8; j++) {
            int idx = j * 128 + tid;
            cp16(base + XS_BYTES + idx * 16, ws + idx * 16);
        }
        CP_COMMIT();
    };

    float c0[8][4] = {}, c1[8][4] = {};

    stage(0, 0);
    for (int c = 0; c < 16; c++) {
        const int bufsel = c & 1;
        if (c < 15) { stage(c + 1, bufsel ^ 1); CP_WAIT(1); }
        else        { CP_WAIT(0); }
        __syncthreads();

        char* bufp = psm + bufsel * PROJ_BUF;
        float* xs  = (float*)bufp;
        uint4* wfs = (uint4*)(bufp + XS_BYTES);

        #pragma unroll
        for (int ks = 0; ks < 4; ks++) {
            const int cb = ks * 16 + 2 * t;
            float2 f00 = *(float2*)&xs[ r0       * XS_STRIDE + cb];
            float2 f01 = *(float2*)&xs[(r0 +  8) * XS_STRIDE + cb];
            float2 f02 = *(float2*)&xs[ r0       * XS_STRIDE + cb + 8];
            float2 f03 = *(float2*)&xs[(r0 +  8) * XS_STRIDE + cb + 8];
            float2 f10 = *(float2*)&xs[(r0 + 16) * XS_STRIDE + cb];
            float2 f11 = *(float2*)&xs[(r0 + 24) * XS_STRIDE + cb];
            float2 f12 = *(float2*)&xs[(r0 + 16) * XS_STRIDE + cb + 8];
            float2 f13 = *(float2*)&xs[(r0 + 24) * XS_STRIDE + cb + 8];

            unsigned ah0[4], al0[4], ah1[4], al1[4];
            bfsplit(f00.x, f00.y, ah0[0], al0[0]);
            bfsplit(f01.x, f01.y, ah0[1], al0[1]);
            bfsplit(f02.x, f02.y, ah0[2], al0[2]);
            bfsplit(f03.x, f03.y, ah0[3], al0[3]);
            bfsplit(f10.x, f10.y, ah1[0], al1[0]);
            bfsplit(f11.x, f11.y, ah1[1], al1[1]);
            bfsplit(f12.x, f12.y, ah1[2], al1[2]);
            bfsplit(f13.x, f13.y, ah1[3], al1[3]);

            const uint4* wrow = wfs + ks * 256 + lane;
            #pragma unroll
            for (int nc = 0; nc < 8; nc++) {
                uint4 b = wrow[nc * 32];
                mma_bf16(c0[nc], ah0, b.x, b.y);   // hi*hi
                mma_bf16(c0[nc], ah0, b.z, b.w);   // hi*lo
                mma_bf16(c0[nc], al0, b.x, b.y);   // lo*hi
                mma_bf16(c1[nc], ah1, b.x, b.y);
                mma_bf16(c1[nc], ah1, b.z, b.w);
                mma_bf16(c1[nc], al1, b.x, b.y);
            }
        }
        __syncthreads();
    }

    // Epilogue: RoPE + attention-ready conversion
    #pragma unroll
    for (int tt = 0; tt < 2; tt++) {
        float (*cc)[4] = (tt == 0) ? c0 : c1;
        const int gr0 = row0 + r0 + tt * 16;
        const int s0  = gr0 & (S_LEN - 1);
        const int s1  = (gr0 + 8) & (S_LEN - 1);
        #pragma unroll
        for (int nc = 0; nc < 8; nc++) {
            int col = nc * 8 + 2 * t;
            float v0 = cc[nc][0], v1 = cc[nc][1], v2 = cc[nc][2], v3 = cc[nc][3];
            float2 o0, o1;
            if (which == 0) {            // Q: rope, prescale 0.125, tf32
                int i0 = col >> 1;
                float sn0 = g_sin[s0 * HALF + i0], cs0 = g_cos[s0 * HALF + i0];
                float sn1 = g_sin[s1 * HALF + i0], cs1 = g_cos[s1 * HALF + i0];
                o0 = make_float2(tf32f((v0 * cs0 - v1 * sn0) * 0.125f),
                                 tf32f((v1 * cs0 + v0 * sn0) * 0.125f));
                o1 = make_float2(tf32f((v2 * cs1 - v3 * sn1) * 0.125f),
                                 tf32f((v3 * cs1 + v2 * sn1) * 0.125f));
            } else if (which == 1) {     // K: rope, tf32
                int i0 = col >> 1;
                float sn0 = g_sin[s0 * HALF + i0], cs0 = g_cos[s0 * HALF + i0];
                float sn1 = g_sin[s1 * HALF + i0], cs1 = g_cos[s1 * HALF + i0];
                o0 = make_float2(tf32f(v0 * cs0 - v1 * sn0),
                                 tf32f(v1 * cs0 + v0 * sn0));
                o1 = make_float2(tf32f(v2 * cs1 - v3 * sn1),
                                 tf32f(v3 * cs1 + v2 * sn1));
            } else {                     // V: tf32
                o0 = make_float2(tf32f(v0), tf32f(v1));
                o1 = make_float2(tf32f(v2), tf32f(v3));
            }
            *(float2*)(outp + (size_t)gr0 * HEAD + col)       = o0;
            *(float2*)(outp + (size_t)(gr0 + 8) * HEAD + col) = o1;
        }
    }
}

// ---------------------------------------------------------------------------
// Tensor-core flash attention, 4-way split-KV (tf32 MMA).
// K/V tiles arrive pre-converted (tf32 bits): staging = cp.async pure copy,
// double-buffered across the jt loop.
// ---------------------------------------------------------------------------
#define KV_TILE  (64 * 68 * 4)           // 17408 bytes (padded rows)
#define KV_BUF   (2 * KV_TILE)           // K + V
#define ATTN_SMEM (2 * KV_BUF)           // 69632

__global__ void __launch_bounds__(128, 3) attn_mma_kernel() {
    extern __shared__ char asmem[];

    const int tid   = threadIdx.x;
    const int warp  = tid >> 5;
    const int lane  = tid & 31;
    const int g     = lane >> 2;
    const int t     = lane & 3;
    const int idx   = blockIdx.x;
    const int qt    = 63 - (idx >> 4);
    const int rem   = idx & 15;
    const int batch = rem >> 2;
    const int split = rem & 3;
    const int q0    = qt * 64;
    const int n     = qt + 1;
    const int lo    = (split * n) >> 2;
    const int hi    = ((split + 1) * n) >> 2;

    const int    rl0     = warp * 16 + g, rl1 = rl0 + 8;
    const size_t rowbase = (size_t)batch * S_LEN + q0;

    if (lo == hi) {
        if (t == 0) {
            int pb = split * R_TOT;
            g_m[pb + rowbase + rl0] = -1e30f;  g_l[pb + rowbase + rl0] = 0.f;
            g_m[pb + rowbase + rl1] = -1e30f;  g_l[pb + rowbase + rl1] = 0.f;
        }
        return;
    }

    const uint32_t smb = smem_u32(asmem);

    // Q tile (pre-scaled, pre-tf32): copy into buf0 K region, extract frags
    unsigned qa[8][4];
    {
        const float* Qg = g_Q + rowbase * HEAD;
        #pragma unroll
        for (int j = 0; j < 8; j++) {
            int i = j * 128 + tid;
            int r = i >> 4, c4 = i & 15;
            cp16(smb + (r * 68 + c4 * 4) * 4, Qg + (size_t)r * HEAD + c4 * 4);
        }
        CP_COMMIT(); CP_WAIT(0);
        __syncthreads();
        const unsigned* Kq = (const unsigned*)asmem;
        const int r0 = warp * 16 + g;
        #pragma unroll
        for (int kc = 0; kc < 8; kc++) {
            qa[kc][0] = Kq[r0 * 68 + kc * 8 + t];
            qa[kc][1] = Kq[(r0 + 8) * 68 + kc * 8 + t];
            qa[kc][2] = Kq[r0 * 68 + kc * 8 + t + 4];
            qa[kc][3] = Kq[(r0 + 8) * 68 + kc * 8 + t + 4];
        }
        __syncthreads();
    }

    float o[8][4];
    #pragma unroll
    for (int nc = 0; nc < 8; nc++) { o[nc][0] = o[nc][1] = o[nc][2] = o[nc][3] = 0.f; }
    float m0 = -1e30f, m1 = -1e30f, l0 = 0.f, l1 = 0.f;

    // --- stage K/V tile jt into buffer b ---
    auto stageKV = [&](int jt, int b) {
        const float* Kg = g_K + ((size_t)batch * S_LEN + jt * 64) * HEAD;
        const float* Vg = g_V + ((size_t)batch * S_LEN + jt * 64) * HEAD;
        const uint32_t kb = smb + b * KV_BUF;
        #pragma unroll
        for (int j = 0; j < 8; j++) {
            int i = j * 128 + tid;
            int r = i >> 4, c4 = i & 15;
            uint32_t off = (r * 68 + c4 * 4) * 4;
            cp16(kb + off,           Kg + (size_t)r * HEAD + c4 * 4);
            cp16(kb + KV_TILE + off, Vg + (size_t)r * HEAD + c4 * 4);
        }
        CP_COMMIT();
    };

    stageKV(lo, 0);
    for (int jt = lo; jt < hi; jt++) {
        const int buf = (jt - lo) & 1;
        if (jt + 1 < hi) { stageKV(jt + 1, buf ^ 1); CP_WAIT(1); }
        else             { CP_WAIT(0); }
        __syncthreads();

        const unsigned* Ksb = (const unsigned*)(asmem + buf * KV_BUF);
        const unsigned* Vsb = (const unsigned*)(asmem + buf * KV_BUF + KV_TILE);

        // S = Q K^T
        float s[8][4];
        #pragma unroll
        for (int nc = 0; nc < 8; nc++) {
            s[nc][0] = s[nc][1] = s[nc][2] = s[nc][3] = 0.f;
            #pragma unroll
            for (int kc = 0; kc < 8; kc++) {
                unsigned b0 = Ksb[(nc * 8 + g) * 68 + kc * 8 + t];
                unsigned b1 = Ksb[(nc * 8 + g) * 68 + kc * 8 + t + 4];
                mma_tf32(s[nc], qa[kc], b0, b1);
            }
        }

        // Causal mask (diagonal tile only)
        if (jt == qt) {
            #pragma unroll
            for (int nc = 0; nc < 8; nc++) {
                int cl = nc * 8 + 2 * t;
                if (cl     > rl0) s[nc][0] = -1e30f;
                if (cl + 1 > rl0) s[nc][1] = -1e30f;
                if (cl     > rl1) s[nc][2] = -1e30f;
                if (cl + 1 > rl1) s[nc][3] = -1e30f;
            }
        }

        // Row max across the quad
        float mt0 = -1e30f, mt1 = -1e30f;
        #pragma unroll
        for (int nc = 0; nc < 8; nc++) {
            mt0 = fmaxf(mt0, fmaxf(s[nc][0], s[nc][1]));
            mt1 = fmaxf(mt1, fmaxf(s[nc][2], s[nc][3]));
        }
        mt0 = fmaxf(mt0, __shfl_xor_sync(0xffffffffu, mt0, 1));
        mt0 = fmaxf(mt0, __shfl_xor_sync(0xffffffffu, mt0, 2));
        mt1 = fmaxf(mt1, __shfl_xor_sync(0xffffffffu, mt1, 1));
        mt1 = fmaxf(mt1, __shfl_xor_sync(0xffffffffu, mt1, 2));

        float mn0 = fmaxf(m0, mt0), mn1 = fmaxf(m1, mt1);
        float corr0 = exp2f((m0 - mn0) * LOG2E);
        float corr1 = exp2f((m1 - mn1) * LOG2E);

        float rs0 = 0.f, rs1 = 0.f;
        #pragma unroll
        for (int nc = 0; nc < 8; nc++) {
            s[nc][0] = exp2f((s[nc][0] - mn0) * LOG2E);
            s[nc][1] = exp2f((s[nc][1] - mn0) * LOG2E);
            s[nc][2] = exp2f((s[nc][2] - mn1) * LOG2E);
            s[nc][3] = exp2f((s[nc][3] - mn1) * LOG2E);
            rs0 += s[nc][0] + s[nc][1];
            rs1 += s[nc][2] + s[nc][3];
        }
        rs0 += __shfl_xor_sync(0xffffffffu, rs0, 1);
        rs0 += __shfl_xor_sync(0xffffffffu, rs0, 2);
        rs1 += __shfl_xor_sync(0xffffffffu, rs1, 1);
        rs1 += __shfl_xor_sync(0xffffffffu, rs1, 2);
        l0 = l0 * corr0 + rs0;
        l1 = l1 * corr1 + rs1;

        #pragma unroll
        for (int nc = 0; nc < 8; nc++) {
            o[nc][0] *= corr0; o[nc][1] *= corr0;
            o[nc][2] *= corr1; o[nc][3] *= corr1;
        }

        // Repack P (C-frag -> A-frag) interleaved with PV MMAs
        const int  src1 = (lane & ~3) | (t >> 1);
        const int  src2 = src1 + 2;
        const bool odd  = (t & 1);
        #pragma unroll
        for (int kc = 0; kc < 8; kc++) {
            float v00 = __shfl_sync(0xffffffffu, s[kc][0], src1);
            float v01 = __shfl_sync(0xffffffffu, s[kc][1], src1);
            float v10 = __shfl_sync(0xffffffffu, s[kc][2], src1);
            float v11 = __shfl_sync(0xffffffffu, s[kc][3], src1);
            float w00 = __shfl_sync(0xffffffffu, s[kc][0], src2);
            float w01 = __shfl_sync(0xffffffffu, s[kc][1], src2);
            float w10 = __shfl_sync(0xffffffffu, s[kc][2], src2);
            float w11 = __shfl_sync(0xffffffffu, s[kc][3], src2);
            unsigned pa[4];
            pa[0] = f2tf(odd ? v01 : v00);
            pa[1] = f2tf(odd ? v11 : v10);
            pa[2] = f2tf(odd ? w01 : w00);
            pa[3] = f2tf(odd ? w11 : w10);
            #pragma unroll
            for (int nc = 0; nc < 8; nc++) {
                unsigned b0 = Vsb[(kc * 8 + t) * 68 + nc * 8 + g];
                unsigned b1 = Vsb[(kc * 8 + t + 4) * 68 + nc * 8 + g];
                mma_tf32(o[nc], pa, b0, b1);
            }
        }

        m0 = mn0; m1 = mn1;
        __syncthreads();
    }

    // Store unnormalized partials + (m, l)
    float* O0 = g_Os + (size_t)split * R_TOT * HEAD + (rowbase + rl0) * HEAD;
    float* O1 = g_Os + (size_t)split * R_TOT * HEAD + (rowbase + rl1) * HEAD;
    #pragma unroll
    for (int nc = 0; nc < 8; nc++) {
        int col = nc * 8 + 2 * t;
        *(float2*)(O0 + col) = make_float2(o[nc][0], o[nc][1]);
        *(float2*)(O1 + col) = make_float2(o[nc][2], o[nc][3]);
    }
    if (t == 0) {
        int pb = split * R_TOT;
        g_m[pb + rowbase + rl0] = m0;  g_l[pb + rowbase + rl0] = l0;
        g_m[pb + rowbase + rl1] = m1;  g_l[pb + rowbase + rl1] = l1;
    }
}

// ---------------------------------------------------------------------------
// Split-KV combine: one thread per (row, 16-col quarter).
// ---------------------------------------------------------------------------
__global__ void __launch_bounds__(128) combine_kernel(float* __restrict__ out) {
    int gt  = blockIdx.x * 128 + threadIdx.x;
    int row = gt >> 2;
    int qp  = gt & 3;

    float m[SPLIT], l[SPLIT];
    float M = -1e30f;
    #pragma unroll
    for (int s = 0; s < SPLIT; s++) {
        m[s] = g_m[s * R_TOT + row];
        l[s] = g_l[s * R_TOT + row];
        M = fmaxf(M, m[s]);
    }
    float L = 0.f, w[SPLIT];
    #pragma unroll
    for (int s = 0; s < SPLIT; s++) {
        w[s] = exp2f((m[s] - M) * LOG2E);
        L += l[s] * w[s];
    }
    const float inv = 1.f / L;

    float4 acc[4];
    #pragma unroll
    for (int j = 0; j < 4; j++) acc[j] = make_float4(0.f, 0.f, 0.f, 0.f);
    #pragma unroll
    for (int s = 0; s < SPLIT; s++) {
        if (l[s] > 0.f) {
            const float4* p = (const float4*)(g_Os + (size_t)s * R_TOT * HEAD +
                                              (size_t)row * HEAD + qp * 16);
            #pragma unroll
            for (int j = 0; j < 4; j++) {
                float4 v = p[j];
                acc[j].x += w[s] * v.x; acc[j].y += w[s] * v.y;
                acc[j].z += w[s] * v.z; acc[j].w += w[s] * v.w;
            }
        }
    }
    float4* po = (float4*)(out + (size_t)row * HEAD + qp * 16);
    #pragma unroll
    for (int j = 0; j < 4; j++) {
        float4 r = acc[j];
        r.x *= inv; r.y *= inv; r.z *= inv; r.w *= inv;
        po[j] = r;
    }
}

// ---------------------------------------------------------------------------
extern "C" void kernel_launch(void* const* d_in, const int* in_sizes, int n_in,
                              void* d_out, int out_size) {
    const float* x  = (const float*)d_in[0];
    const float* Wq = (const float*)d_in[1];
    const float* Wk = (const float*)d_in[2];
    const float* Wv = (const float*)d_in[3];
    float* out = (float*)d_out;

    cudaFuncSetAttribute(proj_mma_kernel,
                         cudaFuncAttributeMaxDynamicSharedMemorySize, PROJ_SMEM);
    cudaFuncSetAttribute(attn_mma_kernel,
                         cudaFuncAttributeMaxDynamicSharedMemorySize, ATTN_SMEM);

    theta_kernel<<<1, 32>>>();
    rope_table_kernel<<<(S_LEN * HALF + 255) / 256, 256>>>();
    wfrag_kernel<<<(3 * NK16 * 8 * 32 + 255) / 256, 256>>>(Wq, Wk, Wv);
    proj_mma_kernel<<<dim3(R_TOT / 128, 3), 128, PROJ_SMEM>>>(x);
    attn_mma_kernel<<<64 * B_SZ * SPLIT, 128, ATTN_SMEM>>>();
    combine_kernel<<<(R_TOT * 4) / 128, 128>>>(out);
}

// round 9
// speedup vs baseline: 7.0839x; 1.0684x over previous
#include <cuda_runtime.h>
#include <cuda_bf16.h>
#include <math.h>
#include <stdint.h>

#define B_SZ    4
#define S_LEN   4096
#define D_MODEL 1024
#define HEAD    64
#define R_TOT   (B_SZ * S_LEN)
#define HALF    (HEAD / 2)
#define LOG2E   1.4426950408889634f
#define SPLIT   4
#define NK16    (D_MODEL / 16)   // 64 k16-slices

// Scratch (allocation-free rule: __device__ globals)
// g_Q holds tf32-rounded, 0.125-prescaled Q; g_K/g_V hold tf32-rounded values.
__device__ float g_Q[R_TOT * HEAD];
__device__ float g_K[R_TOT * HEAD];
__device__ float g_V[R_TOT * HEAD];
__device__ float g_sin[S_LEN * HALF];
__device__ float g_cos[S_LEN * HALF];
__device__ float g_theta[HALF];
__device__ float g_Os[(size_t)SPLIT * R_TOT * HEAD];
__device__ float g_m[SPLIT * R_TOT];
__device__ float g_l[SPLIT * R_TOT];
// Precomputed W B-fragments (bf16 hi/lo): [which][k16][nc][lane] = {b0h,b1h,b0l,b1l}
__device__ unsigned g_Wf[3][NK16][8][32][4];

// ---------------------------------------------------------------------------
__device__ __forceinline__ unsigned f2tf(float f) {
    unsigned u;
    asm("cvt.rna.tf32.f32 %0, %1;" : "=r"(u) : "f"(f));
    return u;
}
__device__ __forceinline__ float tf32f(float f) { return __uint_as_float(f2tf(f)); }

__device__ __forceinline__ void mma_tf32(float c[4], const unsigned a[4],
                                         unsigned b0, unsigned b1) {
    asm volatile(
        "mma.sync.aligned.m16n8k8.row.col.f32.tf32.tf32.f32 "
        "{%0,%1,%2,%3}, {%4,%5,%6,%7}, {%8,%9}, {%0,%1,%2,%3};\n"
        : "+f"(c[0]), "+f"(c[1]), "+f"(c[2]), "+f"(c[3])
        : "r"(a[0]), "r"(a[1]), "r"(a[2]), "r"(a[3]), "r"(b0), "r"(b1));
}

__device__ __forceinline__ void mma_bf16(float c[4], const unsigned a[4],
                                         unsigned b0, unsigned b1) {
    asm volatile(
        "mma.sync.aligned.m16n8k16.row.col.f32.bf16.bf16.f32 "
        "{%0,%1,%2,%3}, {%4,%5,%6,%7}, {%8,%9}, {%0,%1,%2,%3};\n"
        : "+f"(c[0]), "+f"(c[1]), "+f"(c[2]), "+f"(c[3])
        : "r"(a[0]), "r"(a[1]), "r"(a[2]), "r"(a[3]), "r"(b0), "r"(b1));
}

// Split a float pair into packed bf16x2 hi + lo (low half = first element)
__device__ __forceinline__ void bfsplit(float fx, float fy,
                                        unsigned& hi, unsigned& lo) {
    __nv_bfloat162 hp = __floats2bfloat162_rn(fx, fy);
    float2 hf = __bfloat1622float2(hp);
    __nv_bfloat162 lp = __floats2bfloat162_rn(fx - hf.x, fy - hf.y);
    hi = *(unsigned*)&hp;
    lo = *(unsigned*)&lp;
}

__device__ __forceinline__ uint32_t smem_u32(const void* p) {
    uint32_t a;
    asm("{ .reg .u64 t; cvta.to.shared.u64 t, %1; cvt.u32.u64 %0, t; }"
        : "=r"(a) : "l"(p));
    return a;
}

__device__ __forceinline__ void cp16(uint32_t dst, const void* src) {
    asm volatile("cp.async.cg.shared.global [%0], [%1], 16;"
                 :: "r"(dst), "l"(src) : "memory");
}
#define CP_COMMIT()  asm volatile("cp.async.commit_group;" ::: "memory")
#define CP_WAIT(n)   asm volatile("cp.async.wait_group %0;" :: "n"(n) : "memory")

// ---------------------------------------------------------------------------
__global__ void theta_kernel() {
    int i = threadIdx.x;
    if (i < HALF) g_theta[i] = (float)pow(10000.0, -(double)i / (double)HALF);
}

// RoPE table: freq = fp32(s * theta_fp32); accurate sin/cos via double range
// reduction + fp32 Taylor on |r|<=pi/4.
__global__ void rope_table_kernel() {
    int idx = blockIdx.x * blockDim.x + threadIdx.x;
    if (idx >= S_LEN * HALF) return;
    int s = idx >> 5;
    int i = idx & (HALF - 1);
    float fr = (float)s * g_theta[i];

    double x  = (double)fr;
    double kd = rint(x * 0.6366197723675814);
    int    k  = (int)kd;
    double r  = fma(-kd, 1.5707963267948966, x);
    r         = fma(-kd, 6.123233995736766e-17, r);
    float rf = (float)r;
    float r2 = rf * rf;
    float sp = rf * (1.f + r2 * (-1.66666667e-1f + r2 * (8.33333310e-3f +
               r2 * (-1.98412698e-4f + r2 * 2.75573140e-6f))));
    float cp = 1.f + r2 * (-0.5f + r2 * (4.16666679e-2f +
               r2 * (-1.38888892e-3f + r2 * 2.47868524e-5f)));
    float sn, cs;
    switch (k & 3) {
        case 0:  sn = sp;  cs = cp;  break;
        case 1:  sn = cp;  cs = -sp; break;
        case 2:  sn = -sp; cs = -cp; break;
        default: sn = -cp; cs = sp;  break;
    }
    g_sin[idx] = sn;
    g_cos[idx] = cs;
}

// ---------------------------------------------------------------------------
// Precompute W B-fragments (bf16 hi/lo split) for m16n8k16 projection MMAs.
// ---------------------------------------------------------------------------
__global__ void wfrag_kernel(const float* __restrict__ Wq,
                             const float* __restrict__ Wk,
                             const float* __restrict__ Wv) {
    int tid = blockIdx.x * 256 + threadIdx.x;
    if (tid >= 3 * NK16 * 8 * 32) return;
    int lane  = tid & 31;
    int nc    = (tid >> 5) & 7;
    int ks    = (tid >> 8) & (NK16 - 1);
    int which = tid >> 14;
    const float* W = (which == 0) ? Wq : (which == 1) ? Wk : Wv;
    int g = lane >> 2, t = lane & 3;
    int n = nc * 8 + g;
    int k0 = ks * 16 + 2 * t;
    float w00 = W[(k0    ) * HEAD + n];
    float w01 = W[(k0 + 1) * HEAD + n];
    float w10 = W[(k0 + 8) * HEAD + n];
    float w11 = W[(k0 + 9) * HEAD + n];
    unsigned b0h, b0l, b1h, b1l;
    bfsplit(w00, w01, b0h, b0l);
    bfsplit(w10, w11, b1h, b1l);
    *(uint4*)&g_Wf[which][ks][nc][lane][0] = make_uint4(b0h, b1h, b0l, b1l);
}

// ---------------------------------------------------------------------------
// FUSED QKV tensor-core projection (bf16 hi/lo 3-split, m16n8k16) + RoPE.
// One CTA = 128 rows x 64 cols, ALL THREE outputs accumulated together:
// each staged x chunk + bfsplit chain feeds 9 MMAs (3 outputs x 3 products).
// 256 threads = 8 warps, warp owns 16 rows. Double-buffered cp.async staging
// of x chunk (fp32) + all three W-fragment slices.
// Epilogue stores attention-ready values: Q = tf32(rope*0.125), K = tf32(rope),
// V = tf32(v).
// ---------------------------------------------------------------------------
#define XS_STRIDE 68
#define XS_BYTES   (128 * XS_STRIDE * 4)             // 34816
#define WF_BYTES   (4 * 8 * 32 * 16)                 // 16384 per which per chunk
#define WQ_STRIDE  (NK16 * 8 * 32 * 16)              // 262144 bytes per which
#define FBUF       (XS_BYTES + 3 * WF_BYTES)         // 83968
#define FSMEM      (2 * FBUF)                        // 167936

__global__ void __launch_bounds__(256, 1) proj_fused_kernel(const float* __restrict__ x) {
    extern __shared__ char psm[];

    const int tid  = threadIdx.x;
    const int warp = tid >> 5;
    const int lane = tid & 31;
    const int g    = lane >> 2;
    const int t    = lane & 3;
    const int row0 = blockIdx.x * 128;
    const int r0   = warp * 16 + g;

    const uint32_t smb = smem_u32(psm);

    // --- stage chunk c into buffer b: x (8 lines) + 3 W slices (12 lines) ---
    auto stage = [&](int c, int b) {
        const uint32_t base = smb + b * FBUF;
        const float* xsrc = x + (size_t)row0 * D_MODEL + c * 64;
        #pragma unroll
        for (int j = 0; j < 8; j++) {
            int idx = j * 256 + tid;
            int r = idx >> 4, c4 = idx & 15;
            cp16(base + (r * XS_STRIDE + c4 * 4) * 4,
                 xsrc + (size_t)r * D_MODEL + c4 * 4);
        }
        const char* ws = (const char*)&g_Wf[0][0][0][0][0] + (size_t)c * WF_BYTES;
        #pragma unroll
        for (int wq = 0; wq < 3; wq++) {
            #pragma unroll
            for (int j = 0; j < 4; j++) {
                int idx = j * 256 + tid;
                cp16(base + XS_BYTES + wq * WF_BYTES + idx * 16,
                     ws + (size_t)wq * WQ_STRIDE + idx * 16);
            }
        }
        CP_COMMIT();
    };

    float cacc[3][8][4] = {};

    stage(0, 0);
    for (int c = 0; c < 16; c++) {
        const int bufsel = c & 1;
        if (c < 15) { stage(c + 1, bufsel ^ 1); CP_WAIT(1); }
        else        { CP_WAIT(0); }
        __syncthreads();

        char* bufp = psm + bufsel * FBUF;
        float* xs  = (float*)bufp;

        #pragma unroll
        for (int ks = 0; ks < 4; ks++) {
            const int cb = ks * 16 + 2 * t;
            float2 f0 = *(float2*)&xs[ r0      * XS_STRIDE + cb];
            float2 f1 = *(float2*)&xs[(r0 + 8) * XS_STRIDE + cb];
            float2 f2 = *(float2*)&xs[ r0      * XS_STRIDE + cb + 8];
            float2 f3 = *(float2*)&xs[(r0 + 8) * XS_STRIDE + cb + 8];

            unsigned ah[4], al[4];
            bfsplit(f0.x, f0.y, ah[0], al[0]);
            bfsplit(f1.x, f1.y, ah[1], al[1]);
            bfsplit(f2.x, f2.y, ah[2], al[2]);
            bfsplit(f3.x, f3.y, ah[3], al[3]);

            #pragma unroll
            for (int wq = 0; wq < 3; wq++) {
                const uint4* wrow =
                    (const uint4*)(bufp + XS_BYTES + wq * WF_BYTES) + ks * 256 + lane;
                #pragma unroll
                for (int nc = 0; nc < 8; nc++) {
                    uint4 b = wrow[nc * 32];
                    mma_bf16(cacc[wq][nc], ah, b.x, b.y);   // hi*hi
                    mma_bf16(cacc[wq][nc], ah, b.z, b.w);   // hi*lo
                    mma_bf16(cacc[wq][nc], al, b.x, b.y);   // lo*hi
                }
            }
        }
        __syncthreads();
    }

    // Epilogue: RoPE + attention-ready conversion
    const int gr0 = row0 + r0;
    const int s0  = gr0 & (S_LEN - 1);
    const int s1  = (gr0 + 8) & (S_LEN - 1);
    #pragma unroll
    for (int wq = 0; wq < 3; wq++) {
        float (*cc)[4] = cacc[wq];
        float* outp = (wq == 0) ? g_Q : (wq == 1) ? g_K : g_V;
        #pragma unroll
        for (int nc = 0; nc < 8; nc++) {
            int col = nc * 8 + 2 * t;
            float v0 = cc[nc][0], v1 = cc[nc][1], v2 = cc[nc][2], v3 = cc[nc][3];
            float2 o0, o1;
            if (wq == 0) {               // Q: rope, prescale 0.125, tf32
                int i0 = col >> 1;
                float sn0 = g_sin[s0 * HALF + i0], cs0 = g_cos[s0 * HALF + i0];
                float sn1 = g_sin[s1 * HALF + i0], cs1 = g_cos[s1 * HALF + i0];
                o0 = make_float2(tf32f((v0 * cs0 - v1 * sn0) * 0.125f),
                                 tf32f((v1 * cs0 + v0 * sn0) * 0.125f));
                o1 = make_float2(tf32f((v2 * cs1 - v3 * sn1) * 0.125f),
                                 tf32f((v3 * cs1 + v2 * sn1) * 0.125f));
            } else if (wq == 1) {        // K: rope, tf32
                int i0 = col >> 1;
                float sn0 = g_sin[s0 * HALF + i0], cs0 = g_cos[s0 * HALF + i0];
                float sn1 = g_sin[s1 * HALF + i0], cs1 = g_cos[s1 * HALF + i0];
                o0 = make_float2(tf32f(v0 * cs0 - v1 * sn0),
                                 tf32f(v1 * cs0 + v0 * sn0));
                o1 = make_float2(tf32f(v2 * cs1 - v3 * sn1),
                                 tf32f(v3 * cs1 + v2 * sn1));
            } else {                     // V: tf32
                o0 = make_float2(tf32f(v0), tf32f(v1));
                o1 = make_float2(tf32f(v2), tf32f(v3));
            }
            *(float2*)(outp + (size_t)gr0 * HEAD + col)       = o0;
            *(float2*)(outp + (size_t)(gr0 + 8) * HEAD + col) = o1;
        }
    }
}

// ---------------------------------------------------------------------------
// Tensor-core flash attention, 4-way split-KV (tf32 MMA).
// K/V tiles arrive pre-converted (tf32 bits): staging = cp.async pure copy,
// double-buffered across the jt loop.
// ---------------------------------------------------------------------------
#define KV_TILE  (64 * 68 * 4)           // 17408 bytes (padded rows)
#define KV_BUF   (2 * KV_TILE)           // K + V
#define ATTN_SMEM (2 * KV_BUF)           // 69632

__global__ void __launch_bounds__(128, 3) attn_mma_kernel() {
    extern __shared__ char asmem[];

    const int tid   = threadIdx.x;
    const int warp  = tid >> 5;
    const int lane  = tid & 31;
    const int g     = lane >> 2;
    const int t     = lane & 3;
    const int idx   = blockIdx.x;
    const int qt    = 63 - (idx >> 4);
    const int rem   = idx & 15;
    const int batch = rem >> 2;
    const int split = rem & 3;
    const int q0    = qt * 64;
    const int n     = qt + 1;
    const int lo    = (split * n) >> 2;
    const int hi    = ((split + 1) * n) >> 2;

    const int    rl0     = warp * 16 + g, rl1 = rl0 + 8;
    const size_t rowbase = (size_t)batch * S_LEN + q0;

    if (lo == hi) {
        if (t == 0) {
            int pb = split * R_TOT;
            g_m[pb + rowbase + rl0] = -1e30f;  g_l[pb + rowbase + rl0] = 0.f;
            g_m[pb + rowbase + rl1] = -1e30f;  g_l[pb + rowbase + rl1] = 0.f;
        }
        return;
    }

    const uint32_t smb = smem_u32(asmem);

    // Q tile (pre-scaled, pre-tf32): copy into buf0 K region, extract frags
    unsigned qa[8][4];
    {
        const float* Qg = g_Q + rowbase * HEAD;
        #pragma unroll
        for (int j = 0; j < 8; j++) {
            int i = j * 128 + tid;
            int r = i >> 4, c4 = i & 15;
            cp16(smb + (r * 68 + c4 * 4) * 4, Qg + (size_t)r * HEAD + c4 * 4);
        }
        CP_COMMIT(); CP_WAIT(0);
        __syncthreads();
        const unsigned* Kq = (const unsigned*)asmem;
        const int r0 = warp * 16 + g;
        #pragma unroll
        for (int kc = 0; kc < 8; kc++) {
            qa[kc][0] = Kq[r0 * 68 + kc * 8 + t];
            qa[kc][1] = Kq[(r0 + 8) * 68 + kc * 8 + t];
            qa[kc][2] = Kq[r0 * 68 + kc * 8 + t + 4];
            qa[kc][3] = Kq[(r0 + 8) * 68 + kc * 8 + t + 4];
        }
        __syncthreads();
    }

    float o[8][4];
    #pragma unroll
    for (int nc = 0; nc < 8; nc++) { o[nc][0] = o[nc][1] = o[nc][2] = o[nc][3] = 0.f; }
    float m0 = -1e30f, m1 = -1e30f, l0 = 0.f, l1 = 0.f;

    // --- stage K/V tile jt into buffer b ---
    auto stageKV = [&](int jt, int b) {
        const float* Kg = g_K + ((size_t)batch * S_LEN + jt * 64) * HEAD;
        const float* Vg = g_V + ((size_t)batch * S_LEN + jt * 64) * HEAD;
        const uint32_t kb = smb + b * KV_BUF;
        #pragma unroll
        for (int j = 0; j < 8; j++) {
            int i = j * 128 + tid;
            int r = i >> 4, c4 = i & 15;
            uint32_t off = (r * 68 + c4 * 4) * 4;
            cp16(kb + off,           Kg + (size_t)r * HEAD + c4 * 4);
            cp16(kb + KV_TILE + off, Vg + (size_t)r * HEAD + c4 * 4);
        }
        CP_COMMIT();
    };

    stageKV(lo, 0);
    for (int jt = lo; jt < hi; jt++) {
        const int buf = (jt - lo) & 1;
        if (jt + 1 < hi) { stageKV(jt + 1, buf ^ 1); CP_WAIT(1); }
        else             { CP_WAIT(0); }
        __syncthreads();

        const unsigned* Ksb = (const unsigned*)(asmem + buf * KV_BUF);
        const unsigned* Vsb = (const unsigned*)(asmem + buf * KV_BUF + KV_TILE);

        // S = Q K^T
        float s[8][4];
        #pragma unroll
        for (int nc = 0; nc < 8; nc++) {
            s[nc][0] = s[nc][1] = s[nc][2] = s[nc][3] = 0.f;
            #pragma unroll
            for (int kc = 0; kc < 8; kc++) {
                unsigned b0 = Ksb[(nc * 8 + g) * 68 + kc * 8 + t];
                unsigned b1 = Ksb[(nc * 8 + g) * 68 + kc * 8 + t + 4];
                mma_tf32(s[nc], qa[kc], b0, b1);
            }
        }

        // Causal mask (diagonal tile only)
        if (jt == qt) {
            #pragma unroll
            for (int nc = 0; nc < 8; nc++) {
                int cl = nc * 8 + 2 * t;
                if (cl     > rl0) s[nc][0] = -1e30f;
                if (cl + 1 > rl0) s[nc][1] = -1e30f;
                if (cl     > rl1) s[nc][2] = -1e30f;
                if (cl + 1 > rl1) s[nc][3] = -1e30f;
            }
        }

        // Row max across the quad
        float mt0 = -1e30f, mt1 = -1e30f;
        #pragma unroll
        for (int nc = 0; nc < 8; nc++) {
            mt0 = fmaxf(mt0, fmaxf(s[nc][0], s[nc][1]));
            mt1 = fmaxf(mt1, fmaxf(s[nc][2], s[nc][3]));
        }
        mt0 = fmaxf(mt0, __shfl_xor_sync(0xffffffffu, mt0, 1));
        mt0 = fmaxf(mt0, __shfl_xor_sync(0xffffffffu, mt0, 2));
        mt1 = fmaxf(mt1, __shfl_xor_sync(0xffffffffu, mt1, 1));
        mt1 = fmaxf(mt1, __shfl_xor_sync(0xffffffffu, mt1, 2));

        float mn0 = fmaxf(m0, mt0), mn1 = fmaxf(m1, mt1);
        float corr0 = exp2f((m0 - mn0) * LOG2E);
        float corr1 = exp2f((m1 - mn1) * LOG2E);

        float rs0 = 0.f, rs1 = 0.f;
        #pragma unroll
        for (int nc = 0; nc < 8; nc++) {
            s[nc][0] = exp2f((s[nc][0] - mn0) * LOG2E);
            s[nc][1] = exp2f((s[nc][1] - mn0) * LOG2E);
            s[nc][2] = exp2f((s[nc][2] - mn1) * LOG2E);
            s[nc][3] = exp2f((s[nc][3] - mn1) * LOG2E);
            rs0 += s[nc][0] + s[nc][1];
            rs1 += s[nc][2] + s[nc][3];
        }
        rs0 += __shfl_xor_sync(0xffffffffu, rs0, 1);
        rs0 += __shfl_xor_sync(0xffffffffu, rs0, 2);
        rs1 += __shfl_xor_sync(0xffffffffu, rs1, 1);
        rs1 += __shfl_xor_sync(0xffffffffu, rs1, 2);
        l0 = l0 * corr0 + rs0;
        l1 = l1 * corr1 + rs1;

        #pragma unroll
        for (int nc = 0; nc < 8; nc++) {
            o[nc][0] *= corr0; o[nc][1] *= corr0;
            o[nc][2] *= corr1; o[nc][3] *= corr1;
        }

        // Repack P (C-frag -> A-frag) interleaved with PV MMAs
        const int  src1 = (lane & ~3) | (t >> 1);
        const int  src2 = src1 + 2;
        const bool odd  = (t & 1);
        #pragma unroll
        for (int kc = 0; kc < 8; kc++) {
            float v00 = __shfl_sync(0xffffffffu, s[kc][0], src1);
            float v01 = __shfl_sync(0xffffffffu, s[kc][1], src1);
            float v10 = __shfl_sync(0xffffffffu, s[kc][2], src1);
            float v11 = __shfl_sync(0xffffffffu, s[kc][3], src1);
            float w00 = __shfl_sync(0xffffffffu, s[kc][0], src2);
            float w01 = __shfl_sync(0xffffffffu, s[kc][1], src2);
            float w10 = __shfl_sync(0xffffffffu, s[kc][2], src2);
            float w11 = __shfl_sync(0xffffffffu, s[kc][3], src2);
            unsigned pa[4];
            pa[0] = f2tf(odd ? v01 : v00);
            pa[1] = f2tf(odd ? v11 : v10);
            pa[2] = f2tf(odd ? w01 : w00);
            pa[3] = f2tf(odd ? w11 : w10);
            #pragma unroll
            for (int nc = 0; nc < 8; nc++) {
                unsigned b0 = Vsb[(kc * 8 + t) * 68 + nc * 8 + g];
                unsigned b1 = Vsb[(kc * 8 + t + 4) * 68 + nc * 8 + g];
                mma_tf32(o[nc], pa, b0, b1);
            }
        }

        m0 = mn0; m1 = mn1;
        __syncthreads();
    }

    // Store unnormalized partials + (m, l)
    float* O0 = g_Os + (size_t)split * R_TOT * HEAD + (rowbase + rl0) * HEAD;
    float* O1 = g_Os + (size_t)split * R_TOT * HEAD + (rowbase + rl1) * HEAD;
    #pragma unroll
    for (int nc = 0; nc < 8; nc++) {
        int col = nc * 8 + 2 * t;
        *(float2*)(O0 + col) = make_float2(o[nc][0], o[nc][1]);
        *(float2*)(O1 + col) = make_float2(o[nc][2], o[nc][3]);
    }
    if (t == 0) {
        int pb = split * R_TOT;
        g_m[pb + rowbase + rl0] = m0;  g_l[pb + rowbase + rl0] = l0;
        g_m[pb + rowbase + rl1] = m1;  g_l[pb + rowbase + rl1] = l1;
    }
}

// ---------------------------------------------------------------------------
// Split-KV combine: one thread per (row, 16-col quarter).
// ---------------------------------------------------------------------------
__global__ void __launch_bounds__(128) combine_kernel(float* __restrict__ out) {
    int gt  = blockIdx.x * 128 + threadIdx.x;
    int row = gt >> 2;
    int qp  = gt & 3;

    float m[SPLIT], l[SPLIT];
    float M = -1e30f;
    #pragma unroll
    for (int s = 0; s < SPLIT; s++) {
        m[s] = g_m[s * R_TOT + row];
        l[s] = g_l[s * R_TOT + row];
        M = fmaxf(M, m[s]);
    }
    float L = 0.f, w[SPLIT];
    #pragma unroll
    for (int s = 0; s < SPLIT; s++) {
        w[s] = exp2f((m[s] - M) * LOG2E);
        L += l[s] * w[s];
    }
    const float inv = 1.f / L;

    float4 acc[4];
    #pragma unroll
    for (int j = 0; j < 4; j++) acc[j] = make_float4(0.f, 0.f, 0.f, 0.f);
    #pragma unroll
    for (int s = 0; s < SPLIT; s++) {
        if (l[s] > 0.f) {
            const float4* p = (const float4*)(g_Os + (size_t)s * R_TOT * HEAD +
                                              (size_t)row * HEAD + qp * 16);
            #pragma unroll
            for (int j = 0; j < 4; j++) {
                float4 v = p[j];
                acc[j].x += w[s] * v.x; acc[j].y += w[s] * v.y;
                acc[j].z += w[s] * v.z; acc[j].w += w[s] * v.w;
            }
        }
    }
    float4* po = (float4*)(out + (size_t)row * HEAD + qp * 16);
    #pragma unroll
    for (int j = 0; j < 4; j++) {
        float4 r = acc[j];
        r.x *= inv; r.y *= inv; r.z *= inv; r.w *= inv;
        po[j] = r;
    }
}

// ---------------------------------------------------------------------------
extern "C" void kernel_launch(void* const* d_in, const int* in_sizes, int n_in,
                              void* d_out, int out_size) {
    const float* x  = (const float*)d_in[0];
    const float* Wq = (const float*)d_in[1];
    const float* Wk = (const float*)d_in[2];
    const float* Wv = (const float*)d_in[3];
    float* out = (float*)d_out;

    cudaFuncSetAttribute(proj_fused_kernel,
                         cudaFuncAttributeMaxDynamicSharedMemorySize, FSMEM);
    cudaFuncSetAttribute(attn_mma_kernel,
                         cudaFuncAttributeMaxDynamicSharedMemorySize, ATTN_SMEM);

    theta_kernel<<<1, 32>>>();
    rope_table_kernel<<<(S_LEN * HALF + 255) / 256, 256>>>();
    wfrag_kernel<<<(3 * NK16 * 8 * 32 + 255) / 256, 256>>>(Wq, Wk, Wv);
    proj_fused_kernel<<<R_TOT / 128, 256, FSMEM>>>(x);
    attn_mma_kernel<<<64 * B_SZ * SPLIT, 128, ATTN_SMEM>>>();
    combine_kernel<<<(R_TOT * 4) / 128, 128>>>(out);
}

// round 10
// speedup vs baseline: 7.7149x; 1.0891x over previous
#include <cuda_runtime.h>
#include <cuda_bf16.h>
#include <math.h>
#include <stdint.h>

#define B_SZ    4
#define S_LEN   4096
#define D_MODEL 1024
#define HEAD    64
#define R_TOT   (B_SZ * S_LEN)
#define HALF    (HEAD / 2)
#define LOG2E   1.4426950408889634f
#define SPLIT   4
#define NK8     (D_MODEL / 8)    // 128 k8-slices

// Scratch (allocation-free rule: __device__ globals)
// g_Q holds tf32-rounded, 0.125-prescaled Q; g_K/g_V hold tf32-rounded values.
__device__ float g_Q[R_TOT * HEAD];
__device__ float g_K[R_TOT * HEAD];
__device__ float g_V[R_TOT * HEAD];
__device__ float g_sin[S_LEN * HALF];
__device__ float g_cos[S_LEN * HALF];
__device__ float g_theta[HALF];
__device__ float g_Os[(size_t)SPLIT * R_TOT * HEAD];
__device__ float g_m[SPLIT * R_TOT];
__device__ float g_l[SPLIT * R_TOT];
// Precomputed W B-fragments (tf32): [which][k8][nc][lane] = {b0, b1}
__device__ uint2 g_Wf[3][NK8][8][32];

// ---------------------------------------------------------------------------
__device__ __forceinline__ unsigned f2tf(float f) {
    unsigned u;
    asm("cvt.rna.tf32.f32 %0, %1;" : "=r"(u) : "f"(f));
    return u;
}
__device__ __forceinline__ float tf32f(float f) { return __uint_as_float(f2tf(f)); }

__device__ __forceinline__ void mma_tf32(float c[4], const unsigned a[4],
                                         unsigned b0, unsigned b1) {
    asm volatile(
        "mma.sync.aligned.m16n8k8.row.col.f32.tf32.tf32.f32 "
        "{%0,%1,%2,%3}, {%4,%5,%6,%7}, {%8,%9}, {%0,%1,%2,%3};\n"
        : "+f"(c[0]), "+f"(c[1]), "+f"(c[2]), "+f"(c[3])
        : "r"(a[0]), "r"(a[1]), "r"(a[2]), "r"(a[3]), "r"(b0), "r"(b1));
}

__device__ __forceinline__ uint32_t smem_u32(const void* p) {
    uint32_t a;
    asm("{ .reg .u64 t; cvta.to.shared.u64 t, %1; cvt.u32.u64 %0, t; }"
        : "=r"(a) : "l"(p));
    return a;
}

__device__ __forceinline__ void cp16(uint32_t dst, const void* src) {
    asm volatile("cp.async.cg.shared.global [%0], [%1], 16;"
                 :: "r"(dst), "l"(src) : "memory");
}
#define CP_COMMIT()  asm volatile("cp.async.commit_group;" ::: "memory")
#define CP_WAIT(n)   asm volatile("cp.async.wait_group %0;" :: "n"(n) : "memory")

// ---------------------------------------------------------------------------
__global__ void theta_kernel() {
    int i = threadIdx.x;
    if (i < HALF) g_theta[i] = (float)pow(10000.0, -(double)i / (double)HALF);
}

// RoPE table: freq = fp32(s * theta_fp32); accurate sin/cos via double range
// reduction + fp32 Taylor on |r|<=pi/4.
__global__ void rope_table_kernel() {
    int idx = blockIdx.x * blockDim.x + threadIdx.x;
    if (idx >= S_LEN * HALF) return;
    int s = idx >> 5;
    int i = idx & (HALF - 1);
    float fr = (float)s * g_theta[i];

    double x  = (double)fr;
    double kd = rint(x * 0.6366197723675814);
    int    k  = (int)kd;
    double r  = fma(-kd, 1.5707963267948966, x);
    r         = fma(-kd, 6.123233995736766e-17, r);
    float rf = (float)r;
    float r2 = rf * rf;
    float sp = rf * (1.f + r2 * (-1.66666667e-1f + r2 * (8.33333310e-3f +
               r2 * (-1.98412698e-4f + r2 * 2.75573140e-6f))));
    float cp = 1.f + r2 * (-0.5f + r2 * (4.16666679e-2f +
               r2 * (-1.38888892e-3f + r2 * 2.47868524e-5f)));
    float sn, cs;
    switch (k & 3) {
        case 0:  sn = sp;  cs = cp;  break;
        case 1:  sn = cp;  cs = -sp; break;
        case 2:  sn = -sp; cs = -cp; break;
        default: sn = -cp; cs = sp;  break;
    }
    g_sin[idx] = sn;
    g_cos[idx] = cs;
}

// ---------------------------------------------------------------------------
// Precompute W B-fragments (tf32) for m16n8k8 projection MMAs.
// b0 = W[ks*8+t][n], b1 = W[ks*8+t+4][n], n = nc*8+g.
// ---------------------------------------------------------------------------
__global__ void wfrag_kernel(const float* __restrict__ Wq,
                             const float* __restrict__ Wk,
                             const float* __restrict__ Wv) {
    int tid = blockIdx.x * 256 + threadIdx.x;
    if (tid >= 3 * NK8 * 8 * 32) return;
    int lane  = tid & 31;
    int nc    = (tid >> 5) & 7;
    int ks    = (tid >> 8) & (NK8 - 1);
    int which = tid >> 15;
    const float* W = (which == 0) ? Wq : (which == 1) ? Wk : Wv;
    int g = lane >> 2, t = lane & 3;
    int n = nc * 8 + g;
    int k0 = ks * 8;
    uint2 v;
    v.x = f2tf(W[(size_t)(k0 + t)     * HEAD + n]);
    v.y = f2tf(W[(size_t)(k0 + t + 4) * HEAD + n]);
    g_Wf[which][ks][nc][lane] = v;
}

// ---------------------------------------------------------------------------
// FUSED QKV tensor-core projection (single-pass tf32, m16n8k8) + RoPE.
// One CTA = 128 rows x 64 cols, all three outputs accumulated together:
// each staged x chunk feeds 3 outputs per A-fragment. 256 threads = 8 warps,
// warp owns 16 rows. Double-buffered cp.async staging of x chunk (fp32) +
// all three W-fragment slices.
// Epilogue stores attention-ready values: Q = tf32(rope*0.125), K = tf32(rope),
// V = tf32(v).
// ---------------------------------------------------------------------------
#define XS_STRIDE 68
#define XS_BYTES   (128 * XS_STRIDE * 4)             // 34816
#define WF_BYTES   (8 * 8 * 32 * 8)                  // 16384 per which per chunk
#define WQ_STRIDE  (NK8 * 8 * 32 * 8)                // 262144 bytes per which
#define FBUF       (XS_BYTES + 3 * WF_BYTES)         // 83968
#define FSMEM      (2 * FBUF)                        // 167936

__global__ void __launch_bounds__(256, 1) proj_fused_kernel(const float* __restrict__ x) {
    extern __shared__ char psm[];

    const int tid  = threadIdx.x;
    const int warp = tid >> 5;
    const int lane = tid & 31;
    const int g    = lane >> 2;
    const int t    = lane & 3;
    const int row0 = blockIdx.x * 128;
    const int r0   = warp * 16 + g;

    const uint32_t smb = smem_u32(psm);

    // --- stage chunk c into buffer b: x (8 lines) + 3 W slices (12 lines) ---
    auto stage = [&](int c, int b) {
        const uint32_t base = smb + b * FBUF;
        const float* xsrc = x + (size_t)row0 * D_MODEL + c * 64;
        #pragma unroll
        for (int j = 0; j < 8; j++) {
            int idx = j * 256 + tid;
            int r = idx >> 4, c4 = idx & 15;
            cp16(base + (r * XS_STRIDE + c4 * 4) * 4,
                 xsrc + (size_t)r * D_MODEL + c4 * 4);
        }
        const char* ws = (const char*)&g_Wf[0][0][0][0] + (size_t)c * WF_BYTES;
        #pragma unroll
        for (int wq = 0; wq < 3; wq++) {
            #pragma unroll
            for (int j = 0; j < 4; j++) {
                int idx = j * 256 + tid;
                cp16(base + XS_BYTES + wq * WF_BYTES + idx * 16,
                     ws + (size_t)wq * WQ_STRIDE + idx * 16);
            }
        }
        CP_COMMIT();
    };

    float cacc[3][8][4] = {};

    stage(0, 0);
    for (int c = 0; c < 16; c++) {
        const int bufsel = c & 1;
        if (c < 15) { stage(c + 1, bufsel ^ 1); CP_WAIT(1); }
        else        { CP_WAIT(0); }
        __syncthreads();

        char* bufp = psm + bufsel * FBUF;
        float* xs  = (float*)bufp;

        #pragma unroll
        for (int ks = 0; ks < 8; ks++) {
            const int cb = ks * 8 + t;
            unsigned a[4];
            a[0] = f2tf(xs[ r0      * XS_STRIDE + cb]);
            a[1] = f2tf(xs[(r0 + 8) * XS_STRIDE + cb]);
            a[2] = f2tf(xs[ r0      * XS_STRIDE + cb + 4]);
            a[3] = f2tf(xs[(r0 + 8) * XS_STRIDE + cb + 4]);

            #pragma unroll
            for (int wq = 0; wq < 3; wq++) {
                const uint2* wrow =
                    (const uint2*)(bufp + XS_BYTES + wq * WF_BYTES) + ks * 256 + lane;
                #pragma unroll
                for (int nc = 0; nc < 8; nc++) {
                    uint2 b = wrow[nc * 32];
                    mma_tf32(cacc[wq][nc], a, b.x, b.y);
                }
            }
        }
        __syncthreads();
    }

    // Epilogue: RoPE + attention-ready conversion
    const int gr0 = row0 + r0;
    const int s0  = gr0 & (S_LEN - 1);
    const int s1  = (gr0 + 8) & (S_LEN - 1);
    #pragma unroll
    for (int wq = 0; wq < 3; wq++) {
        float (*cc)[4] = cacc[wq];
        float* outp = (wq == 0) ? g_Q : (wq == 1) ? g_K : g_V;
        #pragma unroll
        for (int nc = 0; nc < 8; nc++) {
            int col = nc * 8 + 2 * t;
            float v0 = cc[nc][0], v1 = cc[nc][1], v2 = cc[nc][2], v3 = cc[nc][3];
            float2 o0, o1;
            if (wq == 0) {               // Q: rope, prescale 0.125, tf32
                int i0 = col >> 1;
                float sn0 = g_sin[s0 * HALF + i0], cs0 = g_cos[s0 * HALF + i0];
                float sn1 = g_sin[s1 * HALF + i0], cs1 = g_cos[s1 * HALF + i0];
                o0 = make_float2(tf32f((v0 * cs0 - v1 * sn0) * 0.125f),
                                 tf32f((v1 * cs0 + v0 * sn0) * 0.125f));
                o1 = make_float2(tf32f((v2 * cs1 - v3 * sn1) * 0.125f),
                                 tf32f((v3 * cs1 + v2 * sn1) * 0.125f));
            } else if (wq == 1) {        // K: rope, tf32
                int i0 = col >> 1;
                float sn0 = g_sin[s0 * HALF + i0], cs0 = g_cos[s0 * HALF + i0];
                float sn1 = g_sin[s1 * HALF + i0], cs1 = g_cos[s1 * HALF + i0];
                o0 = make_float2(tf32f(v0 * cs0 - v1 * sn0),
                                 tf32f(v1 * cs0 + v0 * sn0));
                o1 = make_float2(tf32f(v2 * cs1 - v3 * sn1),
                                 tf32f(v3 * cs1 + v2 * sn1));
            } else {                     // V: tf32
                o0 = make_float2(tf32f(v0), tf32f(v1));
                o1 = make_float2(tf32f(v2), tf32f(v3));
            }
            *(float2*)(outp + (size_t)gr0 * HEAD + col)       = o0;
            *(float2*)(outp + (size_t)(gr0 + 8) * HEAD + col) = o1;
        }
    }
}

// ---------------------------------------------------------------------------
// Tensor-core flash attention, 4-way split-KV (tf32 MMA).
// K/V tiles arrive pre-converted (tf32 bits): staging = cp.async pure copy,
// double-buffered across the jt loop.
// ---------------------------------------------------------------------------
#define KV_TILE  (64 * 68 * 4)           // 17408 bytes (padded rows)
#define KV_BUF   (2 * KV_TILE)           // K + V
#define ATTN_SMEM (2 * KV_BUF)           // 69632

__global__ void __launch_bounds__(128, 3) attn_mma_kernel() {
    extern __shared__ char asmem[];

    const int tid   = threadIdx.x;
    const int warp  = tid >> 5;
    const int lane  = tid & 31;
    const int g     = lane >> 2;
    const int t     = lane & 3;
    const int idx   = blockIdx.x;
    const int qt    = 63 - (idx >> 4);
    const int rem   = idx & 15;
    const int batch = rem >> 2;
    const int split = rem & 3;
    const int q0    = qt * 64;
    const int n     = qt + 1;
    const int lo    = (split * n) >> 2;
    const int hi    = ((split + 1) * n) >> 2;

    const int    rl0     = warp * 16 + g, rl1 = rl0 + 8;
    const size_t rowbase = (size_t)batch * S_LEN + q0;

    if (lo == hi) {
        if (t == 0) {
            int pb = split * R_TOT;
            g_m[pb + rowbase + rl0] = -1e30f;  g_l[pb + rowbase + rl0] = 0.f;
            g_m[pb + rowbase + rl1] = -1e30f;  g_l[pb + rowbase + rl1] = 0.f;
        }
        return;
    }

    const uint32_t smb = smem_u32(asmem);

    // Q tile (pre-scaled, pre-tf32): copy into buf0 K region, extract frags
    unsigned qa[8][4];
    {
        const float* Qg = g_Q + rowbase * HEAD;
        #pragma unroll
        for (int j = 0; j < 8; j++) {
            int i = j * 128 + tid;
            int r = i >> 4, c4 = i & 15;
            cp16(smb + (r * 68 + c4 * 4) * 4, Qg + (size_t)r * HEAD + c4 * 4);
        }
        CP_COMMIT(); CP_WAIT(0);
        __syncthreads();
        const unsigned* Kq = (const unsigned*)asmem;
        const int r0 = warp * 16 + g;
        #pragma unroll
        for (int kc = 0; kc < 8; kc++) {
            qa[kc][0] = Kq[r0 * 68 + kc * 8 + t];
            qa[kc][1] = Kq[(r0 + 8) * 68 + kc * 8 + t];
            qa[kc][2] = Kq[r0 * 68 + kc * 8 + t + 4];
            qa[kc][3] = Kq[(r0 + 8) * 68 + kc * 8 + t + 4];
        }
        __syncthreads();
    }

    float o[8][4];
    #pragma unroll
    for (int nc = 0; nc < 8; nc++) { o[nc][0] = o[nc][1] = o[nc][2] = o[nc][3] = 0.f; }
    float m0 = -1e30f, m1 = -1e30f, l0 = 0.f, l1 = 0.f;

    // --- stage K/V tile jt into buffer b ---
    auto stageKV = [&](int jt, int b) {
        const float* Kg = g_K + ((size_t)batch * S_LEN + jt * 64) * HEAD;
        const float* Vg = g_V + ((size_t)batch * S_LEN + jt * 64) * HEAD;
        const uint32_t kb = smb + b * KV_BUF;
        #pragma unroll
        for (int j = 0; j < 8; j++) {
            int i = j * 128 + tid;
            int r = i >> 4, c4 = i & 15;
            uint32_t off = (r * 68 + c4 * 4) * 4;
            cp16(kb + off,           Kg + (size_t)r * HEAD + c4 * 4);
            cp16(kb + KV_TILE + off, Vg + (size_t)r * HEAD + c4 * 4);
        }
        CP_COMMIT();
    };

    stageKV(lo, 0);
    for (int jt = lo; jt < hi; jt++) {
        const int buf = (jt - lo) & 1;
        if (jt + 1 < hi) { stageKV(jt + 1, buf ^ 1); CP_WAIT(1); }
        else             { CP_WAIT(0); }
        __syncthreads();

        const unsigned* Ksb = (const unsigned*)(asmem + buf * KV_BUF);
        const unsigned* Vsb = (const unsigned*)(asmem + buf * KV_BUF + KV_TILE);

        // S = Q K^T
        float s[8][4];
        #pragma unroll
        for (int nc = 0; nc < 8; nc++) {
            s[nc][0] = s[nc][1] = s[nc][2] = s[nc][3] = 0.f;
            #pragma unroll
            for (int kc = 0; kc < 8; kc++) {
                unsigned b0 = Ksb[(nc * 8 + g) * 68 + kc * 8 + t];
                unsigned b1 = Ksb[(nc * 8 + g) * 68 + kc * 8 + t + 4];
                mma_tf32(s[nc], qa[kc], b0, b1);
            }
        }

        // Causal mask (diagonal tile only)
        if (jt == qt) {
            #pragma unroll
            for (int nc = 0; nc < 8; nc++) {
                int cl = nc * 8 + 2 * t;
                if (cl     > rl0) s[nc][0] = -1e30f;
                if (cl + 1 > rl0) s[nc][1] = -1e30f;
                if (cl     > rl1) s[nc][2] = -1e30f;
                if (cl + 1 > rl1) s[nc][3] = -1e30f;
            }
        }

        // Row max across the quad
        float mt0 = -1e30f, mt1 = -1e30f;
        #pragma unroll
        for (int nc = 0; nc < 8; nc++) {
            mt0 = fmaxf(mt0, fmaxf(s[nc][0], s[nc][1]));
            mt1 = fmaxf(mt1, fmaxf(s[nc][2], s[nc][3]));
        }
        mt0 = fmaxf(mt0, __shfl_xor_sync(0xffffffffu, mt0, 1));
        mt0 = fmaxf(mt0, __shfl_xor_sync(0xffffffffu, mt0, 2));
        mt1 = fmaxf(mt1, __shfl_xor_sync(0xffffffffu, mt1, 1));
        mt1 = fmaxf(mt1, __shfl_xor_sync(0xffffffffu, mt1, 2));

        float mn0 = fmaxf(m0, mt0), mn1 = fmaxf(m1, mt1);
        float corr0 = exp2f((m0 - mn0) * LOG2E);
        float corr1 = exp2f((m1 - mn1) * LOG2E);

        float rs0 = 0.f, rs1 = 0.f;
        #pragma unroll
        for (int nc = 0; nc < 8; nc++) {
            s[nc][0] = exp2f((s[nc][0] - mn0) * LOG2E);
            s[nc][1] = exp2f((s[nc][1] - mn0) * LOG2E);
            s[nc][2] = exp2f((s[nc][2] - mn1) * LOG2E);
            s[nc][3] = exp2f((s[nc][3] - mn1) * LOG2E);
            rs0 += s[nc][0] + s[nc][1];
            rs1 += s[nc][2] + s[nc][3];
        }
        rs0 += __shfl_xor_sync(0xffffffffu, rs0, 1);
        rs0 += __shfl_xor_sync(0xffffffffu, rs0, 2);
        rs1 += __shfl_xor_sync(0xffffffffu, rs1, 1);
        rs1 += __shfl_xor_sync(0xffffffffu, rs1, 2);
        l0 = l0 * corr0 + rs0;
        l1 = l1 * corr1 + rs1;

        #pragma unroll
        for (int nc = 0; nc < 8; nc++) {
            o[nc][0] *= corr0; o[nc][1] *= corr0;
            o[nc][2] *= corr1; o[nc][3] *= corr1;
        }

        // Repack P (C-frag -> A-frag) interleaved with PV MMAs
        const int  src1 = (lane & ~3) | (t >> 1);
        const int  src2 = src1 + 2;
        const bool odd  = (t & 1);
        #pragma unroll
        for (int kc = 0; kc < 8; kc++) {
            float v00 = __shfl_sync(0xffffffffu, s[kc][0], src1);
            float v01 = __shfl_sync(0xffffffffu, s[kc][1], src1);
            float v10 = __shfl_sync(0xffffffffu, s[kc][2], src1);
            float v11 = __shfl_sync(0xffffffffu, s[kc][3], src1);
            float w00 = __shfl_sync(0xffffffffu, s[kc][0], src2);
            float w01 = __shfl_sync(0xffffffffu, s[kc][1], src2);
            float w10 = __shfl_sync(0xffffffffu, s[kc][2], src2);
            float w11 = __shfl_sync(0xffffffffu, s[kc][3], src2);
            unsigned pa[4];
            pa[0] = f2tf(odd ? v01 : v00);
            pa[1] = f2tf(odd ? v11 : v10);
            pa[2] = f2tf(odd ? w01 : w00);
            pa[3] = f2tf(odd ? w11 : w10);
            #pragma unroll
            for (int nc = 0; nc < 8; nc++) {
                unsigned b0 = Vsb[(kc * 8 + t) * 68 + nc * 8 + g];
                unsigned b1 = Vsb[(kc * 8 + t + 4) * 68 + nc * 8 + g];
                mma_tf32(o[nc], pa, b0, b1);
            }
        }

        m0 = mn0; m1 = mn1;
        __syncthreads();
    }

    // Store unnormalized partials + (m, l)
    float* O0 = g_Os + (size_t)split * R_TOT * HEAD + (rowbase + rl0) * HEAD;
    float* O1 = g_Os + (size_t)split * R_TOT * HEAD + (rowbase + rl1) * HEAD;
    #pragma unroll
    for (int nc = 0; nc < 8; nc++) {
        int col = nc * 8 + 2 * t;
        *(float2*)(O0 + col) = make_float2(o[nc][0], o[nc][1]);
        *(float2*)(O1 + col) = make_float2(o[nc][2], o[nc][3]);
    }
    if (t == 0) {
        int pb = split * R_TOT;
        g_m[pb + rowbase + rl0] = m0;  g_l[pb + rowbase + rl0] = l0;
        g_m[pb + rowbase + rl1] = m1;  g_l[pb + rowbase + rl1] = l1;
    }
}

// ---------------------------------------------------------------------------
// Split-KV combine: one thread per (row, 16-col quarter).
// ---------------------------------------------------------------------------
__global__ void __launch_bounds__(128) combine_kernel(float* __restrict__ out) {
    int gt  = blockIdx.x * 128 + threadIdx.x;
    int row = gt >> 2;
    int qp  = gt & 3;

    float m[SPLIT], l[SPLIT];
    float M = -1e30f;
    #pragma unroll
    for (int s = 0; s < SPLIT; s++) {
        m[s] = g_m[s * R_TOT + row];
        l[s] = g_l[s * R_TOT + row];
        M = fmaxf(M, m[s]);
    }
    float L = 0.f, w[SPLIT];
    #pragma unroll
    for (int s = 0; s < SPLIT; s++) {
        w[s] = exp2f((m[s] - M) * LOG2E);
        L += l[s] * w[s];
    }
    const float inv = 1.f / L;

    float4 acc[4];
    #pragma unroll
    for (int j = 0; j < 4; j++) acc[j] = make_float4(0.f, 0.f, 0.f, 0.f);
    #pragma unroll
    for (int s = 0; s < SPLIT; s++) {
        if (l[s] > 0.f) {
            const float4* p = (const float4*)(g_Os + (size_t)s * R_TOT * HEAD +
                                              (size_t)row * HEAD + qp * 16);
            #pragma unroll
            for (int j = 0; j < 4; j++) {
                float4 v = p[j];
                acc[j].x += w[s] * v.x; acc[j].y += w[s] * v.y;
                acc[j].z += w[s] * v.z; acc[j].w += w[s] * v.w;
            }
        }
    }
    float4* po = (float4*)(out + (size_t)row * HEAD + qp * 16);
    #pragma unroll
    for (int j = 0; j < 4; j++) {
        float4 r = acc[j];
        r.x *= inv; r.y *= inv; r.z *= inv; r.w *= inv;
        po[j] = r;
    }
}

// ---------------------------------------------------------------------------
extern "C" void kernel_launch(void* const* d_in, const int* in_sizes, int n_in,
                              void* d_out, int out_size) {
    const float* x  = (const float*)d_in[0];
    const float* Wq = (const float*)d_in[1];
    const float* Wk = (const float*)d_in[2];
    const float* Wv = (const float*)d_in[3];
    float* out = (float*)d_out;

    cudaFuncSetAttribute(proj_fused_kernel,
                         cudaFuncAttributeMaxDynamicSharedMemorySize, FSMEM);
    cudaFuncSetAttribute(attn_mma_kernel,
                         cudaFuncAttributeMaxDynamicSharedMemorySize, ATTN_SMEM);

    theta_kernel<<<1, 32>>>();
    rope_table_kernel<<<(S_LEN * HALF + 255) / 256, 256>>>();
    wfrag_kernel<<<(3 * NK8 * 8 * 32 + 255) / 256, 256>>>(Wq, Wk, Wv);
    proj_fused_kernel<<<R_TOT / 128, 256, FSMEM>>>(x);
    attn_mma_kernel<<<64 * B_SZ * SPLIT, 128, ATTN_SMEM>>>();
    combine_kernel<<<(R_TOT * 4) / 128, 128>>>(out);
}

// round 11
// speedup vs baseline: 8.4693x; 1.0978x over previous
#include <cuda_runtime.h>
#include <cuda_bf16.h>
#include <math.h>
#include <stdint.h>

#define B_SZ    4
#define S_LEN   4096
#define D_MODEL 1024
#define HEAD    64
#define R_TOT   (B_SZ * S_LEN)
#define HALF    (HEAD / 2)
#define LOG2E   1.4426950408889634f
#define SPLIT   4
#define NK8     (D_MODEL / 8)    // 128 k8-slices

// Scratch (allocation-free rule: __device__ globals)
// g_Q holds tf32-rounded, 0.125-prescaled Q; g_K/g_V hold tf32-rounded values.
__device__ float g_Q[R_TOT * HEAD];
__device__ float g_K[R_TOT * HEAD];
__device__ float g_V[R_TOT * HEAD];
__device__ float g_sin[S_LEN * HALF];
__device__ float g_cos[S_LEN * HALF];
__device__ float g_theta[HALF];
__device__ float g_Os[(size_t)SPLIT * R_TOT * HEAD];
__device__ float g_m[SPLIT * R_TOT];
__device__ float g_l[SPLIT * R_TOT];
// Precomputed W B-fragments (tf32): [which][k8][nc][lane] = {b0, b1}
__device__ uint2 g_Wf[3][NK8][8][32];

// ---------------------------------------------------------------------------
__device__ __forceinline__ unsigned f2tf(float f) {
    unsigned u;
    asm("cvt.rna.tf32.f32 %0, %1;" : "=r"(u) : "f"(f));
    return u;
}
__device__ __forceinline__ float tf32f(float f) { return __uint_as_float(f2tf(f)); }

__device__ __forceinline__ void mma_tf32(float c[4], const unsigned a[4],
                                         unsigned b0, unsigned b1) {
    asm volatile(
        "mma.sync.aligned.m16n8k8.row.col.f32.tf32.tf32.f32 "
        "{%0,%1,%2,%3}, {%4,%5,%6,%7}, {%8,%9}, {%0,%1,%2,%3};\n"
        : "+f"(c[0]), "+f"(c[1]), "+f"(c[2]), "+f"(c[3])
        : "r"(a[0]), "r"(a[1]), "r"(a[2]), "r"(a[3]), "r"(b0), "r"(b1));
}

__device__ __forceinline__ uint32_t smem_u32(const void* p) {
    uint32_t a;
    asm("{ .reg .u64 t; cvta.to.shared.u64 t, %1; cvt.u32.u64 %0, t; }"
        : "=r"(a) : "l"(p));
    return a;
}

__device__ __forceinline__ void cp16(uint32_t dst, const void* src) {
    asm volatile("cp.async.cg.shared.global [%0], [%1], 16;"
                 :: "r"(dst), "l"(src) : "memory");
}
#define CP_COMMIT()  asm volatile("cp.async.commit_group;" ::: "memory")
#define CP_WAIT(n)   asm volatile("cp.async.wait_group %0;" :: "n"(n) : "memory")

// ---------------------------------------------------------------------------
__global__ void theta_kernel() {
    int i = threadIdx.x;
    if (i < HALF) g_theta[i] = (float)pow(10000.0, -(double)i / (double)HALF);
}

// RoPE table: freq = fp32(s * theta_fp32); accurate sin/cos via double range
// reduction + fp32 Taylor on |r|<=pi/4.
__global__ void rope_table_kernel() {
    int idx = blockIdx.x * blockDim.x + threadIdx.x;
    if (idx >= S_LEN * HALF) return;
    int s = idx >> 5;
    int i = idx & (HALF - 1);
    float fr = (float)s * g_theta[i];

    double x  = (double)fr;
    double kd = rint(x * 0.6366197723675814);
    int    k  = (int)kd;
    double r  = fma(-kd, 1.5707963267948966, x);
    r         = fma(-kd, 6.123233995736766e-17, r);
    float rf = (float)r;
    float r2 = rf * rf;
    float sp = rf * (1.f + r2 * (-1.66666667e-1f + r2 * (8.33333310e-3f +
               r2 * (-1.98412698e-4f + r2 * 2.75573140e-6f))));
    float cp = 1.f + r2 * (-0.5f + r2 * (4.16666679e-2f +
               r2 * (-1.38888892e-3f + r2 * 2.47868524e-5f)));
    float sn, cs;
    switch (k & 3) {
        case 0:  sn = sp;  cs = cp;  break;
        case 1:  sn = cp;  cs = -sp; break;
        case 2:  sn = -sp; cs = -cp; break;
        default: sn = -cp; cs = sp;  break;
    }
    g_sin[idx] = sn;
    g_cos[idx] = cs;
}

// ---------------------------------------------------------------------------
// Precompute W B-fragments (tf32) for m16n8k8 projection MMAs.
// ---------------------------------------------------------------------------
__global__ void wfrag_kernel(const float* __restrict__ Wq,
                             const float* __restrict__ Wk,
                             const float* __restrict__ Wv) {
    int tid = blockIdx.x * 256 + threadIdx.x;
    if (tid >= 3 * NK8 * 8 * 32) return;
    int lane  = tid & 31;
    int nc    = (tid >> 5) & 7;
    int ks    = (tid >> 8) & (NK8 - 1);
    int which = tid >> 15;
    const float* W = (which == 0) ? Wq : (which == 1) ? Wk : Wv;
    int g = lane >> 2, t = lane & 3;
    int n = nc * 8 + g;
    int k0 = ks * 8;
    uint2 v;
    v.x = f2tf(W[(size_t)(k0 + t)     * HEAD + n]);
    v.y = f2tf(W[(size_t)(k0 + t + 4) * HEAD + n]);
    g_Wf[which][ks][nc][lane] = v;
}

// ---------------------------------------------------------------------------
// FUSED QKV tensor-core projection (single-pass tf32, m16n8k8) + RoPE.
// (unchanged from round 10)
// ---------------------------------------------------------------------------
#define XS_STRIDE 68
#define XS_BYTES   (128 * XS_STRIDE * 4)             // 34816
#define WF_BYTES   (8 * 8 * 32 * 8)                  // 16384 per which per chunk
#define WQ_STRIDE  (NK8 * 8 * 32 * 8)                // 262144 bytes per which
#define FBUF       (XS_BYTES + 3 * WF_BYTES)         // 83968
#define FSMEM      (2 * FBUF)                        // 167936

__global__ void __launch_bounds__(256, 1) proj_fused_kernel(const float* __restrict__ x) {
    extern __shared__ char psm[];

    const int tid  = threadIdx.x;
    const int warp = tid >> 5;
    const int lane = tid & 31;
    const int g    = lane >> 2;
    const int t    = lane & 3;
    const int row0 = blockIdx.x * 128;
    const int r0   = warp * 16 + g;

    const uint32_t smb = smem_u32(psm);

    auto stage = [&](int c, int b) {
        const uint32_t base = smb + b * FBUF;
        const float* xsrc = x + (size_t)row0 * D_MODEL + c * 64;
        #pragma unroll
        for (int j = 0; j < 8; j++) {
            int idx = j * 256 + tid;
            int r = idx >> 4, c4 = idx & 15;
            cp16(base + (r * XS_STRIDE + c4 * 4) * 4,
                 xsrc + (size_t)r * D_MODEL + c4 * 4);
        }
        const char* ws = (const char*)&g_Wf[0][0][0][0] + (size_t)c * WF_BYTES;
        #pragma unroll
        for (int wq = 0; wq < 3; wq++) {
            #pragma unroll
            for (int j = 0; j < 4; j++) {
                int idx = j * 256 + tid;
                cp16(base + XS_BYTES + wq * WF_BYTES + idx * 16,
                     ws + (size_t)wq * WQ_STRIDE + idx * 16);
            }
        }
        CP_COMMIT();
    };

    float cacc[3][8][4] = {};

    stage(0, 0);
    for (int c = 0; c < 16; c++) {
        const int bufsel = c & 1;
        if (c < 15) { stage(c + 1, bufsel ^ 1); CP_WAIT(1); }
        else        { CP_WAIT(0); }
        __syncthreads();

        char* bufp = psm + bufsel * FBUF;
        float* xs  = (float*)bufp;

        #pragma unroll
        for (int ks = 0; ks < 8; ks++) {
            const int cb = ks * 8 + t;
            unsigned a[4];
            a[0] = f2tf(xs[ r0      * XS_STRIDE + cb]);
            a[1] = f2tf(xs[(r0 + 8) * XS_STRIDE + cb]);
            a[2] = f2tf(xs[ r0      * XS_STRIDE + cb + 4]);
            a[3] = f2tf(xs[(r0 + 8) * XS_STRIDE + cb + 4]);

            #pragma unroll
            for (int wq = 0; wq < 3; wq++) {
                const uint2* wrow =
                    (const uint2*)(bufp + XS_BYTES + wq * WF_BYTES) + ks * 256 + lane;
                #pragma unroll
                for (int nc = 0; nc < 8; nc++) {
                    uint2 b = wrow[nc * 32];
                    mma_tf32(cacc[wq][nc], a, b.x, b.y);
                }
            }
        }
        __syncthreads();
    }

    const int gr0 = row0 + r0;
    const int s0  = gr0 & (S_LEN - 1);
    const int s1  = (gr0 + 8) & (S_LEN - 1);
    #pragma unroll
    for (int wq = 0; wq < 3; wq++) {
        float (*cc)[4] = cacc[wq];
        float* outp = (wq == 0) ? g_Q : (wq == 1) ? g_K : g_V;
        #pragma unroll
        for (int nc = 0; nc < 8; nc++) {
            int col = nc * 8 + 2 * t;
            float v0 = cc[nc][0], v1 = cc[nc][1], v2 = cc[nc][2], v3 = cc[nc][3];
            float2 o0, o1;
            if (wq == 0) {
                int i0 = col >> 1;
                float sn0 = g_sin[s0 * HALF + i0], cs0 = g_cos[s0 * HALF + i0];
                float sn1 = g_sin[s1 * HALF + i0], cs1 = g_cos[s1 * HALF + i0];
                o0 = make_float2(tf32f((v0 * cs0 - v1 * sn0) * 0.125f),
                                 tf32f((v1 * cs0 + v0 * sn0) * 0.125f));
                o1 = make_float2(tf32f((v2 * cs1 - v3 * sn1) * 0.125f),
                                 tf32f((v3 * cs1 + v2 * sn1) * 0.125f));
            } else if (wq == 1) {
                int i0 = col >> 1;
                float sn0 = g_sin[s0 * HALF + i0], cs0 = g_cos[s0 * HALF + i0];
                float sn1 = g_sin[s1 * HALF + i0], cs1 = g_cos[s1 * HALF + i0];
                o0 = make_float2(tf32f(v0 * cs0 - v1 * sn0),
                                 tf32f(v1 * cs0 + v0 * sn0));
                o1 = make_float2(tf32f(v2 * cs1 - v3 * sn1),
                                 tf32f(v3 * cs1 + v2 * sn1));
            } else {
                o0 = make_float2(tf32f(v0), tf32f(v1));
                o1 = make_float2(tf32f(v2), tf32f(v3));
            }
            *(float2*)(outp + (size_t)gr0 * HEAD + col)       = o0;
            *(float2*)(outp + (size_t)(gr0 + 8) * HEAD + col) = o1;
        }
    }
}

// ---------------------------------------------------------------------------
// Tensor-core flash attention v2: 32 q-rows per warp (two m16 A-tiles),
// block = 128 q-rows, 4-way split-KV. Each K/V B-fragment LDS feeds 2 MMAs.
// K/V pre-converted tf32, cp.async double-buffered.
// ---------------------------------------------------------------------------
#define KV_TILE   (64 * 68 * 4)          // 17408 bytes
#define KV_BUF    (2 * KV_TILE)          // K + V per stage = 34816
#define ATTN_SMEM (2 * KV_BUF)           // 69632

__global__ void __launch_bounds__(128, 2) attn_mma_kernel() {
    extern __shared__ char asmem[];

    const int tid   = threadIdx.x;
    const int warp  = tid >> 5;
    const int lane  = tid & 31;
    const int g     = lane >> 2;
    const int t     = lane & 3;
    const int idx   = blockIdx.x;
    const int qt    = 31 - (idx >> 4);        // 128-row q-tile, big first
    const int rem   = idx & 15;
    const int batch = rem >> 2;
    const int split = rem & 3;
    const int q0    = qt * 128;
    const int n     = 2 * qt + 2;             // 64-wide kv tiles
    const int lo    = (split * n) >> 2;
    const int hi    = ((split + 1) * n) >> 2;

    const int    rl0     = warp * 32 + g;     // row groups: rl0, +8, +16, +24
    const size_t rowbase = (size_t)batch * S_LEN + q0;

    if (lo == hi) {
        if (t == 0) {
            int pb = split * R_TOT;
            #pragma unroll
            for (int rg = 0; rg < 4; rg++) {
                g_m[pb + rowbase + rl0 + rg * 8] = -1e30f;
                g_l[pb + rowbase + rl0 + rg * 8] = 0.f;
            }
        }
        return;
    }

    const uint32_t smb = smem_u32(asmem);

    // Q tile (128 rows, pre-scaled pre-tf32) -> smem -> A-frags for 2 tiles
    unsigned qa[2][8][4];
    {
        const float* Qg = g_Q + rowbase * HEAD;
        #pragma unroll
        for (int j = 0; j < 16; j++) {
            int i = j * 128 + tid;
            int r = i >> 4, c4 = i & 15;
            cp16(smb + (r * 68 + c4 * 4) * 4, Qg + (size_t)r * HEAD + c4 * 4);
        }
        CP_COMMIT(); CP_WAIT(0);
        __syncthreads();
        const unsigned* Kq = (const unsigned*)asmem;
        #pragma unroll
        for (int tt = 0; tt < 2; tt++) {
            const int r0 = rl0 + tt * 16;
            #pragma unroll
            for (int kc = 0; kc < 8; kc++) {
                qa[tt][kc][0] = Kq[r0 * 68 + kc * 8 + t];
                qa[tt][kc][1] = Kq[(r0 + 8) * 68 + kc * 8 + t];
                qa[tt][kc][2] = Kq[r0 * 68 + kc * 8 + t + 4];
                qa[tt][kc][3] = Kq[(r0 + 8) * 68 + kc * 8 + t + 4];
            }
        }
        __syncthreads();
    }

    float o0[8][4], o1[8][4];
    #pragma unroll
    for (int nc = 0; nc < 8; nc++) {
        o0[nc][0] = o0[nc][1] = o0[nc][2] = o0[nc][3] = 0.f;
        o1[nc][0] = o1[nc][1] = o1[nc][2] = o1[nc][3] = 0.f;
    }
    float m[4] = {-1e30f, -1e30f, -1e30f, -1e30f};
    float l[4] = {0.f, 0.f, 0.f, 0.f};

    auto stageKV = [&](int jt, int b) {
        const float* Kg = g_K + ((size_t)batch * S_LEN + jt * 64) * HEAD;
        const float* Vg = g_V + ((size_t)batch * S_LEN + jt * 64) * HEAD;
        const uint32_t kb = smb + b * KV_BUF;
        #pragma unroll
        for (int j = 0; j < 8; j++) {
            int i = j * 128 + tid;
            int r = i >> 4, c4 = i & 15;
            uint32_t off = (r * 68 + c4 * 4) * 4;
            cp16(kb + off,           Kg + (size_t)r * HEAD + c4 * 4);
            cp16(kb + KV_TILE + off, Vg + (size_t)r * HEAD + c4 * 4);
        }
        CP_COMMIT();
    };

    stageKV(lo, 0);
    for (int jt = lo; jt < hi; jt++) {
        const int buf = (jt - lo) & 1;
        if (jt + 1 < hi) { stageKV(jt + 1, buf ^ 1); CP_WAIT(1); }
        else             { CP_WAIT(0); }
        __syncthreads();

        const unsigned* Ksb = (const unsigned*)(asmem + buf * KV_BUF);
        const unsigned* Vsb = (const unsigned*)(asmem + buf * KV_BUF + KV_TILE);

        // S = Q K^T  (both A-tiles share each B-fragment)
        float s0[8][4], s1[8][4];
        #pragma unroll
        for (int nc = 0; nc < 8; nc++) {
            s0[nc][0] = s0[nc][1] = s0[nc][2] = s0[nc][3] = 0.f;
            s1[nc][0] = s1[nc][1] = s1[nc][2] = s1[nc][3] = 0.f;
            #pragma unroll
            for (int kc = 0; kc < 8; kc++) {
                unsigned b0 = Ksb[(nc * 8 + g) * 68 + kc * 8 + t];
                unsigned b1 = Ksb[(nc * 8 + g) * 68 + kc * 8 + t + 4];
                mma_tf32(s0[nc], qa[0][kc], b0, b1);
                mma_tf32(s1[nc], qa[1][kc], b0, b1);
            }
        }

        // Causal mask (last two kv tiles of the 128-row q-tile)
        if (jt >= 2 * qt) {
            const int base = q0 - jt * 64;     // q - jof for row offset 0
            #pragma unroll
            for (int nc = 0; nc < 8; nc++) {
                int cl = nc * 8 + 2 * t;
                int L0 = base + rl0,      L1 = L0 + 8;
                int L2 = L0 + 16,         L3 = L0 + 24;
                if (cl     > L0) s0[nc][0] = -1e30f;
                if (cl + 1 > L0) s0[nc][1] = -1e30f;
                if (cl     > L1) s0[nc][2] = -1e30f;
                if (cl + 1 > L1) s0[nc][3] = -1e30f;
                if (cl     > L2) s1[nc][0] = -1e30f;
                if (cl + 1 > L2) s1[nc][1] = -1e30f;
                if (cl     > L3) s1[nc][2] = -1e30f;
                if (cl + 1 > L3) s1[nc][3] = -1e30f;
            }
        }

        // Row max per group (4 groups)
        float mt[4] = {-1e30f, -1e30f, -1e30f, -1e30f};
        #pragma unroll
        for (int nc = 0; nc < 8; nc++) {
            mt[0] = fmaxf(mt[0], fmaxf(s0[nc][0], s0[nc][1]));
            mt[1] = fmaxf(mt[1], fmaxf(s0[nc][2], s0[nc][3]));
            mt[2] = fmaxf(mt[2], fmaxf(s1[nc][0], s1[nc][1]));
            mt[3] = fmaxf(mt[3], fmaxf(s1[nc][2], s1[nc][3]));
        }
        #pragma unroll
        for (int rg = 0; rg < 4; rg++) {
            mt[rg] = fmaxf(mt[rg], __shfl_xor_sync(0xffffffffu, mt[rg], 1));
            mt[rg] = fmaxf(mt[rg], __shfl_xor_sync(0xffffffffu, mt[rg], 2));
        }

        float mn[4], corr[4];
        #pragma unroll
        for (int rg = 0; rg < 4; rg++) {
            mn[rg]   = fmaxf(m[rg], mt[rg]);
            corr[rg] = exp2f((m[rg] - mn[rg]) * LOG2E);
        }

        float rs[4] = {0.f, 0.f, 0.f, 0.f};
        #pragma unroll
        for (int nc = 0; nc < 8; nc++) {
            s0[nc][0] = exp2f((s0[nc][0] - mn[0]) * LOG2E);
            s0[nc][1] = exp2f((s0[nc][1] - mn[0]) * LOG2E);
            s0[nc][2] = exp2f((s0[nc][2] - mn[1]) * LOG2E);
            s0[nc][3] = exp2f((s0[nc][3] - mn[1]) * LOG2E);
            s1[nc][0] = exp2f((s1[nc][0] - mn[2]) * LOG2E);
            s1[nc][1] = exp2f((s1[nc][1] - mn[2]) * LOG2E);
            s1[nc][2] = exp2f((s1[nc][2] - mn[3]) * LOG2E);
            s1[nc][3] = exp2f((s1[nc][3] - mn[3]) * LOG2E);
            rs[0] += s0[nc][0] + s0[nc][1];
            rs[1] += s0[nc][2] + s0[nc][3];
            rs[2] += s1[nc][0] + s1[nc][1];
            rs[3] += s1[nc][2] + s1[nc][3];
        }
        #pragma unroll
        for (int rg = 0; rg < 4; rg++) {
            rs[rg] += __shfl_xor_sync(0xffffffffu, rs[rg], 1);
            rs[rg] += __shfl_xor_sync(0xffffffffu, rs[rg], 2);
            l[rg] = l[rg] * corr[rg] + rs[rg];
            m[rg] = mn[rg];
        }

        #pragma unroll
        for (int nc = 0; nc < 8; nc++) {
            o0[nc][0] *= corr[0]; o0[nc][1] *= corr[0];
            o0[nc][2] *= corr[1]; o0[nc][3] *= corr[1];
            o1[nc][0] *= corr[2]; o1[nc][1] *= corr[2];
            o1[nc][2] *= corr[3]; o1[nc][3] *= corr[3];
        }

        // Repack P (C-frag -> A-frag) for both tiles, interleaved with PV MMAs
        const int  src1 = (lane & ~3) | (t >> 1);
        const int  src2 = src1 + 2;
        const bool odd  = (t & 1);
        #pragma unroll
        for (int kc = 0; kc < 8; kc++) {
            unsigned pa0[4], pa1[4];
            {
                float v00 = __shfl_sync(0xffffffffu, s0[kc][0], src1);
                float v01 = __shfl_sync(0xffffffffu, s0[kc][1], src1);
                float v10 = __shfl_sync(0xffffffffu, s0[kc][2], src1);
                float v11 = __shfl_sync(0xffffffffu, s0[kc][3], src1);
                float w00 = __shfl_sync(0xffffffffu, s0[kc][0], src2);
                float w01 = __shfl_sync(0xffffffffu, s0[kc][1], src2);
                float w10 = __shfl_sync(0xffffffffu, s0[kc][2], src2);
                float w11 = __shfl_sync(0xffffffffu, s0[kc][3], src2);
                pa0[0] = f2tf(odd ? v01 : v00);
                pa0[1] = f2tf(odd ? v11 : v10);
                pa0[2] = f2tf(odd ? w01 : w00);
                pa0[3] = f2tf(odd ? w11 : w10);
            }
            {
                float v00 = __shfl_sync(0xffffffffu, s1[kc][0], src1);
                float v01 = __shfl_sync(0xffffffffu, s1[kc][1], src1);
                float v10 = __shfl_sync(0xffffffffu, s1[kc][2], src1);
                float v11 = __shfl_sync(0xffffffffu, s1[kc][3], src1);
                float w00 = __shfl_sync(0xffffffffu, s1[kc][0], src2);
                float w01 = __shfl_sync(0xffffffffu, s1[kc][1], src2);
                float w10 = __shfl_sync(0xffffffffu, s1[kc][2], src2);
                float w11 = __shfl_sync(0xffffffffu, s1[kc][3], src2);
                pa1[0] = f2tf(odd ? v01 : v00);
                pa1[1] = f2tf(odd ? v11 : v10);
                pa1[2] = f2tf(odd ? w01 : w00);
                pa1[3] = f2tf(odd ? w11 : w10);
            }
            #pragma unroll
            for (int nc = 0; nc < 8; nc++) {
                unsigned b0 = Vsb[(kc * 8 + t) * 68 + nc * 8 + g];
                unsigned b1 = Vsb[(kc * 8 + t + 4) * 68 + nc * 8 + g];
                mma_tf32(o0[nc], pa0, b0, b1);
                mma_tf32(o1[nc], pa1, b0, b1);
            }
        }

        __syncthreads();
    }

    // Store unnormalized partials + (m, l) for 4 row groups
    float* base = g_Os + (size_t)split * R_TOT * HEAD + rowbase * HEAD;
    #pragma unroll
    for (int nc = 0; nc < 8; nc++) {
        int col = nc * 8 + 2 * t;
        *(float2*)(base + (size_t)(rl0     ) * HEAD + col) = make_float2(o0[nc][0], o0[nc][1]);
        *(float2*)(base + (size_t)(rl0 +  8) * HEAD + col) = make_float2(o0[nc][2], o0[nc][3]);
        *(float2*)(base + (size_t)(rl0 + 16) * HEAD + col) = make_float2(o1[nc][0], o1[nc][1]);
        *(float2*)(base + (size_t)(rl0 + 24) * HEAD + col) = make_float2(o1[nc][2], o1[nc][3]);
    }
    if (t == 0) {
        int pb = split * R_TOT;
        #pragma unroll
        for (int rg = 0; rg < 4; rg++) {
            g_m[pb + rowbase + rl0 + rg * 8] = m[rg];
            g_l[pb + rowbase + rl0 + rg * 8] = l[rg];
        }
    }
}

// ---------------------------------------------------------------------------
// Split-KV combine: one thread per (row, 16-col quarter).
// ---------------------------------------------------------------------------
__global__ void __launch_bounds__(128) combine_kernel(float* __restrict__ out) {
    int gt  = blockIdx.x * 128 + threadIdx.x;
    int row = gt >> 2;
    int qp  = gt & 3;

    float m[SPLIT], l[SPLIT];
    float M = -1e30f;
    #pragma unroll
    for (int s = 0; s < SPLIT; s++) {
        m[s] = g_m[s * R_TOT + row];
        l[s] = g_l[s * R_TOT + row];
        M = fmaxf(M, m[s]);
    }
    float L = 0.f, w[SPLIT];
    #pragma unroll
    for (int s = 0; s < SPLIT; s++) {
        w[s] = exp2f((m[s] - M) * LOG2E);
        L += l[s] * w[s];
    }
    const float inv = 1.f / L;

    float4 acc[4];
    #pragma unroll
    for (int j = 0; j < 4; j++) acc[j] = make_float4(0.f, 0.f, 0.f, 0.f);
    #pragma unroll
    for (int s = 0; s < SPLIT; s++) {
        if (l[s] > 0.f) {
            const float4* p = (const float4*)(g_Os + (size_t)s * R_TOT * HEAD +
                                              (size_t)row * HEAD + qp * 16);
            #pragma unroll
            for (int j = 0; j < 4; j++) {
                float4 v = p[j];
                acc[j].x += w[s] * v.x; acc[j].y += w[s] * v.y;
                acc[j].z += w[s] * v.z; acc[j].w += w[s] * v.w;
            }
        }
    }
    float4* po = (float4*)(out + (size_t)row * HEAD + qp * 16);
    #pragma unroll
    for (int j = 0; j < 4; j++) {
        float4 r = acc[j];
        r.x *= inv; r.y *= inv; r.z *= inv; r.w *= inv;
        po[j] = r;
    }
}

// ---------------------------------------------------------------------------
extern "C" void kernel_launch(void* const* d_in, const int* in_sizes, int n_in,
                              void* d_out, int out_size) {
    const float* x  = (const float*)d_in[0];
    const float* Wq = (const float*)d_in[1];
    const float* Wk = (const float*)d_in[2];
    const float* Wv = (const float*)d_in[3];
    float* out = (float*)d_out;

    cudaFuncSetAttribute(proj_fused_kernel,
                         cudaFuncAttributeMaxDynamicSharedMemorySize, FSMEM);
    cudaFuncSetAttribute(attn_mma_kernel,
                         cudaFuncAttributeMaxDynamicSharedMemorySize, ATTN_SMEM);

    theta_kernel<<<1, 32>>>();
    rope_table_kernel<<<(S_LEN * HALF + 255) / 256, 256>>>();
    wfrag_kernel<<<(3 * NK8 * 8 * 32 + 255) / 256, 256>>>(Wq, Wk, Wv);
    proj_fused_kernel<<<R_TOT / 128, 256, FSMEM>>>(x);
    attn_mma_kernel<<<32 * B_SZ * SPLIT, 128, ATTN_SMEM>>>();
    combine_kernel<<<(R_TOT * 4) / 128, 128>>>(out);
}

// round 13
// speedup vs baseline: 12.4008x; 1.4642x over previous
#include <cuda_runtime.h>
#include <cuda_fp16.h>
#include <math.h>
#include <stdint.h>

#define B_SZ    4
#define S_LEN   4096
#define D_MODEL 1024
#define HEAD    64
#define R_TOT   (B_SZ * S_LEN)
#define HALF    (HEAD / 2)
#define LOG2E   1.4426950408889634f
#define SPLIT   4
#define NK16    (D_MODEL / 16)   // 64 k16-slices

// Scratch (allocation-free rule: __device__ globals)
// g_Qh: fp16 rope(Q)*0.125; g_Kh: fp16 rope(K) [row][col];
// g_Vh2: fp16 V transposed kv-pair packed: [batch][d][spair] half2.
__device__ __half  g_Qh[R_TOT * HEAD];
__device__ __half  g_Kh[R_TOT * HEAD];
__device__ __half2 g_Vh2[R_TOT * HEAD / 2];
__device__ float g_sin[S_LEN * HALF];
__device__ float g_cos[S_LEN * HALF];
__device__ float g_theta[HALF];
__device__ float g_Os[(size_t)SPLIT * R_TOT * HEAD];
__device__ float g_m[SPLIT * R_TOT];
__device__ float g_l[SPLIT * R_TOT];
// Precomputed W B-fragments (fp16, m16n8k16): [which][k16][nc][lane] = {b0, b1}
__device__ uint2 g_Wfh[3][NK16][8][32];

// ---------------------------------------------------------------------------
__device__ __forceinline__ void mma_f16(float c[4], const unsigned a[4],
                                        unsigned b0, unsigned b1) {
    asm volatile(
        "mma.sync.aligned.m16n8k16.row.col.f32.f16.f16.f32 "
        "{%0,%1,%2,%3}, {%4,%5,%6,%7}, {%8,%9}, {%0,%1,%2,%3};\n"
        : "+f"(c[0]), "+f"(c[1]), "+f"(c[2]), "+f"(c[3])
        : "r"(a[0]), "r"(a[1]), "r"(a[2]), "r"(a[3]), "r"(b0), "r"(b1));
}

__device__ __forceinline__ unsigned pack_h2(float a, float b) {
    __half2 h = __floats2half2_rn(a, b);
    return *(unsigned*)&h;
}

__device__ __forceinline__ uint32_t smem_u32(const void* p) {
    uint32_t a;
    asm("{ .reg .u64 t; cvta.to.shared.u64 t, %1; cvt.u32.u64 %0, t; }"
        : "=r"(a) : "l"(p));
    return a;
}

__device__ __forceinline__ void cp16(uint32_t dst, const void* src) {
    asm volatile("cp.async.cg.shared.global [%0], [%1], 16;"
                 :: "r"(dst), "l"(src) : "memory");
}
#define CP_COMMIT()  asm volatile("cp.async.commit_group;" ::: "memory")
#define CP_WAIT(n)   asm volatile("cp.async.wait_group %0;" :: "n"(n) : "memory")

// ---------------------------------------------------------------------------
__global__ void theta_kernel() {
    int i = threadIdx.x;
    if (i < HALF) g_theta[i] = (float)pow(10000.0, -(double)i / (double)HALF);
}

// RoPE table: freq = fp32(s * theta_fp32); accurate sin/cos via double range
// reduction + fp32 Taylor on |r|<=pi/4.
__global__ void rope_table_kernel() {
    int idx = blockIdx.x * blockDim.x + threadIdx.x;
    if (idx >= S_LEN * HALF) return;
    int s = idx >> 5;
    int i = idx & (HALF - 1);
    float fr = (float)s * g_theta[i];

    double x  = (double)fr;
    double kd = rint(x * 0.6366197723675814);
    int    k  = (int)kd;
    double r  = fma(-kd, 1.5707963267948966, x);
    r         = fma(-kd, 6.123233995736766e-17, r);
    float rf = (float)r;
    float r2 = rf * rf;
    float sp = rf * (1.f + r2 * (-1.66666667e-1f + r2 * (8.33333310e-3f +
               r2 * (-1.98412698e-4f + r2 * 2.75573140e-6f))));
    float cp = 1.f + r2 * (-0.5f + r2 * (4.16666679e-2f +
               r2 * (-1.38888892e-3f + r2 * 2.47868524e-5f)));
    float sn, cs;
    switch (k & 3) {
        case 0:  sn = sp;  cs = cp;  break;
        case 1:  sn = cp;  cs = -sp; break;
        case 2:  sn = -sp; cs = -cp; break;
        default: sn = -cp; cs = sp;  break;
    }
    g_sin[idx] = sn;
    g_cos[idx] = cs;
}

// ---------------------------------------------------------------------------
// Precompute W B-fragments (fp16) for m16n8k16 projection MMAs.
// b0 = {W[k0+2t][n], W[k0+2t+1][n]}, b1 = {W[k0+2t+8][n], W[k0+2t+9][n]}.
// ---------------------------------------------------------------------------
__global__ void wfrag_kernel(const float* __restrict__ Wq,
                             const float* __restrict__ Wk,
                             const float* __restrict__ Wv) {
    int tid = blockIdx.x * 256 + threadIdx.x;
    if (tid >= 3 * NK16 * 8 * 32) return;
    int lane  = tid & 31;
    int nc    = (tid >> 5) & 7;
    int ks    = (tid >> 8) & (NK16 - 1);
    int which = tid >> 14;
    const float* W = (which == 0) ? Wq : (which == 1) ? Wk : Wv;
    int g = lane >> 2, t = lane & 3;
    int n = nc * 8 + g;
    int k0 = ks * 16 + 2 * t;
    uint2 v;
    v.x = pack_h2(W[(size_t)(k0    ) * HEAD + n], W[(size_t)(k0 + 1) * HEAD + n]);
    v.y = pack_h2(W[(size_t)(k0 + 8) * HEAD + n], W[(size_t)(k0 + 9) * HEAD + n]);
    g_Wfh[which][ks][nc][lane] = v;
}

// ---------------------------------------------------------------------------
// FUSED QKV projection, fp16 m16n8k16, fp32 accum, + RoPE.
// CTA = 128 rows x 64 cols, 256 threads (8 warps x 16 rows), all 3 outputs.
// Double-buffered cp.async staging of x (fp32) + 3 W-frag slices (fp16).
// Epilogue: Q/K -> fp16 [row][col] (Q prescaled 0.125); V -> fp16 transposed
// kv-pair packed via smem transpose.
// ---------------------------------------------------------------------------
#define XS_STRIDE 68
#define XS_BYTES   (128 * XS_STRIDE * 4)             // 34816
#define WFH_BYTES  (4 * 8 * 32 * 8)                  // 8192 per which per chunk
#define WQH_STRIDE (NK16 * 8 * 32 * 8)               // 131072 bytes per which
#define FBUF       (XS_BYTES + 3 * WFH_BYTES)        // 59392
#define FSMEM      (2 * FBUF)                        // 118784

__global__ void __launch_bounds__(256, 1) proj_fused_kernel(const float* __restrict__ x) {
    extern __shared__ char psm[];

    const int tid  = threadIdx.x;
    const int warp = tid >> 5;
    const int lane = tid & 31;
    const int g    = lane >> 2;
    const int t    = lane & 3;
    const int row0 = blockIdx.x * 128;
    const int r0   = warp * 16 + g;      // local row; rows r0, r0+8

    const uint32_t smb = smem_u32(psm);

    auto stage = [&](int c, int b) {
        const uint32_t base = smb + b * FBUF;
        const float* xsrc = x + (size_t)row0 * D_MODEL + c * 64;
        #pragma unroll
        for (int j = 0; j < 8; j++) {
            int idx = j * 256 + tid;
            int r = idx >> 4, c4 = idx & 15;
            cp16(base + (r * XS_STRIDE + c4 * 4) * 4,
                 xsrc + (size_t)r * D_MODEL + c4 * 4);
        }
        const char* ws = (const char*)&g_Wfh[0][0][0][0] + (size_t)c * WFH_BYTES;
        #pragma unroll
        for (int wq = 0; wq < 3; wq++) {
            #pragma unroll
            for (int j = 0; j < 2; j++) {
                int idx = j * 256 + tid;
                cp16(base + XS_BYTES + wq * WFH_BYTES + idx * 16,
                     ws + (size_t)wq * WQH_STRIDE + idx * 16);
            }
        }
        CP_COMMIT();
    };

    float cacc[3][8][4] = {};

    stage(0, 0);
    for (int c = 0; c < 16; c++) {
        const int bufsel = c & 1;
        if (c < 15) { stage(c + 1, bufsel ^ 1); CP_WAIT(1); }
        else        { CP_WAIT(0); }
        __syncthreads();

        char* bufp = psm + bufsel * FBUF;
        float* xs  = (float*)bufp;

        #pragma unroll
        for (int ks = 0; ks < 4; ks++) {
            const int cb = ks * 16 + 2 * t;
            float2 f0 = *(float2*)&xs[ r0      * XS_STRIDE + cb];
            float2 f1 = *(float2*)&xs[(r0 + 8) * XS_STRIDE + cb];
            float2 f2 = *(float2*)&xs[ r0      * XS_STRIDE + cb + 8];
            float2 f3 = *(float2*)&xs[(r0 + 8) * XS_STRIDE + cb + 8];
            unsigned a[4];
            a[0] = pack_h2(f0.x, f0.y);
            a[1] = pack_h2(f1.x, f1.y);
            a[2] = pack_h2(f2.x, f2.y);
            a[3] = pack_h2(f3.x, f3.y);

            #pragma unroll
            for (int wq = 0; wq < 3; wq++) {
                const uint2* wrow =
                    (const uint2*)(bufp + XS_BYTES + wq * WFH_BYTES) + ks * 256 + lane;
                #pragma unroll
                for (int nc = 0; nc < 8; nc++) {
                    uint2 b = wrow[nc * 32];
                    mma_f16(cacc[wq][nc], a, b.x, b.y);
                }
            }
        }
        __syncthreads();
    }

    // Epilogue: RoPE; Q/K -> fp16 direct; V -> smem transpose (pairs along kv)
    const int gr0 = row0 + r0;
    const int s0  = gr0 & (S_LEN - 1);
    const int s1  = (gr0 + 8) & (S_LEN - 1);
    __half* Vt = (__half*)psm;                      // [64 d][136 halfs]
    #pragma unroll
    for (int wq = 0; wq < 3; wq++) {
        float (*cc)[4] = cacc[wq];
        #pragma unroll
        for (int nc = 0; nc < 8; nc++) {
            int col = nc * 8 + 2 * t;
            float v0 = cc[nc][0], v1 = cc[nc][1], v2 = cc[nc][2], v3 = cc[nc][3];
            if (wq < 2) {
                int i0 = col >> 1;
                float sn0 = g_sin[s0 * HALF + i0], cs0 = g_cos[s0 * HALF + i0];
                float sn1 = g_sin[s1 * HALF + i0], cs1 = g_cos[s1 * HALF + i0];
                float a0 = v0 * cs0 - v1 * sn0, b0 = v1 * cs0 + v0 * sn0;
                float a1 = v2 * cs1 - v3 * sn1, b1 = v3 * cs1 + v2 * sn1;
                if (wq == 0) { a0 *= 0.125f; b0 *= 0.125f; a1 *= 0.125f; b1 *= 0.125f; }
                __half* outp = (wq == 0) ? g_Qh : g_Kh;
                *(__half2*)(outp + (size_t)gr0 * HEAD + col)       = __floats2half2_rn(a0, b0);
                *(__half2*)(outp + (size_t)(gr0 + 8) * HEAD + col) = __floats2half2_rn(a1, b1);
            } else {
                Vt[(col    ) * 136 + r0]     = __float2half_rn(v0);
                Vt[(col + 1) * 136 + r0]     = __float2half_rn(v1);
                Vt[(col    ) * 136 + r0 + 8] = __float2half_rn(v2);
                Vt[(col + 1) * 136 + r0 + 8] = __float2half_rn(v3);
            }
        }
    }
    __syncthreads();
    // Cooperative coalesced write of transposed V: 64 d x 64 spairs
    {
        const int batch  = row0 >> 12;
        const int spair0 = (row0 & (S_LEN - 1)) >> 1;
        #pragma unroll
        for (int j = 0; j < 4; j++) {
            int idx = j * 256 + tid;
            int d   = idx >> 4;
            int r16 = idx & 15;
            uint4 v = *(uint4*)(psm + d * 272 + r16 * 16);
            *(uint4*)&g_Vh2[(size_t)(batch * HEAD + d) * (S_LEN / 2) + spair0 + r16 * 4] = v;
        }
    }
}

// ---------------------------------------------------------------------------
// fp16 flash attention: m16n8k16 QK and PV, 32 q-rows/warp, 128 q-rows/block,
// 4-way split-KV, cp.async double-buffered. PV A-fragments come straight from
// softmax C-fragments (pair layouts match) — no shuffles.
// ---------------------------------------------------------------------------
#define KT_STRIDE 72                     // halfs per K row
#define KT_BYTES  (64 * KT_STRIDE * 2)   // 9216
#define VT_STRIDE 36                     // half2 per V d-row (d-major)
#define VT_BYTES  (64 * VT_STRIDE * 4)   // 9216
#define KV_BUF2   (KT_BYTES + VT_BYTES)  // 18432
#define ATTN_SMEM (2 * KV_BUF2)          // 36864

__global__ void __launch_bounds__(128, 2) attn_mma_kernel() {
    extern __shared__ char asmem[];

    const int tid   = threadIdx.x;
    const int warp  = tid >> 5;
    const int lane  = tid & 31;
    const int g     = lane >> 2;
    const int t     = lane & 3;
    const int idx   = blockIdx.x;
    const int qt    = 31 - (idx >> 4);
    const int rem   = idx & 15;
    const int batch = rem >> 2;
    const int split = rem & 3;
    const int q0    = qt * 128;
    const int n     = 2 * qt + 2;
    const int lo    = (split * n) >> 2;
    const int hi    = ((split + 1) * n) >> 2;

    const int    rl0     = warp * 32 + g;
    const size_t rowbase = (size_t)batch * S_LEN + q0;

    if (lo == hi) {
        if (t == 0) {
            int pb = split * R_TOT;
            #pragma unroll
            for (int rg = 0; rg < 4; rg++) {
                g_m[pb + rowbase + rl0 + rg * 8] = -1e30f;
                g_l[pb + rowbase + rl0 + rg * 8] = 0.f;
            }
        }
        return;
    }

    const uint32_t smb = smem_u32(asmem);

    // Q tile (128 rows fp16) -> smem [r][72] -> A-frags (pairs along d)
    unsigned qa[2][4][4];
    {
        const __half* Qg = g_Qh + rowbase * HEAD;
        #pragma unroll
        for (int j = 0; j < 8; j++) {
            int i = j * 128 + tid;
            int r = i >> 3, c8 = i & 7;
            cp16(smb + r * (KT_STRIDE * 2) + c8 * 16, Qg + (size_t)r * HEAD + c8 * 8);
        }
        CP_COMMIT(); CP_WAIT(0);
        __syncthreads();
        const __half* Qs = (const __half*)asmem;
        #pragma unroll
        for (int tt = 0; tt < 2; tt++) {
            const int r0 = rl0 + tt * 16;
            #pragma unroll
            for (int kc = 0; kc < 4; kc++) {
                qa[tt][kc][0] = *(const unsigned*)&Qs[ r0      * KT_STRIDE + kc * 16 + 2 * t];
                qa[tt][kc][1] = *(const unsigned*)&Qs[(r0 + 8) * KT_STRIDE + kc * 16 + 2 * t];
                qa[tt][kc][2] = *(const unsigned*)&Qs[ r0      * KT_STRIDE + kc * 16 + 2 * t + 8];
                qa[tt][kc][3] = *(const unsigned*)&Qs[(r0 + 8) * KT_STRIDE + kc * 16 + 2 * t + 8];
            }
        }
        __syncthreads();
    }

    float o0[8][4], o1[8][4];
    #pragma unroll
    for (int nc = 0; nc < 8; nc++) {
        o0[nc][0] = o0[nc][1] = o0[nc][2] = o0[nc][3] = 0.f;
        o1[nc][0] = o1[nc][1] = o1[nc][2] = o1[nc][3] = 0.f;
    }
    float m[4] = {-1e30f, -1e30f, -1e30f, -1e30f};
    float l[4] = {0.f, 0.f, 0.f, 0.f};

    auto stageKV = [&](int jt, int b) {
        const uint32_t kb = smb + b * KV_BUF2;
        const __half*  Kg = g_Kh + ((size_t)batch * S_LEN + jt * 64) * HEAD;
        const __half2* Vg = g_Vh2 + (size_t)batch * HEAD * (S_LEN / 2) + jt * 32;
        #pragma unroll
        for (int j = 0; j < 4; j++) {
            int i = j * 128 + tid;
            int r = i >> 3, c8 = i & 7;
            cp16(kb + r * (KT_STRIDE * 2) + c8 * 16, Kg + (size_t)r * HEAD + c8 * 8);
        }
        // V tile: 64 d-rows x 32 half2 (128 B) = 512 cp16
        #pragma unroll
        for (int j = 0; j < 4; j++) {
            int i = j * 128 + tid;
            int d = i >> 3, c16 = i & 7;
            cp16(kb + KT_BYTES + d * (VT_STRIDE * 4) + c16 * 16,
                 Vg + (size_t)d * (S_LEN / 2) + c16 * 4);
        }
        CP_COMMIT();
    };

    stageKV(lo, 0);
    for (int jt = lo; jt < hi; jt++) {
        const int buf = (jt - lo) & 1;
        if (jt + 1 < hi) { stageKV(jt + 1, buf ^ 1); CP_WAIT(1); }
        else             { CP_WAIT(0); }
        __syncthreads();

        const __half*   Ksb = (const __half*)(asmem + buf * KV_BUF2);
        const unsigned* Vsb = (const unsigned*)(asmem + buf * KV_BUF2 + KT_BYTES);

        // S = Q K^T (fp16, k16) — both A-tiles share each B-fragment
        float s0[8][4], s1[8][4];
        #pragma unroll
        for (int nc = 0; nc < 8; nc++) {
            s0[nc][0] = s0[nc][1] = s0[nc][2] = s0[nc][3] = 0.f;
            s1[nc][0] = s1[nc][1] = s1[nc][2] = s1[nc][3] = 0.f;
            const __half* Krow = Ksb + (nc * 8 + g) * KT_STRIDE;
            #pragma unroll
            for (int kc = 0; kc < 4; kc++) {
                unsigned b0 = *(const unsigned*)&Krow[kc * 16 + 2 * t];
                unsigned b1 = *(const unsigned*)&Krow[kc * 16 + 2 * t + 8];
                mma_f16(s0[nc], qa[0][kc], b0, b1);
                mma_f16(s1[nc], qa[1][kc], b0, b1);
            }
        }

        // Causal mask (last two kv tiles of the 128-row q-tile)
        if (jt >= 2 * qt) {
            const int base = q0 - jt * 64;
            #pragma unroll
            for (int nc = 0; nc < 8; nc++) {
                int cl = nc * 8 + 2 * t;
                int L0 = base + rl0, L1 = L0 + 8, L2 = L0 + 16, L3 = L0 + 24;
                if (cl     > L0) s0[nc][0] = -1e30f;
                if (cl + 1 > L0) s0[nc][1] = -1e30f;
                if (cl     > L1) s0[nc][2] = -1e30f;
                if (cl + 1 > L1) s0[nc][3] = -1e30f;
                if (cl     > L2) s1[nc][0] = -1e30f;
                if (cl + 1 > L2) s1[nc][1] = -1e30f;
                if (cl     > L3) s1[nc][2] = -1e30f;
                if (cl + 1 > L3) s1[nc][3] = -1e30f;
            }
        }

        // Row max per group
        float mt[4] = {-1e30f, -1e30f, -1e30f, -1e30f};
        #pragma unroll
        for (int nc = 0; nc < 8; nc++) {
            mt[0] = fmaxf(mt[0], fmaxf(s0[nc][0], s0[nc][1]));
            mt[1] = fmaxf(mt[1], fmaxf(s0[nc][2], s0[nc][3]));
            mt[2] = fmaxf(mt[2], fmaxf(s1[nc][0], s1[nc][1]));
            mt[3] = fmaxf(mt[3], fmaxf(s1[nc][2], s1[nc][3]));
        }
        #pragma unroll
        for (int rg = 0; rg < 4; rg++) {
            mt[rg] = fmaxf(mt[rg], __shfl_xor_sync(0xffffffffu, mt[rg], 1));
            mt[rg] = fmaxf(mt[rg], __shfl_xor_sync(0xffffffffu, mt[rg], 2));
        }

        float mn[4], corr[4];
        #pragma unroll
        for (int rg = 0; rg < 4; rg++) {
            mn[rg]   = fmaxf(m[rg], mt[rg]);
            corr[rg] = exp2f((m[rg] - mn[rg]) * LOG2E);
        }

        float rs[4] = {0.f, 0.f, 0.f, 0.f};
        #pragma unroll
        for (int nc = 0; nc < 8; nc++) {
            s0[nc][0] = exp2f((s0[nc][0] - mn[0]) * LOG2E);
            s0[nc][1] = exp2f((s0[nc][1] - mn[0]) * LOG2E);
            s0[nc][2] = exp2f((s0[nc][2] - mn[1]) * LOG2E);
            s0[nc][3] = exp2f((s0[nc][3] - mn[1]) * LOG2E);
            s1[nc][0] = exp2f((s1[nc][0] - mn[2]) * LOG2E);
            s1[nc][1] = exp2f((s1[nc][1] - mn[2]) * LOG2E);
            s1[nc][2] = exp2f((s1[nc][2] - mn[3]) * LOG2E);
            s1[nc][3] = exp2f((s1[nc][3] - mn[3]) * LOG2E);
            rs[0] += s0[nc][0] + s0[nc][1];
            rs[1] += s0[nc][2] + s0[nc][3];
            rs[2] += s1[nc][0] + s1[nc][1];
            rs[3] += s1[nc][2] + s1[nc][3];
        }
        #pragma unroll
        for (int rg = 0; rg < 4; rg++) {
            rs[rg] += __shfl_xor_sync(0xffffffffu, rs[rg], 1);
            rs[rg] += __shfl_xor_sync(0xffffffffu, rs[rg], 2);
            l[rg] = l[rg] * corr[rg] + rs[rg];
            m[rg] = mn[rg];
        }

        #pragma unroll
        for (int nc = 0; nc < 8; nc++) {
            o0[nc][0] *= corr[0]; o0[nc][1] *= corr[0];
            o0[nc][2] *= corr[1]; o0[nc][3] *= corr[1];
            o1[nc][0] *= corr[2]; o1[nc][1] *= corr[2];
            o1[nc][2] *= corr[3]; o1[nc][3] *= corr[3];
        }

        // O += P V : P C-frag pairs == fp16 A-frag pairs (no shuffles)
        #pragma unroll
        for (int kc = 0; kc < 4; kc++) {
            unsigned pa0[4], pa1[4];
            pa0[0] = pack_h2(s0[2 * kc][0],     s0[2 * kc][1]);
            pa0[1] = pack_h2(s0[2 * kc][2],     s0[2 * kc][3]);
            pa0[2] = pack_h2(s0[2 * kc + 1][0], s0[2 * kc + 1][1]);
            pa0[3] = pack_h2(s0[2 * kc + 1][2], s0[2 * kc + 1][3]);
            pa1[0] = pack_h2(s1[2 * kc][0],     s1[2 * kc][1]);
            pa1[1] = pack_h2(s1[2 * kc][2],     s1[2 * kc][3]);
            pa1[2] = pack_h2(s1[2 * kc + 1][0], s1[2 * kc + 1][1]);
            pa1[3] = pack_h2(s1[2 * kc + 1][2], s1[2 * kc + 1][3]);
            #pragma unroll
            for (int nc = 0; nc < 8; nc++) {
                unsigned b0 = Vsb[(nc * 8 + g) * VT_STRIDE + kc * 8 + t];
                unsigned b1 = Vsb[(nc * 8 + g) * VT_STRIDE + kc * 8 + t + 4];
                mma_f16(o0[nc], pa0, b0, b1);
                mma_f16(o1[nc], pa1, b0, b1);
            }
        }

        __syncthreads();
    }

    // Store unnormalized partials + (m, l)
    float* base = g_Os + (size_t)split * R_TOT * HEAD + rowbase * HEAD;
    #pragma unroll
    for (int nc = 0; nc < 8; nc++) {
        int col = nc * 8 + 2 * t;
        *(float2*)(base + (size_t)(rl0     ) * HEAD + col) = make_float2(o0[nc][0], o0[nc][1]);
        *(float2*)(base + (size_t)(rl0 +  8) * HEAD + col) = make_float2(o0[nc][2], o0[nc][3]);
        *(float2*)(base + (size_t)(rl0 + 16) * HEAD + col) = make_float2(o1[nc][0], o1[nc][1]);
        *(float2*)(base + (size_t)(rl0 + 24) * HEAD + col) = make_float2(o1[nc][2], o1[nc][3]);
    }
    if (t == 0) {
        int pb = split * R_TOT;
        #pragma unroll
        for (int rg = 0; rg < 4; rg++) {
            g_m[pb + rowbase + rl0 + rg * 8] = m[rg];
            g_l[pb + rowbase + rl0 + rg * 8] = l[rg];
        }
    }
}

// ---------------------------------------------------------------------------
// Split-KV combine: one thread per (row, 16-col quarter).
// ---------------------------------------------------------------------------
__global__ void __launch_bounds__(128) combine_kernel(float* __restrict__ out) {
    int gt  = blockIdx.x * 128 + threadIdx.x;
    int row = gt >> 2;
    int qp  = gt & 3;

    float m[SPLIT], l[SPLIT];
    float M = -1e30f;
    #pragma unroll
    for (int s = 0; s < SPLIT; s++) {
        m[s] = g_m[s * R_TOT + row];
        l[s] = g_l[s * R_TOT + row];
        M = fmaxf(M, m[s]);
    }
    float L = 0.f, w[SPLIT];
    #pragma unroll
    for (int s = 0; s < SPLIT; s++) {
        w[s] = exp2f((m[s] - M) * LOG2E);
        L += l[s] * w[s];
    }
    const float inv = 1.f / L;

    float4 acc[4];
    #pragma unroll
    for (int j = 0; j < 4; j++) acc[j] = make_float4(0.f, 0.f, 0.f, 0.f);
    #pragma unroll
    for (int s = 0; s < SPLIT; s++) {
        if (l[s] > 0.f) {
            const float4* p = (const float4*)(g_Os + (size_t)s * R_TOT * HEAD +
                                              (size_t)row * HEAD + qp * 16);
            #pragma unroll
            for (int j = 0; j < 4; j++) {
                float4 v = p[j];
                acc[j].x += w[s] * v.x; acc[j].y += w[s] * v.y;
                acc[j].z += w[s] * v.z; acc[j].w += w[s] * v.w;
            }
        }
    }
    float4* po = (float4*)(out + (size_t)row * HEAD + qp * 16);
    #pragma unroll
    for (int j = 0; j < 4; j++) {
        float4 r = acc[j];
        r.x *= inv; r.y *= inv; r.z *= inv; r.w *= inv;
        po[j] = r;
    }
}

// ---------------------------------------------------------------------------
extern "C" void kernel_launch(void* const* d_in, const int* in_sizes, int n_in,
                              void* d_out, int out_size) {
    const float* x  = (const float*)d_in[0];
    const float* Wq = (const float*)d_in[1];
    const float* Wk = (const float*)d_in[2];
    const float* Wv = (const float*)d_in[3];
    float* out = (float*)d_out;

    cudaFuncSetAttribute(proj_fused_kernel,
                         cudaFuncAttributeMaxDynamicSharedMemorySize, FSMEM);
    cudaFuncSetAttribute(attn_mma_kernel,
                         cudaFuncAttributeMaxDynamicSharedMemorySize, ATTN_SMEM);

    theta_kernel<<<1, 32>>>();
    rope_table_kernel<<<(S_LEN * HALF + 255) / 256, 256>>>();
    wfrag_kernel<<<(3 * NK16 * 8 * 32 + 255) / 256, 256>>>(Wq, Wk, Wv);
    proj_fused_kernel<<<R_TOT / 128, 256, FSMEM>>>(x);
    attn_mma_kernel<<<32 * B_SZ * SPLIT, 128, ATTN_SMEM>>>();
    combine_kernel<<<(R_TOT * 4) / 128, 128>>>(out);
}